// round 1
// baseline (speedup 1.0000x reference)
#include <cuda_runtime.h>
#include <cuda_bf16.h>
#include <math.h>

// ---------------- problem constants ----------------
#define BATCH 4
#define KQ    512        // query tokens per batch
#define NKV   4096       // kv tokens per batch
#define DMODEL 1024
#define NHEAD 16
#define HD    64
#define MQ    (BATCH*KQ)    // 2048
#define MKV   (BATCH*NKV)   // 16384
#define DFF   (4*DMODEL)    // 4096

// ---------------- scratch (device globals, no allocs) ----------------
__device__ float g_qln [MQ  * DMODEL];
__device__ float g_kvln[MKV * DMODEL];
__device__ float g_q   [MQ  * DMODEL];
__device__ float g_k   [MKV * DMODEL];
__device__ float g_v   [MKV * DMODEL];
__device__ float g_ctx [MQ  * DMODEL];
__device__ float g_out [MQ  * DMODEL];
__device__ float g_h   [MQ  * DMODEL];
__device__ float g_mlp1[MQ  * DFF];

// ---------------- norms (one block per row, D=1024, 256 thr) ----------------
__device__ __forceinline__ void block_reduce2(float& s1, float& s2) {
    #pragma unroll
    for (int off = 16; off; off >>= 1) {
        s1 += __shfl_xor_sync(0xffffffffu, s1, off);
        s2 += __shfl_xor_sync(0xffffffffu, s2, off);
    }
    __shared__ float a[8], b[8];
    int w = threadIdx.x >> 5, lane = threadIdx.x & 31;
    if (lane == 0) { a[w] = s1; b[w] = s2; }
    __syncthreads();
    s1 = 0.f; s2 = 0.f;
    #pragma unroll
    for (int i = 0; i < 8; i++) { s1 += a[i]; s2 += b[i]; }
}

__global__ void layernorm_k(const float* __restrict__ x, const float* __restrict__ g,
                            const float* __restrict__ b, float* __restrict__ y, float eps) {
    long row = blockIdx.x;
    const float4* xr = (const float4*)(x + row * DMODEL);
    float4 xv = xr[threadIdx.x];
    float s  = xv.x + xv.y + xv.z + xv.w;
    float sq = xv.x*xv.x + xv.y*xv.y + xv.z*xv.z + xv.w*xv.w;
    block_reduce2(s, sq);
    float mu  = s * (1.0f / DMODEL);
    float var = sq * (1.0f / DMODEL) - mu * mu;
    float rstd = rsqrtf(var + eps);
    float4 gv = ((const float4*)g)[threadIdx.x];
    float4 bv = ((const float4*)b)[threadIdx.x];
    float4 o;
    o.x = (xv.x - mu) * rstd * gv.x + bv.x;
    o.y = (xv.y - mu) * rstd * gv.y + bv.y;
    o.z = (xv.z - mu) * rstd * gv.z + bv.z;
    o.w = (xv.w - mu) * rstd * gv.w + bv.w;
    ((float4*)(y + row * DMODEL))[threadIdx.x] = o;
}

__global__ void rmsnorm_k(float* __restrict__ x, const float* __restrict__ w, float eps) {
    long row = blockIdx.x;
    float4* xr = (float4*)(x + row * DMODEL);
    float4 xv = xr[threadIdx.x];
    float sq = xv.x*xv.x + xv.y*xv.y + xv.z*xv.z + xv.w*xv.w;
    float dummy = 0.f;
    block_reduce2(sq, dummy);
    float rstd = rsqrtf(sq * (1.0f / DMODEL) + eps);
    float4 wv = ((const float4*)w)[threadIdx.x];
    float4 o;
    o.x = xv.x * rstd * wv.x; o.y = xv.y * rstd * wv.y;
    o.z = xv.z * rstd * wv.z; o.w = xv.w * rstd * wv.w;
    xr[threadIdx.x] = o;
}

// ---------------- GEMM: C = A[MxK] @ W[KxN] + bias, epilogues ----------------
// EPI: 0 = none, 1 = +residual, 2 = exact GELU
#define BM 64
#define BN 64
#define BKK 16

template<int EPI>
__global__ __launch_bounds__(256) void sgemm_k(
    const float* __restrict__ A, const float* __restrict__ W,
    const float* __restrict__ bias, const float* __restrict__ R,
    float* __restrict__ C, int M, int N, int Kd)
{
    __shared__ float As[BKK][BM + 4];
    __shared__ float Bs[BKK][BN];

    const int tx = threadIdx.x & 15;
    const int ty = threadIdx.x >> 4;
    const int m0 = blockIdx.y * BM;
    const int n0 = blockIdx.x * BN;

    const int la_m = threadIdx.x >> 2;          // 0..63
    const int la_k = (threadIdx.x & 3) << 2;    // 0,4,8,12
    const int lb_k = threadIdx.x >> 4;          // 0..15
    const int lb_n = (threadIdx.x & 15) << 2;   // 0..60

    const float* Aptr = A + (long)(m0 + la_m) * Kd + la_k;
    const float* Wptr = W + (long)lb_k * N + n0 + lb_n;

    float acc[4][4] = {};

    for (int k0 = 0; k0 < Kd; k0 += BKK) {
        float4 a4 = *(const float4*)(Aptr + k0);
        As[la_k + 0][la_m] = a4.x;
        As[la_k + 1][la_m] = a4.y;
        As[la_k + 2][la_m] = a4.z;
        As[la_k + 3][la_m] = a4.w;
        *(float4*)&Bs[lb_k][lb_n] = *(const float4*)(Wptr + (long)k0 * N);
        __syncthreads();
        #pragma unroll
        for (int kk = 0; kk < BKK; kk++) {
            float4 a = *(const float4*)&As[kk][ty << 2];
            float4 b = *(const float4*)&Bs[kk][tx << 2];
            float av[4] = {a.x, a.y, a.z, a.w};
            float bv[4] = {b.x, b.y, b.z, b.w};
            #pragma unroll
            for (int i = 0; i < 4; i++)
                #pragma unroll
                for (int j = 0; j < 4; j++)
                    acc[i][j] += av[i] * bv[j];
        }
        __syncthreads();
    }

    #pragma unroll
    for (int i = 0; i < 4; i++) {
        int row = m0 + (ty << 2) + i;
        int col = n0 + (tx << 2);
        float4 bv = *(const float4*)&bias[col];
        float v[4] = {acc[i][0] + bv.x, acc[i][1] + bv.y, acc[i][2] + bv.z, acc[i][3] + bv.w};
        if (EPI == 1) {
            float4 rv = *(const float4*)&R[(long)row * N + col];
            v[0] += rv.x; v[1] += rv.y; v[2] += rv.z; v[3] += rv.w;
        }
        if (EPI == 2) {
            #pragma unroll
            for (int j = 0; j < 4; j++)
                v[j] = 0.5f * v[j] * (1.0f + erff(v[j] * 0.7071067811865476f));
        }
        float4 o = {v[0], v[1], v[2], v[3]};
        *(float4*)&C[(long)row * N + col] = o;
    }
}

// ---------------- fused flash attention (fp32) ----------------
// grid: (KQ/64, NHEAD, BATCH), block 256.
// Tiles: 64 queries x 32 keys, HD=64. Online softmax.
// Thread layout: r = tid/4 (query row 0..63), c = tid%4.
//   - S: thread owns keys {c, c+4, ..., c+28} (8 keys).
//   - O: thread owns dim chunks 4*(c+4j)..+3 for j=0..3 (16 dims, interleaved).
__global__ __launch_bounds__(256) void flash_attn_k(
    const float* __restrict__ Q, const float* __restrict__ Kt,
    const float* __restrict__ V, float* __restrict__ O)
{
    __shared__ float qs[64][68];
    __shared__ float ks[32][68];
    __shared__ float vs[32][68];
    __shared__ float ps[64][36];

    const int qt = blockIdx.x, h = blockIdx.y, b = blockIdx.z;
    const int tid = threadIdx.x;
    const int r = tid >> 2, c = tid & 3;
    const int q0 = qt * 64;
    const float scale = 0.125f; // 1/sqrt(64)

    // load Q tile [64 x 64]
    for (int t = tid; t < 64 * 16; t += 256) {
        int rr = t >> 4, dc = (t & 15) << 2;
        *(float4*)&qs[rr][dc] =
            *(const float4*)&Q[((long)(b * KQ + q0 + rr)) * DMODEL + h * HD + dc];
    }

    float o[16] = {};
    float m = -INFINITY, l = 0.f;

    for (int n0 = 0; n0 < NKV; n0 += 32) {
        __syncthreads();  // prior-iteration reads of ks/vs done (also covers qs load)
        for (int t = tid; t < 32 * 16; t += 256) {
            int rr = t >> 4, dc = (t & 15) << 2;
            long gidx = ((long)(b * NKV + n0 + rr)) * DMODEL + h * HD + dc;
            *(float4*)&ks[rr][dc] = *(const float4*)&Kt[gidx];
            *(float4*)&vs[rr][dc] = *(const float4*)&V[gidx];
        }
        __syncthreads();

        // S = q . k for 8 keys
        float s[8] = {};
        #pragma unroll
        for (int d4 = 0; d4 < 16; d4++) {
            float4 q4 = *(const float4*)&qs[r][d4 << 2];
            #pragma unroll
            for (int kk = 0; kk < 8; kk++) {
                float4 k4 = *(const float4*)&ks[c + (kk << 2)][d4 << 2];
                s[kk] += q4.x * k4.x + q4.y * k4.y + q4.z * k4.z + q4.w * k4.w;
            }
        }
        float mloc = -INFINITY;
        #pragma unroll
        for (int kk = 0; kk < 8; kk++) { s[kk] *= scale; mloc = fmaxf(mloc, s[kk]); }
        mloc = fmaxf(mloc, __shfl_xor_sync(0xffffffffu, mloc, 1));
        mloc = fmaxf(mloc, __shfl_xor_sync(0xffffffffu, mloc, 2));
        float mnew = fmaxf(m, mloc);
        float corr = __expf(m - mnew);   // 0 on first tile (m = -inf)
        float lsum = 0.f;
        #pragma unroll
        for (int kk = 0; kk < 8; kk++) {
            float p = __expf(s[kk] - mnew);
            ps[r][c + (kk << 2)] = p;
            lsum += p;
        }
        lsum += __shfl_xor_sync(0xffffffffu, lsum, 1);
        lsum += __shfl_xor_sync(0xffffffffu, lsum, 2);
        l = l * corr + lsum;
        m = mnew;
        #pragma unroll
        for (int i = 0; i < 16; i++) o[i] *= corr;
        __syncwarp();  // ps row r written by 4 lanes of same warp

        // O += P @ V
        #pragma unroll
        for (int key = 0; key < 32; key++) {
            float p = ps[r][key];
            #pragma unroll
            for (int j = 0; j < 4; j++) {
                float4 v4 = *(const float4*)&vs[key][(c + (j << 2)) << 2];
                o[j * 4 + 0] += p * v4.x;
                o[j * 4 + 1] += p * v4.y;
                o[j * 4 + 2] += p * v4.z;
                o[j * 4 + 3] += p * v4.w;
            }
        }
    }

    float inv = 1.f / l;
    long obase = ((long)(b * KQ + q0 + r)) * DMODEL + h * HD;
    #pragma unroll
    for (int j = 0; j < 4; j++) {
        float4 ov = {o[j*4+0]*inv, o[j*4+1]*inv, o[j*4+2]*inv, o[j*4+3]*inv};
        *(float4*)&O[obase + ((c + (j << 2)) << 2)] = ov;
    }
}

// ---------------- launch ----------------
extern "C" void kernel_launch(void* const* d_in, const int* in_sizes, int n_in,
                              void* d_out, int out_size) {
    const float* query_tokens   = (const float*)d_in[0];
    const float* point_features = (const float*)d_in[1];
    const float* ln_q_g  = (const float*)d_in[2];
    const float* ln_q_b  = (const float*)d_in[3];
    const float* ln_kv_g = (const float*)d_in[4];
    const float* ln_kv_b = (const float*)d_in[5];
    const float* Wq = (const float*)d_in[6];   const float* bq = (const float*)d_in[7];
    const float* Wk = (const float*)d_in[8];   const float* bk = (const float*)d_in[9];
    const float* Wv = (const float*)d_in[10];  const float* bv = (const float*)d_in[11];
    const float* rms_q_w = (const float*)d_in[12];
    const float* rms_k_w = (const float*)d_in[13];
    const float* Wo = (const float*)d_in[14];  const float* bo = (const float*)d_in[15];
    const float* ln_mlp_g = (const float*)d_in[16];
    const float* ln_mlp_b = (const float*)d_in[17];
    const float* W1 = (const float*)d_in[18];  const float* b1 = (const float*)d_in[19];
    const float* W2 = (const float*)d_in[20];  const float* b2 = (const float*)d_in[21];
    float* out = (float*)d_out;

    float *p_qln, *p_kvln, *p_q, *p_k, *p_v, *p_ctx, *p_out, *p_h, *p_mlp1;
    cudaGetSymbolAddress((void**)&p_qln,  g_qln);
    cudaGetSymbolAddress((void**)&p_kvln, g_kvln);
    cudaGetSymbolAddress((void**)&p_q,    g_q);
    cudaGetSymbolAddress((void**)&p_k,    g_k);
    cudaGetSymbolAddress((void**)&p_v,    g_v);
    cudaGetSymbolAddress((void**)&p_ctx,  g_ctx);
    cudaGetSymbolAddress((void**)&p_out,  g_out);
    cudaGetSymbolAddress((void**)&p_h,    g_h);
    cudaGetSymbolAddress((void**)&p_mlp1, g_mlp1);

    // 1. pre-LN
    layernorm_k<<<MQ,  256>>>(query_tokens,   ln_q_g,  ln_q_b,  p_qln,  1e-5f);
    layernorm_k<<<MKV, 256>>>(point_features, ln_kv_g, ln_kv_b, p_kvln, 1e-5f);

    // 2. projections
    sgemm_k<0><<<dim3(DMODEL/BN, MQ /BM), 256>>>(p_qln,  Wq, bq, nullptr, p_q, MQ,  DMODEL, DMODEL);
    rmsnorm_k<<<MQ, 256>>>(p_q, rms_q_w, 1e-6f);
    sgemm_k<0><<<dim3(DMODEL/BN, MKV/BM), 256>>>(p_kvln, Wk, bk, nullptr, p_k, MKV, DMODEL, DMODEL);
    rmsnorm_k<<<MKV, 256>>>(p_k, rms_k_w, 1e-6f);
    sgemm_k<0><<<dim3(DMODEL/BN, MKV/BM), 256>>>(p_kvln, Wv, bv, nullptr, p_v, MKV, DMODEL, DMODEL);

    // 3. attention
    flash_attn_k<<<dim3(KQ/64, NHEAD, BATCH), 256>>>(p_q, p_k, p_v, p_ctx);

    // 4. output proj + residual
    sgemm_k<1><<<dim3(DMODEL/BN, MQ/BM), 256>>>(p_ctx, Wo, bo, query_tokens, p_out, MQ, DMODEL, DMODEL);

    // 5. MLP
    layernorm_k<<<MQ, 256>>>(p_out, ln_mlp_g, ln_mlp_b, p_h, 1e-5f);
    sgemm_k<2><<<dim3(DFF/BN,    MQ/BM), 256>>>(p_h,    W1, b1, nullptr, p_mlp1, MQ, DFF,    DMODEL);
    sgemm_k<1><<<dim3(DMODEL/BN, MQ/BM), 256>>>(p_mlp1, W2, b2, p_out,   out,    MQ, DMODEL, DFF);
}

// round 3
// speedup vs baseline: 1.5831x; 1.5831x over previous
#include <cuda_runtime.h>
#include <cuda_bf16.h>
#include <math.h>
#include <stdint.h>

// ---------------- problem constants ----------------
#define BATCH 4
#define KQ    512
#define NKV   4096
#define DMODEL 1024
#define NHEAD 16
#define HD    64
#define MQ    (BATCH*KQ)    // 2048
#define MKV   (BATCH*NKV)   // 16384
#define DFF   (4*DMODEL)    // 4096

// ---------------- scratch (device globals, no allocs) ----------------
__device__ float g_q   [MQ  * DMODEL];
__device__ float g_k   [MKV * DMODEL];
__device__ float g_v   [MKV * DMODEL];
__device__ float g_ctx [MQ  * DMODEL];
__device__ float g_out [MQ  * DMODEL];

__device__ __nv_bfloat16 g_qln_h [MQ  * DMODEL], g_qln_l [MQ  * DMODEL];
__device__ __nv_bfloat16 g_kvln_h[MKV * DMODEL], g_kvln_l[MKV * DMODEL];
__device__ __nv_bfloat16 g_ctx_h [MQ  * DMODEL], g_ctx_l [MQ  * DMODEL];
__device__ __nv_bfloat16 g_hln_h [MQ  * DMODEL], g_hln_l [MQ  * DMODEL];
__device__ __nv_bfloat16 g_m1_h  [MQ  * DFF],    g_m1_l  [MQ  * DFF];

__device__ __nv_bfloat16 g_wq_h[DMODEL*DMODEL], g_wq_l[DMODEL*DMODEL];
__device__ __nv_bfloat16 g_wk_h[DMODEL*DMODEL], g_wk_l[DMODEL*DMODEL];
__device__ __nv_bfloat16 g_wv_h[DMODEL*DMODEL], g_wv_l[DMODEL*DMODEL];
__device__ __nv_bfloat16 g_wo_h[DMODEL*DMODEL], g_wo_l[DMODEL*DMODEL];
__device__ __nv_bfloat16 g_w1_h[DMODEL*DFF],    g_w1_l[DMODEL*DFF];
__device__ __nv_bfloat16 g_w2_h[DFF*DMODEL],    g_w2_l[DFF*DMODEL];

// ---------------- low-level helpers ----------------
__device__ __forceinline__ uint32_t smem_u32(const void* p) {
    uint32_t a;
    asm("{ .reg .u64 t; cvta.to.shared.u64 t, %1; cvt.u32.u64 %0, t; }" : "=r"(a) : "l"(p));
    return a;
}
__device__ __forceinline__ void cpa16(uint32_t saddr, const void* g) {
    asm volatile("cp.async.cg.shared.global [%0], [%1], 16;" :: "r"(saddr), "l"(g));
}
__device__ __forceinline__ void cpa_commit() { asm volatile("cp.async.commit_group;"); }
__device__ __forceinline__ void cpa_wait1()  { asm volatile("cp.async.wait_group 1;"); }
__device__ __forceinline__ void cpa_wait0()  { asm volatile("cp.async.wait_group 0;"); }

#define LDMX4(r0, r1, r2, r3, addr) \
    asm volatile("ldmatrix.sync.aligned.m8n8.x4.shared.b16 {%0,%1,%2,%3}, [%4];" \
        : "=r"(r0), "=r"(r1), "=r"(r2), "=r"(r3) : "r"(addr))

__device__ __forceinline__ void mma_bf16(float* d, const uint32_t* a, const uint32_t* b) {
    asm volatile(
        "mma.sync.aligned.m16n8k16.row.col.f32.bf16.bf16.f32 "
        "{%0,%1,%2,%3}, {%4,%5,%6,%7}, {%8,%9}, {%0,%1,%2,%3};"
        : "+f"(d[0]), "+f"(d[1]), "+f"(d[2]), "+f"(d[3])
        : "r"(a[0]), "r"(a[1]), "r"(a[2]), "r"(a[3]), "r"(b[0]), "r"(b[1]));
}

// smem tile layout: 128 rows x 64 bytes (32 bf16). 16B group swizzled by (row>>1)&3.
__device__ __forceinline__ uint32_t tile_off(int row, int grp) {
    return (uint32_t)(row * 64 + ((grp ^ ((row >> 1) & 3)) << 4));
}

// ---------------- norm kernels ----------------
__device__ __forceinline__ void block_reduce2(float& s1, float& s2) {
    #pragma unroll
    for (int off = 16; off; off >>= 1) {
        s1 += __shfl_xor_sync(0xffffffffu, s1, off);
        s2 += __shfl_xor_sync(0xffffffffu, s2, off);
    }
    __shared__ float a[8], b[8];
    int w = threadIdx.x >> 5, lane = threadIdx.x & 31;
    if (lane == 0) { a[w] = s1; b[w] = s2; }
    __syncthreads();
    s1 = 0.f; s2 = 0.f;
    #pragma unroll
    for (int i = 0; i < 8; i++) { s1 += a[i]; s2 += b[i]; }
}

__device__ __forceinline__ void split_store(__nv_bfloat16* hp, __nv_bfloat16* lp, long idx,
                                            float v0, float v1, float v2, float v3) {
    __nv_bfloat16 h0 = __float2bfloat16(v0), h1 = __float2bfloat16(v1);
    __nv_bfloat16 h2 = __float2bfloat16(v2), h3 = __float2bfloat16(v3);
    __nv_bfloat162 a; a.x = h0; a.y = h1;
    __nv_bfloat162 b; b.x = h2; b.y = h3;
    *(__nv_bfloat162*)(hp + idx)     = a;
    *(__nv_bfloat162*)(hp + idx + 2) = b;
    __nv_bfloat162 c, d;
    c.x = __float2bfloat16(v0 - __bfloat162float(h0));
    c.y = __float2bfloat16(v1 - __bfloat162float(h1));
    d.x = __float2bfloat16(v2 - __bfloat162float(h2));
    d.y = __float2bfloat16(v3 - __bfloat162float(h3));
    *(__nv_bfloat162*)(lp + idx)     = c;
    *(__nv_bfloat162*)(lp + idx + 2) = d;
}

__global__ void layernorm_split_k(const float* __restrict__ x, const float* __restrict__ g,
                                  const float* __restrict__ b,
                                  __nv_bfloat16* __restrict__ yh, __nv_bfloat16* __restrict__ yl,
                                  float eps) {
    long row = blockIdx.x;
    float4 xv = ((const float4*)(x + row * DMODEL))[threadIdx.x];
    float s  = xv.x + xv.y + xv.z + xv.w;
    float sq = xv.x*xv.x + xv.y*xv.y + xv.z*xv.z + xv.w*xv.w;
    block_reduce2(s, sq);
    float mu  = s * (1.0f / DMODEL);
    float var = sq * (1.0f / DMODEL) - mu * mu;
    float rstd = rsqrtf(var + eps);
    float4 gv = ((const float4*)g)[threadIdx.x];
    float4 bv = ((const float4*)b)[threadIdx.x];
    float v0 = (xv.x - mu) * rstd * gv.x + bv.x;
    float v1 = (xv.y - mu) * rstd * gv.y + bv.y;
    float v2 = (xv.z - mu) * rstd * gv.z + bv.z;
    float v3 = (xv.w - mu) * rstd * gv.w + bv.w;
    split_store(yh, yl, row * DMODEL + threadIdx.x * 4, v0, v1, v2, v3);
}

__global__ void rmsnorm_k(float* __restrict__ x, const float* __restrict__ w, float eps) {
    long row = blockIdx.x;
    float4* xr = (float4*)(x + row * DMODEL);
    float4 xv = xr[threadIdx.x];
    float sq = xv.x*xv.x + xv.y*xv.y + xv.z*xv.z + xv.w*xv.w;
    float dummy = 0.f;
    block_reduce2(sq, dummy);
    float rstd = rsqrtf(sq * (1.0f / DMODEL) + eps);
    float4 wv = ((const float4*)w)[threadIdx.x];
    float4 o;
    o.x = xv.x * rstd * wv.x; o.y = xv.y * rstd * wv.y;
    o.z = xv.z * rstd * wv.z; o.w = xv.w * rstd * wv.w;
    xr[threadIdx.x] = o;
}

__global__ void split_k(const float* __restrict__ x, __nv_bfloat16* __restrict__ hp,
                        __nv_bfloat16* __restrict__ lp, long n4) {
    long i = (long)blockIdx.x * blockDim.x + threadIdx.x;
    if (i >= n4) return;
    float4 v = ((const float4*)x)[i];
    split_store(hp, lp, i * 4, v.x, v.y, v.z, v.w);
}

// W[K x N] fp32 -> Wt[N x K] split bf16
__global__ void wsplit_t_k(const float* __restrict__ W, __nv_bfloat16* __restrict__ Th,
                           __nv_bfloat16* __restrict__ Tl, int Kd, int N) {
    __shared__ float ts[32][33];
    int k0 = blockIdx.y * 32, n0 = blockIdx.x * 32;
    int tx = threadIdx.x & 31, ty = threadIdx.x >> 5;
    #pragma unroll
    for (int i = 0; i < 32; i += 8)
        ts[ty + i][tx] = W[(long)(k0 + ty + i) * N + n0 + tx];
    __syncthreads();
    #pragma unroll
    for (int i = 0; i < 32; i += 8) {
        float v = ts[tx][ty + i];
        __nv_bfloat16 h = __float2bfloat16(v);
        long gi = (long)(n0 + ty + i) * Kd + k0 + tx;
        Th[gi] = h;
        Tl[gi] = __float2bfloat16(v - __bfloat162float(h));
    }
}

// ---------------- bf16x3 HMMA GEMM ----------------
// C[M x N] = A[M x K] @ B^T + bias,  A split (Ah,Al) [M][K], B split (Bh,Bl) [N][K].
// CTA tile 128x128, K-chunk 32, cp.async double buffer, 8 warps each 64x32.
// EPI: 0 = fp32 out, 1 = fp32 out + residual, 2 = GELU -> split bf16 out
#define GEMM_SMEM_BYTES (2 * 4 * 8192)   // 2 stages x (Ah,Al,Bh,Bl) x 8KB = 64KB

template<int EPI>
__global__ __launch_bounds__(256) void hgemm3_k(
    const __nv_bfloat16* __restrict__ Ah, const __nv_bfloat16* __restrict__ Al,
    const __nv_bfloat16* __restrict__ Bh, const __nv_bfloat16* __restrict__ Bl,
    const float* __restrict__ bias, const float* __restrict__ R,
    float* __restrict__ Cf, __nv_bfloat16* __restrict__ Ch, __nv_bfloat16* __restrict__ Cl,
    int M, int N, int Kd)
{
    extern __shared__ char smem[];
    const uint32_t sbase = smem_u32(smem);
    const int tid = threadIdx.x;
    const int lane = tid & 31, wid = tid >> 5;
    const int wm = wid >> 2, wn = wid & 3;          // warp grid 2 x 4
    const int m0 = blockIdx.y * 128, n0 = blockIdx.x * 128;

    float acc[4][4][4] = {};

    const int nch = Kd >> 5;   // K-chunks of 32

    // ---- chunk loader (cp.async, 16B per op) ----
    auto load_chunk = [&](int c) {
        const uint32_t stg = sbase + (c & 1) * 32768;
        const int k0 = c << 5;
        #pragma unroll
        for (int e = tid; e < 512; e += 256) {
            int row = e >> 2, grp = e & 3;
            uint32_t so = tile_off(row, grp);
            long ga = (long)(m0 + row) * Kd + k0 + grp * 8;
            long gb = (long)(n0 + row) * Kd + k0 + grp * 8;
            cpa16(stg +         so, Ah + ga);
            cpa16(stg +  8192 + so, Al + ga);
            cpa16(stg + 16384 + so, Bh + gb);
            cpa16(stg + 24576 + so, Bl + gb);
        }
        cpa_commit();
    };

    load_chunk(0);

    // ldmatrix lane-address components
    const int arow = lane & 15;            // A: row within m16 tile
    const int akh  = (lane >> 4) & 1;      // A: k half (0/1 -> +16B)
    const int bn   = ((lane >> 4) & 1) * 8 + (lane & 7);  // B: n within n16 pair
    const int bkh  = (lane >> 3) & 1;      // B: k half

    for (int c = 0; c < nch; ++c) {
        if (c + 1 < nch) { load_chunk(c + 1); cpa_wait1(); }
        else             { cpa_wait0(); }
        __syncthreads();

        const uint32_t sA = sbase + (c & 1) * 32768;
        const uint32_t sB = sA + 16384;

        #pragma unroll
        for (int ks = 0; ks < 2; ++ks) {
            // B fragments for all 4 n8 tiles (h and l)
            uint32_t bh[4][2], bl[4][2];
            #pragma unroll
            for (int nt2 = 0; nt2 < 2; ++nt2) {
                int row = wn * 32 + nt2 * 16 + bn;
                int grp = ks * 2 + bkh;
                uint32_t so = tile_off(row, grp);
                LDMX4(bh[nt2*2][0], bh[nt2*2][1], bh[nt2*2+1][0], bh[nt2*2+1][1], sB + so);
                LDMX4(bl[nt2*2][0], bl[nt2*2][1], bl[nt2*2+1][0], bl[nt2*2+1][1], sB + 8192 + so);
            }
            #pragma unroll
            for (int mt = 0; mt < 4; ++mt) {
                int row = wm * 64 + mt * 16 + arow;
                int grp = ks * 2 + akh;
                uint32_t so = tile_off(row, grp);
                uint32_t ah[4], al[4];
                LDMX4(ah[0], ah[1], ah[2], ah[3], sA + so);
                LDMX4(al[0], al[1], al[2], al[3], sA + 8192 + so);
                #pragma unroll
                for (int nt = 0; nt < 4; ++nt) {
                    mma_bf16(acc[mt][nt], ah, bh[nt]);
                    mma_bf16(acc[mt][nt], al, bh[nt]);
                    mma_bf16(acc[mt][nt], ah, bl[nt]);
                }
            }
        }
        __syncthreads();
    }

    // ---- epilogue: direct register -> gmem stores ----
    #pragma unroll
    for (int mt = 0; mt < 4; ++mt) {
        #pragma unroll
        for (int nt = 0; nt < 4; ++nt) {
            int r0 = m0 + wm * 64 + mt * 16 + (lane >> 2);
            int c0 = n0 + wn * 32 + nt * 8 + (lane & 3) * 2;
            float b0 = bias[c0], b1 = bias[c0 + 1];
            #pragma unroll
            for (int half = 0; half < 2; ++half) {
                int row = r0 + half * 8;
                long gi = (long)row * N + c0;
                float v0 = acc[mt][nt][half * 2 + 0] + b0;
                float v1 = acc[mt][nt][half * 2 + 1] + b1;
                if (EPI == 1) {
                    float2 rv = *(const float2*)(R + gi);
                    v0 += rv.x; v1 += rv.y;
                }
                if (EPI == 2) {
                    v0 = 0.5f * v0 * (1.0f + erff(v0 * 0.7071067811865476f));
                    v1 = 0.5f * v1 * (1.0f + erff(v1 * 0.7071067811865476f));
                    __nv_bfloat16 h0 = __float2bfloat16(v0);
                    __nv_bfloat16 h1 = __float2bfloat16(v1);
                    __nv_bfloat162 hp; hp.x = h0; hp.y = h1;
                    __nv_bfloat162 lp;
                    lp.x = __float2bfloat16(v0 - __bfloat162float(h0));
                    lp.y = __float2bfloat16(v1 - __bfloat162float(h1));
                    *(__nv_bfloat162*)(Ch + gi) = hp;
                    *(__nv_bfloat162*)(Cl + gi) = lp;
                } else {
                    float2 o = {v0, v1};
                    *(float2*)(Cf + gi) = o;
                }
            }
        }
    }
}

// ---------------- fused flash attention (fp32, passing R1 version) ----------------
__global__ __launch_bounds__(256) void flash_attn_k(
    const float* __restrict__ Q, const float* __restrict__ Kt,
    const float* __restrict__ V, float* __restrict__ O)
{
    __shared__ float qs[64][68];
    __shared__ float ks[32][68];
    __shared__ float vs[32][68];
    __shared__ float ps[64][36];

    const int qt = blockIdx.x, h = blockIdx.y, b = blockIdx.z;
    const int tid = threadIdx.x;
    const int r = tid >> 2, c = tid & 3;
    const int q0 = qt * 64;
    const float scale = 0.125f;

    for (int t = tid; t < 64 * 16; t += 256) {
        int rr = t >> 4, dc = (t & 15) << 2;
        *(float4*)&qs[rr][dc] =
            *(const float4*)&Q[((long)(b * KQ + q0 + rr)) * DMODEL + h * HD + dc];
    }

    float o[16] = {};
    float m = -INFINITY, l = 0.f;

    for (int n0 = 0; n0 < NKV; n0 += 32) {
        __syncthreads();
        for (int t = tid; t < 32 * 16; t += 256) {
            int rr = t >> 4, dc = (t & 15) << 2;
            long gidx = ((long)(b * NKV + n0 + rr)) * DMODEL + h * HD + dc;
            *(float4*)&ks[rr][dc] = *(const float4*)&Kt[gidx];
            *(float4*)&vs[rr][dc] = *(const float4*)&V[gidx];
        }
        __syncthreads();

        float s[8] = {};
        #pragma unroll
        for (int d4 = 0; d4 < 16; d4++) {
            float4 q4 = *(const float4*)&qs[r][d4 << 2];
            #pragma unroll
            for (int kk = 0; kk < 8; kk++) {
                float4 k4 = *(const float4*)&ks[c + (kk << 2)][d4 << 2];
                s[kk] += q4.x * k4.x + q4.y * k4.y + q4.z * k4.z + q4.w * k4.w;
            }
        }
        float mloc = -INFINITY;
        #pragma unroll
        for (int kk = 0; kk < 8; kk++) { s[kk] *= scale; mloc = fmaxf(mloc, s[kk]); }
        mloc = fmaxf(mloc, __shfl_xor_sync(0xffffffffu, mloc, 1));
        mloc = fmaxf(mloc, __shfl_xor_sync(0xffffffffu, mloc, 2));
        float mnew = fmaxf(m, mloc);
        float corr = __expf(m - mnew);
        float lsum = 0.f;
        #pragma unroll
        for (int kk = 0; kk < 8; kk++) {
            float p = __expf(s[kk] - mnew);
            ps[r][c + (kk << 2)] = p;
            lsum += p;
        }
        lsum += __shfl_xor_sync(0xffffffffu, lsum, 1);
        lsum += __shfl_xor_sync(0xffffffffu, lsum, 2);
        l = l * corr + lsum;
        m = mnew;
        #pragma unroll
        for (int i = 0; i < 16; i++) o[i] *= corr;
        __syncwarp();

        #pragma unroll
        for (int key = 0; key < 32; key++) {
            float p = ps[r][key];
            #pragma unroll
            for (int j = 0; j < 4; j++) {
                float4 v4 = *(const float4*)&vs[key][(c + (j << 2)) << 2];
                o[j * 4 + 0] += p * v4.x;
                o[j * 4 + 1] += p * v4.y;
                o[j * 4 + 2] += p * v4.z;
                o[j * 4 + 3] += p * v4.w;
            }
        }
    }

    float inv = 1.f / l;
    long obase = ((long)(b * KQ + q0 + r)) * DMODEL + h * HD;
    #pragma unroll
    for (int j = 0; j < 4; j++) {
        float4 ov = {o[j*4+0]*inv, o[j*4+1]*inv, o[j*4+2]*inv, o[j*4+3]*inv};
        *(float4*)&O[obase + ((c + (j << 2)) << 2)] = ov;
    }
}

// ---------------- launch ----------------
extern "C" void kernel_launch(void* const* d_in, const int* in_sizes, int n_in,
                              void* d_out, int out_size) {
    const float* query_tokens   = (const float*)d_in[0];
    const float* point_features = (const float*)d_in[1];
    const float* ln_q_g  = (const float*)d_in[2];
    const float* ln_q_b  = (const float*)d_in[3];
    const float* ln_kv_g = (const float*)d_in[4];
    const float* ln_kv_b = (const float*)d_in[5];
    const float* Wq = (const float*)d_in[6];   const float* bq = (const float*)d_in[7];
    const float* Wk = (const float*)d_in[8];   const float* bk = (const float*)d_in[9];
    const float* Wv = (const float*)d_in[10];  const float* bv = (const float*)d_in[11];
    const float* rms_q_w = (const float*)d_in[12];
    const float* rms_k_w = (const float*)d_in[13];
    const float* Wo = (const float*)d_in[14];  const float* bo = (const float*)d_in[15];
    const float* ln_mlp_g = (const float*)d_in[16];
    const float* ln_mlp_b = (const float*)d_in[17];
    const float* W1 = (const float*)d_in[18];  const float* b1 = (const float*)d_in[19];
    const float* W2 = (const float*)d_in[20];  const float* b2 = (const float*)d_in[21];
    float* out = (float*)d_out;

    float *p_q, *p_k, *p_v, *p_ctx, *p_out;
    cudaGetSymbolAddress((void**)&p_q,   g_q);
    cudaGetSymbolAddress((void**)&p_k,   g_k);
    cudaGetSymbolAddress((void**)&p_v,   g_v);
    cudaGetSymbolAddress((void**)&p_ctx, g_ctx);
    cudaGetSymbolAddress((void**)&p_out, g_out);

    __nv_bfloat16 *qln_h,*qln_l,*kvln_h,*kvln_l,*ctx_h,*ctx_l,*hln_h,*hln_l,*m1_h,*m1_l;
    __nv_bfloat16 *wq_h,*wq_l,*wk_h,*wk_l,*wv_h,*wv_l,*wo_h,*wo_l,*w1_h,*w1_l,*w2_h,*w2_l;
    cudaGetSymbolAddress((void**)&qln_h, g_qln_h);  cudaGetSymbolAddress((void**)&qln_l, g_qln_l);
    cudaGetSymbolAddress((void**)&kvln_h, g_kvln_h);cudaGetSymbolAddress((void**)&kvln_l, g_kvln_l);
    cudaGetSymbolAddress((void**)&ctx_h, g_ctx_h);  cudaGetSymbolAddress((void**)&ctx_l, g_ctx_l);
    cudaGetSymbolAddress((void**)&hln_h, g_hln_h);  cudaGetSymbolAddress((void**)&hln_l, g_hln_l);
    cudaGetSymbolAddress((void**)&m1_h, g_m1_h);    cudaGetSymbolAddress((void**)&m1_l, g_m1_l);
    cudaGetSymbolAddress((void**)&wq_h, g_wq_h);    cudaGetSymbolAddress((void**)&wq_l, g_wq_l);
    cudaGetSymbolAddress((void**)&wk_h, g_wk_h);    cudaGetSymbolAddress((void**)&wk_l, g_wk_l);
    cudaGetSymbolAddress((void**)&wv_h, g_wv_h);    cudaGetSymbolAddress((void**)&wv_l, g_wv_l);
    cudaGetSymbolAddress((void**)&wo_h, g_wo_h);    cudaGetSymbolAddress((void**)&wo_l, g_wo_l);
    cudaGetSymbolAddress((void**)&w1_h, g_w1_h);    cudaGetSymbolAddress((void**)&w1_l, g_w1_l);
    cudaGetSymbolAddress((void**)&w2_h, g_w2_h);    cudaGetSymbolAddress((void**)&w2_l, g_w2_l);

    cudaFuncSetAttribute(hgemm3_k<0>, cudaFuncAttributeMaxDynamicSharedMemorySize, GEMM_SMEM_BYTES);
    cudaFuncSetAttribute(hgemm3_k<1>, cudaFuncAttributeMaxDynamicSharedMemorySize, GEMM_SMEM_BYTES);
    cudaFuncSetAttribute(hgemm3_k<2>, cudaFuncAttributeMaxDynamicSharedMemorySize, GEMM_SMEM_BYTES);

    // weight transpose + split
    wsplit_t_k<<<dim3(DMODEL/32, DMODEL/32), 256>>>(Wq, wq_h, wq_l, DMODEL, DMODEL);
    wsplit_t_k<<<dim3(DMODEL/32, DMODEL/32), 256>>>(Wk, wk_h, wk_l, DMODEL, DMODEL);
    wsplit_t_k<<<dim3(DMODEL/32, DMODEL/32), 256>>>(Wv, wv_h, wv_l, DMODEL, DMODEL);
    wsplit_t_k<<<dim3(DMODEL/32, DMODEL/32), 256>>>(Wo, wo_h, wo_l, DMODEL, DMODEL);
    wsplit_t_k<<<dim3(DFF/32,    DMODEL/32), 256>>>(W1, w1_h, w1_l, DMODEL, DFF);
    wsplit_t_k<<<dim3(DMODEL/32, DFF/32),    256>>>(W2, w2_h, w2_l, DFF, DMODEL);

    // pre-LN (split bf16 out)
    layernorm_split_k<<<MQ,  256>>>(query_tokens,   ln_q_g,  ln_q_b,  qln_h,  qln_l,  1e-5f);
    layernorm_split_k<<<MKV, 256>>>(point_features, ln_kv_g, ln_kv_b, kvln_h, kvln_l, 1e-5f);

    // projections (HMMA bf16x3)
    hgemm3_k<0><<<dim3(DMODEL/128, MQ/128),  256, GEMM_SMEM_BYTES>>>(
        qln_h, qln_l, wq_h, wq_l, bq, nullptr, p_q, nullptr, nullptr, MQ, DMODEL, DMODEL);
    rmsnorm_k<<<MQ, 256>>>(p_q, rms_q_w, 1e-6f);
    hgemm3_k<0><<<dim3(DMODEL/128, MKV/128), 256, GEMM_SMEM_BYTES>>>(
        kvln_h, kvln_l, wk_h, wk_l, bk, nullptr, p_k, nullptr, nullptr, MKV, DMODEL, DMODEL);
    rmsnorm_k<<<MKV, 256>>>(p_k, rms_k_w, 1e-6f);
    hgemm3_k<0><<<dim3(DMODEL/128, MKV/128), 256, GEMM_SMEM_BYTES>>>(
        kvln_h, kvln_l, wv_h, wv_l, bv, nullptr, p_v, nullptr, nullptr, MKV, DMODEL, DMODEL);

    // attention (fp32)
    flash_attn_k<<<dim3(KQ/64, NHEAD, BATCH), 256>>>(p_q, p_k, p_v, p_ctx);
    split_k<<<(MQ*DMODEL/4 + 255)/256, 256>>>(p_ctx, ctx_h, ctx_l, (long)MQ*DMODEL/4);

    // output proj + residual
    hgemm3_k<1><<<dim3(DMODEL/128, MQ/128), 256, GEMM_SMEM_BYTES>>>(
        ctx_h, ctx_l, wo_h, wo_l, bo, query_tokens, p_out, nullptr, nullptr, MQ, DMODEL, DMODEL);

    // MLP
    layernorm_split_k<<<MQ, 256>>>(p_out, ln_mlp_g, ln_mlp_b, hln_h, hln_l, 1e-5f);
    hgemm3_k<2><<<dim3(DFF/128, MQ/128), 256, GEMM_SMEM_BYTES>>>(
        hln_h, hln_l, w1_h, w1_l, b1, nullptr, nullptr, m1_h, m1_l, MQ, DFF, DMODEL);
    hgemm3_k<1><<<dim3(DMODEL/128, MQ/128), 256, GEMM_SMEM_BYTES>>>(
        m1_h, m1_l, w2_h, w2_l, b2, p_out, out, nullptr, nullptr, MQ, DMODEL, DFF);
}

// round 4
// speedup vs baseline: 3.9148x; 2.4728x over previous
#include <cuda_runtime.h>
#include <cuda_bf16.h>
#include <math.h>
#include <stdint.h>

// ---------------- problem constants ----------------
#define BATCH 4
#define KQ    512
#define NKV   4096
#define DMODEL 1024
#define NHEAD 16
#define HD    64
#define MQ    (BATCH*KQ)    // 2048
#define MKV   (BATCH*NKV)   // 16384
#define DFF   (4*DMODEL)    // 4096

// ---------------- scratch (device globals, no allocs) ----------------
__device__ float g_q   [MQ  * DMODEL];   // fp32 q proj (pre-rmsnorm)
__device__ float g_k   [MKV * DMODEL];   // fp32 k proj (pre-rmsnorm)
__device__ float g_out [MQ  * DMODEL];

__device__ __nv_bfloat16 g_qln_h [MQ  * DMODEL], g_qln_l [MQ  * DMODEL];
__device__ __nv_bfloat16 g_kvln_h[MKV * DMODEL], g_kvln_l[MKV * DMODEL];
__device__ __nv_bfloat16 g_qh [MQ  * DMODEL], g_ql [MQ  * DMODEL];
__device__ __nv_bfloat16 g_kh [MKV * DMODEL], g_kl [MKV * DMODEL];
__device__ __nv_bfloat16 g_vh [MKV * DMODEL], g_vl [MKV * DMODEL];
__device__ __nv_bfloat16 g_ctx_h [MQ  * DMODEL], g_ctx_l [MQ  * DMODEL];
__device__ __nv_bfloat16 g_hln_h [MQ  * DMODEL], g_hln_l [MQ  * DMODEL];
__device__ __nv_bfloat16 g_m1_h  [MQ  * DFF],    g_m1_l  [MQ  * DFF];

__device__ __nv_bfloat16 g_wq_h[DMODEL*DMODEL], g_wq_l[DMODEL*DMODEL];
__device__ __nv_bfloat16 g_wk_h[DMODEL*DMODEL], g_wk_l[DMODEL*DMODEL];
__device__ __nv_bfloat16 g_wv_h[DMODEL*DMODEL], g_wv_l[DMODEL*DMODEL];
__device__ __nv_bfloat16 g_wo_h[DMODEL*DMODEL], g_wo_l[DMODEL*DMODEL];
__device__ __nv_bfloat16 g_w1_h[DMODEL*DFF],    g_w1_l[DMODEL*DFF];
__device__ __nv_bfloat16 g_w2_h[DFF*DMODEL],    g_w2_l[DFF*DMODEL];

// ---------------- low-level helpers ----------------
__device__ __forceinline__ uint32_t smem_u32(const void* p) {
    uint32_t a;
    asm("{ .reg .u64 t; cvta.to.shared.u64 t, %1; cvt.u32.u64 %0, t; }" : "=r"(a) : "l"(p));
    return a;
}
__device__ __forceinline__ void cpa16(uint32_t saddr, const void* g) {
    asm volatile("cp.async.cg.shared.global [%0], [%1], 16;" :: "r"(saddr), "l"(g));
}
__device__ __forceinline__ void cpa_commit() { asm volatile("cp.async.commit_group;"); }
__device__ __forceinline__ void cpa_wait1()  { asm volatile("cp.async.wait_group 1;"); }
__device__ __forceinline__ void cpa_wait0()  { asm volatile("cp.async.wait_group 0;"); }

#define LDMX4(r0, r1, r2, r3, addr) \
    asm volatile("ldmatrix.sync.aligned.m8n8.x4.shared.b16 {%0,%1,%2,%3}, [%4];" \
        : "=r"(r0), "=r"(r1), "=r"(r2), "=r"(r3) : "r"(addr))

#define LDMX4T(r0, r1, r2, r3, addr) \
    asm volatile("ldmatrix.sync.aligned.m8n8.x4.trans.shared.b16 {%0,%1,%2,%3}, [%4];" \
        : "=r"(r0), "=r"(r1), "=r"(r2), "=r"(r3) : "r"(addr))

__device__ __forceinline__ void mma_bf16(float* d, const uint32_t* a, const uint32_t* b) {
    asm volatile(
        "mma.sync.aligned.m16n8k16.row.col.f32.bf16.bf16.f32 "
        "{%0,%1,%2,%3}, {%4,%5,%6,%7}, {%8,%9}, {%0,%1,%2,%3};"
        : "+f"(d[0]), "+f"(d[1]), "+f"(d[2]), "+f"(d[3])
        : "r"(a[0]), "r"(a[1]), "r"(a[2]), "r"(a[3]), "r"(b[0]), "r"(b[1]));
}

// GEMM smem tile: 128 rows x 64 bytes (32 bf16), 16B group swizzle
__device__ __forceinline__ uint32_t tile_off(int row, int grp) {
    return (uint32_t)(row * 64 + ((grp ^ ((row >> 1) & 3)) << 4));
}
// attention smem tile: rows of 128 bytes (64 bf16), 8 groups, xor swizzle
__device__ __forceinline__ uint32_t aoff(int row, int grp) {
    return (uint32_t)(row * 128 + ((grp ^ (row & 7)) << 4));
}

__device__ __forceinline__ uint32_t pack_split(float lo, float hi, float& rlo, float& rhi) {
    __nv_bfloat162 p = __floats2bfloat162_rn(lo, hi);
    rlo = lo - __bfloat162float(p.x);
    rhi = hi - __bfloat162float(p.y);
    return *reinterpret_cast<uint32_t*>(&p);
}

// ---------------- norm kernels ----------------
__device__ __forceinline__ void block_reduce2(float& s1, float& s2) {
    #pragma unroll
    for (int off = 16; off; off >>= 1) {
        s1 += __shfl_xor_sync(0xffffffffu, s1, off);
        s2 += __shfl_xor_sync(0xffffffffu, s2, off);
    }
    __shared__ float a[8], b[8];
    int w = threadIdx.x >> 5, lane = threadIdx.x & 31;
    if (lane == 0) { a[w] = s1; b[w] = s2; }
    __syncthreads();
    s1 = 0.f; s2 = 0.f;
    #pragma unroll
    for (int i = 0; i < 8; i++) { s1 += a[i]; s2 += b[i]; }
}

__device__ __forceinline__ void split_store(__nv_bfloat16* hp, __nv_bfloat16* lp, long idx,
                                            float v0, float v1, float v2, float v3) {
    float r0, r1, r2, r3;
    uint32_t p01 = pack_split(v0, v1, r0, r1);
    uint32_t p23 = pack_split(v2, v3, r2, r3);
    *(uint32_t*)(hp + idx)     = p01;
    *(uint32_t*)(hp + idx + 2) = p23;
    __nv_bfloat162 l01 = __floats2bfloat162_rn(r0, r1);
    __nv_bfloat162 l23 = __floats2bfloat162_rn(r2, r3);
    *(__nv_bfloat162*)(lp + idx)     = l01;
    *(__nv_bfloat162*)(lp + idx + 2) = l23;
}

__global__ void layernorm_split_k(const float* __restrict__ x, const float* __restrict__ g,
                                  const float* __restrict__ b,
                                  __nv_bfloat16* __restrict__ yh, __nv_bfloat16* __restrict__ yl,
                                  float eps) {
    long row = blockIdx.x;
    float4 xv = ((const float4*)(x + row * DMODEL))[threadIdx.x];
    float s  = xv.x + xv.y + xv.z + xv.w;
    float sq = xv.x*xv.x + xv.y*xv.y + xv.z*xv.z + xv.w*xv.w;
    block_reduce2(s, sq);
    float mu  = s * (1.0f / DMODEL);
    float var = sq * (1.0f / DMODEL) - mu * mu;
    float rstd = rsqrtf(var + eps);
    float4 gv = ((const float4*)g)[threadIdx.x];
    float4 bv = ((const float4*)b)[threadIdx.x];
    float v0 = (xv.x - mu) * rstd * gv.x + bv.x;
    float v1 = (xv.y - mu) * rstd * gv.y + bv.y;
    float v2 = (xv.z - mu) * rstd * gv.z + bv.z;
    float v3 = (xv.w - mu) * rstd * gv.w + bv.w;
    split_store(yh, yl, row * DMODEL + threadIdx.x * 4, v0, v1, v2, v3);
}

__global__ void rmsnorm_split_k(const float* __restrict__ x, const float* __restrict__ w,
                                __nv_bfloat16* __restrict__ yh, __nv_bfloat16* __restrict__ yl,
                                float eps) {
    long row = blockIdx.x;
    float4 xv = ((const float4*)(x + row * DMODEL))[threadIdx.x];
    float sq = xv.x*xv.x + xv.y*xv.y + xv.z*xv.z + xv.w*xv.w;
    float dummy = 0.f;
    block_reduce2(sq, dummy);
    float rstd = rsqrtf(sq * (1.0f / DMODEL) + eps);
    float4 wv = ((const float4*)w)[threadIdx.x];
    split_store(yh, yl, row * DMODEL + threadIdx.x * 4,
                xv.x * rstd * wv.x, xv.y * rstd * wv.y,
                xv.z * rstd * wv.z, xv.w * rstd * wv.w);
}

// W[K x N] fp32 -> Wt[N x K] split bf16
__global__ void wsplit_t_k(const float* __restrict__ W, __nv_bfloat16* __restrict__ Th,
                           __nv_bfloat16* __restrict__ Tl, int Kd, int N) {
    __shared__ float ts[32][33];
    int k0 = blockIdx.y * 32, n0 = blockIdx.x * 32;
    int tx = threadIdx.x & 31, ty = threadIdx.x >> 5;
    #pragma unroll
    for (int i = 0; i < 32; i += 8)
        ts[ty + i][tx] = W[(long)(k0 + ty + i) * N + n0 + tx];
    __syncthreads();
    #pragma unroll
    for (int i = 0; i < 32; i += 8) {
        float v = ts[tx][ty + i];
        __nv_bfloat16 h = __float2bfloat16(v);
        long gi = (long)(n0 + ty + i) * Kd + k0 + tx;
        Th[gi] = h;
        Tl[gi] = __float2bfloat16(v - __bfloat162float(h));
    }
}

// ---------------- bf16x3 HMMA GEMM ----------------
// EPI: 0 = fp32 out, 1 = fp32 out + residual, 2 = GELU -> split bf16, 3 = plain -> split bf16
#define GEMM_SMEM_BYTES (2 * 4 * 8192)

template<int EPI>
__global__ __launch_bounds__(256) void hgemm3_k(
    const __nv_bfloat16* __restrict__ Ah, const __nv_bfloat16* __restrict__ Al,
    const __nv_bfloat16* __restrict__ Bh, const __nv_bfloat16* __restrict__ Bl,
    const float* __restrict__ bias, const float* __restrict__ R,
    float* __restrict__ Cf, __nv_bfloat16* __restrict__ Ch, __nv_bfloat16* __restrict__ Cl,
    int M, int N, int Kd)
{
    extern __shared__ char smem[];
    const uint32_t sbase = smem_u32(smem);
    const int tid = threadIdx.x;
    const int lane = tid & 31, wid = tid >> 5;
    const int wm = wid >> 2, wn = wid & 3;
    const int m0 = blockIdx.y * 128, n0 = blockIdx.x * 128;

    float acc[4][4][4] = {};
    const int nch = Kd >> 5;

    auto load_chunk = [&](int c) {
        const uint32_t stg = sbase + (c & 1) * 32768;
        const int k0 = c << 5;
        #pragma unroll
        for (int e = tid; e < 512; e += 256) {
            int row = e >> 2, grp = e & 3;
            uint32_t so = tile_off(row, grp);
            long ga = (long)(m0 + row) * Kd + k0 + grp * 8;
            long gb = (long)(n0 + row) * Kd + k0 + grp * 8;
            cpa16(stg +         so, Ah + ga);
            cpa16(stg +  8192 + so, Al + ga);
            cpa16(stg + 16384 + so, Bh + gb);
            cpa16(stg + 24576 + so, Bl + gb);
        }
        cpa_commit();
    };

    load_chunk(0);

    const int arow = lane & 15;
    const int akh  = (lane >> 4) & 1;
    const int bn   = ((lane >> 4) & 1) * 8 + (lane & 7);
    const int bkh  = (lane >> 3) & 1;

    for (int c = 0; c < nch; ++c) {
        if (c + 1 < nch) { load_chunk(c + 1); cpa_wait1(); }
        else             { cpa_wait0(); }
        __syncthreads();

        const uint32_t sA = sbase + (c & 1) * 32768;
        const uint32_t sB = sA + 16384;

        #pragma unroll
        for (int ks = 0; ks < 2; ++ks) {
            uint32_t bh[4][2], bl[4][2];
            #pragma unroll
            for (int nt2 = 0; nt2 < 2; ++nt2) {
                int row = wn * 32 + nt2 * 16 + bn;
                int grp = ks * 2 + bkh;
                uint32_t so = tile_off(row, grp);
                LDMX4(bh[nt2*2][0], bh[nt2*2][1], bh[nt2*2+1][0], bh[nt2*2+1][1], sB + so);
                LDMX4(bl[nt2*2][0], bl[nt2*2][1], bl[nt2*2+1][0], bl[nt2*2+1][1], sB + 8192 + so);
            }
            #pragma unroll
            for (int mt = 0; mt < 4; ++mt) {
                int row = wm * 64 + mt * 16 + arow;
                int grp = ks * 2 + akh;
                uint32_t so = tile_off(row, grp);
                uint32_t ah[4], al[4];
                LDMX4(ah[0], ah[1], ah[2], ah[3], sA + so);
                LDMX4(al[0], al[1], al[2], al[3], sA + 8192 + so);
                #pragma unroll
                for (int nt = 0; nt < 4; ++nt) {
                    mma_bf16(acc[mt][nt], ah, bh[nt]);
                    mma_bf16(acc[mt][nt], al, bh[nt]);
                    mma_bf16(acc[mt][nt], ah, bl[nt]);
                }
            }
        }
        __syncthreads();
    }

    #pragma unroll
    for (int mt = 0; mt < 4; ++mt) {
        #pragma unroll
        for (int nt = 0; nt < 4; ++nt) {
            int r0 = m0 + wm * 64 + mt * 16 + (lane >> 2);
            int c0 = n0 + wn * 32 + nt * 8 + (lane & 3) * 2;
            float b0 = bias[c0], b1 = bias[c0 + 1];
            #pragma unroll
            for (int half = 0; half < 2; ++half) {
                int row = r0 + half * 8;
                long gi = (long)row * N + c0;
                float v0 = acc[mt][nt][half * 2 + 0] + b0;
                float v1 = acc[mt][nt][half * 2 + 1] + b1;
                if (EPI == 1) {
                    float2 rv = *(const float2*)(R + gi);
                    v0 += rv.x; v1 += rv.y;
                }
                if (EPI == 2) {
                    v0 = 0.5f * v0 * (1.0f + erff(v0 * 0.7071067811865476f));
                    v1 = 0.5f * v1 * (1.0f + erff(v1 * 0.7071067811865476f));
                }
                if (EPI >= 2) {
                    float r0f, r1f;
                    uint32_t ph = pack_split(v0, v1, r0f, r1f);
                    __nv_bfloat162 pl = __floats2bfloat162_rn(r0f, r1f);
                    *(uint32_t*)(Ch + gi) = ph;
                    *(__nv_bfloat162*)(Cl + gi) = pl;
                } else {
                    float2 o = {v0, v1};
                    *(float2*)(Cf + gi) = o;
                }
            }
        }
    }
}

// ---------------- HMMA flash attention (bf16x3) ----------------
// grid (KQ/64, NHEAD, BATCH), 128 threads (4 warps x 16 q-rows).
// 64-key tiles, 3-stage cp.async pipeline. smem: Q 16KB + 3 x 32KB = 112KB.
#define ATT_SMEM (16384 + 3 * 32768)

__global__ __launch_bounds__(128) void flash_attn_mma(
    const __nv_bfloat16* __restrict__ Qh, const __nv_bfloat16* __restrict__ Ql,
    const __nv_bfloat16* __restrict__ Kh, const __nv_bfloat16* __restrict__ Kl,
    const __nv_bfloat16* __restrict__ Vh, const __nv_bfloat16* __restrict__ Vl,
    __nv_bfloat16* __restrict__ Ch, __nv_bfloat16* __restrict__ Cl)
{
    extern __shared__ char smem[];
    const uint32_t sb = smem_u32(smem);
    const int tid = threadIdx.x, lane = tid & 31, warp = tid >> 5;
    const int q0 = blockIdx.x * 64, h = blockIdx.y, b = blockIdx.z;
    const int wq0 = warp * 16;
    const float scale = 0.125f;   // 1/sqrt(64)

    const uint32_t sQh = sb, sQl = sb + 8192;

    // ---- issue Q + stage0, stage1 loads ----
    {
        const long gq = (long)(b * KQ + q0) * DMODEL + h * HD;
        for (int e = tid; e < 512; e += 128) {
            int row = e >> 3, grp = e & 7;
            long g = gq + (long)row * DMODEL + grp * 8;
            uint32_t so = aoff(row, grp);
            cpa16(sQh + so, Qh + g);
            cpa16(sQl + so, Ql + g);
        }
    }
    #define LOAD_KV(it_) do { \
        const uint32_t st_ = sb + 16384 + ((it_) % 3) * 32768; \
        const long gk_ = (long)(b * NKV + (it_) * 64) * DMODEL + h * HD; \
        for (int e = tid; e < 512; e += 128) { \
            int row = e >> 3, grp = e & 7; \
            long g = gk_ + (long)row * DMODEL + grp * 8; \
            uint32_t so = aoff(row, grp); \
            cpa16(st_ +          so, Kh + g); \
            cpa16(st_ +  8192 + so, Kl + g); \
            cpa16(st_ + 16384 + so, Vh + g); \
            cpa16(st_ + 24576 + so, Vl + g); \
        } \
        cpa_commit(); \
    } while (0)

    LOAD_KV(0);   // group 0 (includes Q)
    LOAD_KV(1);   // group 1

    uint32_t qfh[4][4], qfl[4][4];
    float ctx[8][4] = {};
    float m0 = -INFINITY, m1 = -INFINITY, l0 = 0.f, l1 = 0.f;

    const int NIT = NKV / 64;
    for (int it = 0; it < NIT; ++it) {
        if (it + 1 < NIT) cpa_wait1(); else cpa_wait0();
        __syncthreads();
        if (it == 0) {
            int row = wq0 + (lane & 15);
            #pragma unroll
            for (int ks = 0; ks < 4; ++ks) {
                int grp = ks * 2 + ((lane >> 4) & 1);
                uint32_t so = aoff(row, grp);
                LDMX4(qfh[ks][0], qfh[ks][1], qfh[ks][2], qfh[ks][3], sQh + so);
                LDMX4(qfl[ks][0], qfl[ks][1], qfl[ks][2], qfl[ks][3], sQl + so);
            }
        }
        if (it + 2 < NIT) LOAD_KV(it + 2);

        const uint32_t st  = sb + 16384 + (it % 3) * 32768;
        const uint32_t skh = st, skl = st + 8192, svh = st + 16384, svl = st + 24576;

        // ---- S = Q K^T (bf16x3) ----
        float S[8][4] = {};
        #pragma unroll
        for (int ks = 0; ks < 4; ++ks) {
            uint32_t bh[8][2], bl[8][2];
            #pragma unroll
            for (int kp = 0; kp < 4; ++kp) {
                int row = kp * 16 + ((lane >> 4) & 1) * 8 + (lane & 7);
                int grp = ks * 2 + ((lane >> 3) & 1);
                uint32_t so = aoff(row, grp);
                LDMX4(bh[2*kp][0], bh[2*kp][1], bh[2*kp+1][0], bh[2*kp+1][1], skh + so);
                LDMX4(bl[2*kp][0], bl[2*kp][1], bl[2*kp+1][0], bl[2*kp+1][1], skl + so);
            }
            #pragma unroll
            for (int nt = 0; nt < 8; ++nt) {
                mma_bf16(S[nt], qfh[ks], bh[nt]);
                mma_bf16(S[nt], qfh[ks], bl[nt]);
                mma_bf16(S[nt], qfl[ks], bh[nt]);
            }
        }

        // ---- online softmax (rows r = lane>>2 and r+8) ----
        float mx0 = -INFINITY, mx1 = -INFINITY;
        #pragma unroll
        for (int nt = 0; nt < 8; ++nt) {
            mx0 = fmaxf(mx0, fmaxf(S[nt][0], S[nt][1]));
            mx1 = fmaxf(mx1, fmaxf(S[nt][2], S[nt][3]));
        }
        mx0 = fmaxf(mx0, __shfl_xor_sync(0xffffffffu, mx0, 1));
        mx0 = fmaxf(mx0, __shfl_xor_sync(0xffffffffu, mx0, 2));
        mx1 = fmaxf(mx1, __shfl_xor_sync(0xffffffffu, mx1, 1));
        mx1 = fmaxf(mx1, __shfl_xor_sync(0xffffffffu, mx1, 2));
        float m0n = fmaxf(m0, mx0), m1n = fmaxf(m1, mx1);
        float cr0 = __expf((m0 - m0n) * scale), cr1 = __expf((m1 - m1n) * scale);
        float s0 = 0.f, s1 = 0.f;
        #pragma unroll
        for (int nt = 0; nt < 8; ++nt) {
            S[nt][0] = __expf((S[nt][0] - m0n) * scale);
            S[nt][1] = __expf((S[nt][1] - m0n) * scale);
            S[nt][2] = __expf((S[nt][2] - m1n) * scale);
            S[nt][3] = __expf((S[nt][3] - m1n) * scale);
            s0 += S[nt][0] + S[nt][1];
            s1 += S[nt][2] + S[nt][3];
        }
        s0 += __shfl_xor_sync(0xffffffffu, s0, 1);
        s0 += __shfl_xor_sync(0xffffffffu, s0, 2);
        s1 += __shfl_xor_sync(0xffffffffu, s1, 1);
        s1 += __shfl_xor_sync(0xffffffffu, s1, 2);
        l0 = l0 * cr0 + s0;  l1 = l1 * cr1 + s1;
        m0 = m0n;  m1 = m1n;
        #pragma unroll
        for (int dt = 0; dt < 8; ++dt) {
            ctx[dt][0] *= cr0; ctx[dt][1] *= cr0;
            ctx[dt][2] *= cr1; ctx[dt][3] *= cr1;
        }

        // ---- P fragments (C-frag -> A-frag, register-local) ----
        uint32_t pah[4][4], pal[4][4];
        #pragma unroll
        for (int j = 0; j < 4; ++j) {
            float r0, r1;
            pah[j][0] = pack_split(S[2*j][0],   S[2*j][1],   r0, r1);
            { __nv_bfloat162 t = __floats2bfloat162_rn(r0, r1); pal[j][0] = *(uint32_t*)&t; }
            pah[j][1] = pack_split(S[2*j][2],   S[2*j][3],   r0, r1);
            { __nv_bfloat162 t = __floats2bfloat162_rn(r0, r1); pal[j][1] = *(uint32_t*)&t; }
            pah[j][2] = pack_split(S[2*j+1][0], S[2*j+1][1], r0, r1);
            { __nv_bfloat162 t = __floats2bfloat162_rn(r0, r1); pal[j][2] = *(uint32_t*)&t; }
            pah[j][3] = pack_split(S[2*j+1][2], S[2*j+1][3], r0, r1);
            { __nv_bfloat162 t = __floats2bfloat162_rn(r0, r1); pal[j][3] = *(uint32_t*)&t; }
        }

        // ---- O += P V (bf16x3, V via ldmatrix.trans) ----
        #pragma unroll
        for (int ks = 0; ks < 4; ++ks) {
            uint32_t vbh[8][2], vbl[8][2];
            #pragma unroll
            for (int dp = 0; dp < 4; ++dp) {
                int row = ks * 16 + ((lane >> 3) & 1) * 8 + (lane & 7);
                int grp = dp * 2 + ((lane >> 4) & 1);
                uint32_t so = aoff(row, grp);
                LDMX4T(vbh[2*dp][0], vbh[2*dp][1], vbh[2*dp+1][0], vbh[2*dp+1][1], svh + so);
                LDMX4T(vbl[2*dp][0], vbl[2*dp][1], vbl[2*dp+1][0], vbl[2*dp+1][1], svl + so);
            }
            #pragma unroll
            for (int dt = 0; dt < 8; ++dt) {
                mma_bf16(ctx[dt], pah[ks], vbh[dt]);
                mma_bf16(ctx[dt], pal[ks], vbh[dt]);
                mma_bf16(ctx[dt], pah[ks], vbl[dt]);
            }
        }
        __syncthreads();
    }

    // ---- epilogue: split bf16 ctx ----
    float i0 = 1.f / l0, i1 = 1.f / l1;
    int r0 = q0 + wq0 + (lane >> 2);
    int r1 = r0 + 8;
    #pragma unroll
    for (int dt = 0; dt < 8; ++dt) {
        int col = h * HD + dt * 8 + (lane & 3) * 2;
        long g0 = (long)(b * KQ + r0) * DMODEL + col;
        long g1 = (long)(b * KQ + r1) * DMODEL + col;
        float a0, a1;
        uint32_t ph = pack_split(ctx[dt][0] * i0, ctx[dt][1] * i0, a0, a1);
        __nv_bfloat162 pl = __floats2bfloat162_rn(a0, a1);
        *(uint32_t*)(Ch + g0) = ph;
        *(__nv_bfloat162*)(Cl + g0) = pl;
        ph = pack_split(ctx[dt][2] * i1, ctx[dt][3] * i1, a0, a1);
        pl = __floats2bfloat162_rn(a0, a1);
        *(uint32_t*)(Ch + g1) = ph;
        *(__nv_bfloat162*)(Cl + g1) = pl;
    }
    #undef LOAD_KV
}

// ---------------- launch ----------------
extern "C" void kernel_launch(void* const* d_in, const int* in_sizes, int n_in,
                              void* d_out, int out_size) {
    const float* query_tokens   = (const float*)d_in[0];
    const float* point_features = (const float*)d_in[1];
    const float* ln_q_g  = (const float*)d_in[2];
    const float* ln_q_b  = (const float*)d_in[3];
    const float* ln_kv_g = (const float*)d_in[4];
    const float* ln_kv_b = (const float*)d_in[5];
    const float* Wq = (const float*)d_in[6];   const float* bq = (const float*)d_in[7];
    const float* Wk = (const float*)d_in[8];   const float* bk = (const float*)d_in[9];
    const float* Wv = (const float*)d_in[10];  const float* bv = (const float*)d_in[11];
    const float* rms_q_w = (const float*)d_in[12];
    const float* rms_k_w = (const float*)d_in[13];
    const float* Wo = (const float*)d_in[14];  const float* bo = (const float*)d_in[15];
    const float* ln_mlp_g = (const float*)d_in[16];
    const float* ln_mlp_b = (const float*)d_in[17];
    const float* W1 = (const float*)d_in[18];  const float* b1 = (const float*)d_in[19];
    const float* W2 = (const float*)d_in[20];  const float* b2 = (const float*)d_in[21];
    float* out = (float*)d_out;

    float *p_q, *p_k, *p_out;
    cudaGetSymbolAddress((void**)&p_q,   g_q);
    cudaGetSymbolAddress((void**)&p_k,   g_k);
    cudaGetSymbolAddress((void**)&p_out, g_out);

    __nv_bfloat16 *qln_h,*qln_l,*kvln_h,*kvln_l,*ctx_h,*ctx_l,*hln_h,*hln_l,*m1_h,*m1_l;
    __nv_bfloat16 *qh,*ql,*kh,*kl,*vh,*vl;
    __nv_bfloat16 *wq_h,*wq_l,*wk_h,*wk_l,*wv_h,*wv_l,*wo_h,*wo_l,*w1_h,*w1_l,*w2_h,*w2_l;
    cudaGetSymbolAddress((void**)&qln_h, g_qln_h);  cudaGetSymbolAddress((void**)&qln_l, g_qln_l);
    cudaGetSymbolAddress((void**)&kvln_h, g_kvln_h);cudaGetSymbolAddress((void**)&kvln_l, g_kvln_l);
    cudaGetSymbolAddress((void**)&ctx_h, g_ctx_h);  cudaGetSymbolAddress((void**)&ctx_l, g_ctx_l);
    cudaGetSymbolAddress((void**)&hln_h, g_hln_h);  cudaGetSymbolAddress((void**)&hln_l, g_hln_l);
    cudaGetSymbolAddress((void**)&m1_h, g_m1_h);    cudaGetSymbolAddress((void**)&m1_l, g_m1_l);
    cudaGetSymbolAddress((void**)&qh, g_qh);  cudaGetSymbolAddress((void**)&ql, g_ql);
    cudaGetSymbolAddress((void**)&kh, g_kh);  cudaGetSymbolAddress((void**)&kl, g_kl);
    cudaGetSymbolAddress((void**)&vh, g_vh);  cudaGetSymbolAddress((void**)&vl, g_vl);
    cudaGetSymbolAddress((void**)&wq_h, g_wq_h);    cudaGetSymbolAddress((void**)&wq_l, g_wq_l);
    cudaGetSymbolAddress((void**)&wk_h, g_wk_h);    cudaGetSymbolAddress((void**)&wk_l, g_wk_l);
    cudaGetSymbolAddress((void**)&wv_h, g_wv_h);    cudaGetSymbolAddress((void**)&wv_l, g_wv_l);
    cudaGetSymbolAddress((void**)&wo_h, g_wo_h);    cudaGetSymbolAddress((void**)&wo_l, g_wo_l);
    cudaGetSymbolAddress((void**)&w1_h, g_w1_h);    cudaGetSymbolAddress((void**)&w1_l, g_w1_l);
    cudaGetSymbolAddress((void**)&w2_h, g_w2_h);    cudaGetSymbolAddress((void**)&w2_l, g_w2_l);

    cudaFuncSetAttribute(hgemm3_k<0>, cudaFuncAttributeMaxDynamicSharedMemorySize, GEMM_SMEM_BYTES);
    cudaFuncSetAttribute(hgemm3_k<1>, cudaFuncAttributeMaxDynamicSharedMemorySize, GEMM_SMEM_BYTES);
    cudaFuncSetAttribute(hgemm3_k<2>, cudaFuncAttributeMaxDynamicSharedMemorySize, GEMM_SMEM_BYTES);
    cudaFuncSetAttribute(hgemm3_k<3>, cudaFuncAttributeMaxDynamicSharedMemorySize, GEMM_SMEM_BYTES);
    cudaFuncSetAttribute(flash_attn_mma, cudaFuncAttributeMaxDynamicSharedMemorySize, ATT_SMEM);

    // weight transpose + split
    wsplit_t_k<<<dim3(DMODEL/32, DMODEL/32), 256>>>(Wq, wq_h, wq_l, DMODEL, DMODEL);
    wsplit_t_k<<<dim3(DMODEL/32, DMODEL/32), 256>>>(Wk, wk_h, wk_l, DMODEL, DMODEL);
    wsplit_t_k<<<dim3(DMODEL/32, DMODEL/32), 256>>>(Wv, wv_h, wv_l, DMODEL, DMODEL);
    wsplit_t_k<<<dim3(DMODEL/32, DMODEL/32), 256>>>(Wo, wo_h, wo_l, DMODEL, DMODEL);
    wsplit_t_k<<<dim3(DFF/32,    DMODEL/32), 256>>>(W1, w1_h, w1_l, DMODEL, DFF);
    wsplit_t_k<<<dim3(DMODEL/32, DFF/32),    256>>>(W2, w2_h, w2_l, DFF, DMODEL);

    // pre-LN (split bf16 out)
    layernorm_split_k<<<MQ,  256>>>(query_tokens,   ln_q_g,  ln_q_b,  qln_h,  qln_l,  1e-5f);
    layernorm_split_k<<<MKV, 256>>>(point_features, ln_kv_g, ln_kv_b, kvln_h, kvln_l, 1e-5f);

    // projections
    hgemm3_k<0><<<dim3(DMODEL/128, MQ/128),  256, GEMM_SMEM_BYTES>>>(
        qln_h, qln_l, wq_h, wq_l, bq, nullptr, p_q, nullptr, nullptr, MQ, DMODEL, DMODEL);
    rmsnorm_split_k<<<MQ, 256>>>(p_q, rms_q_w, qh, ql, 1e-6f);
    hgemm3_k<0><<<dim3(DMODEL/128, MKV/128), 256, GEMM_SMEM_BYTES>>>(
        kvln_h, kvln_l, wk_h, wk_l, bk, nullptr, p_k, nullptr, nullptr, MKV, DMODEL, DMODEL);
    rmsnorm_split_k<<<MKV, 256>>>(p_k, rms_k_w, kh, kl, 1e-6f);
    hgemm3_k<3><<<dim3(DMODEL/128, MKV/128), 256, GEMM_SMEM_BYTES>>>(
        kvln_h, kvln_l, wv_h, wv_l, bv, nullptr, nullptr, vh, vl, MKV, DMODEL, DMODEL);

    // attention (HMMA bf16x3)
    flash_attn_mma<<<dim3(KQ/64, NHEAD, BATCH), 128, ATT_SMEM>>>(
        qh, ql, kh, kl, vh, vl, ctx_h, ctx_l);

    // output proj + residual
    hgemm3_k<1><<<dim3(DMODEL/128, MQ/128), 256, GEMM_SMEM_BYTES>>>(
        ctx_h, ctx_l, wo_h, wo_l, bo, query_tokens, p_out, nullptr, nullptr, MQ, DMODEL, DMODEL);

    // MLP
    layernorm_split_k<<<MQ, 256>>>(p_out, ln_mlp_g, ln_mlp_b, hln_h, hln_l, 1e-5f);
    hgemm3_k<2><<<dim3(DFF/128, MQ/128), 256, GEMM_SMEM_BYTES>>>(
        hln_h, hln_l, w1_h, w1_l, b1, nullptr, nullptr, m1_h, m1_l, MQ, DFF, DMODEL);
    hgemm3_k<1><<<dim3(DMODEL/128, MQ/128), 256, GEMM_SMEM_BYTES>>>(
        m1_h, m1_l, w2_h, w2_l, b2, p_out, out, nullptr, nullptr, MQ, DMODEL, DFF);
}

// round 5
// speedup vs baseline: 5.5450x; 1.4164x over previous
#include <cuda_runtime.h>
#include <cuda_fp16.h>
#include <math.h>
#include <stdint.h>

// ---------------- problem constants ----------------
#define BATCH 4
#define KQ    512
#define NKV   4096
#define DMODEL 1024
#define NHEAD 16
#define HD    64
#define MQ    (BATCH*KQ)    // 2048
#define MKV   (BATCH*NKV)   // 16384
#define DFF   (4*DMODEL)    // 4096

// ---------------- scratch (device globals, no allocs) ----------------
__device__ float g_q   [MQ  * DMODEL];   // fp32 q proj (pre-rmsnorm)
__device__ float g_k   [MKV * DMODEL];   // fp32 k proj (pre-rmsnorm)
__device__ float g_out [MQ  * DMODEL];

__device__ __half g_qln_h [MQ  * DMODEL], g_qln_l [MQ  * DMODEL];
__device__ __half g_kvln_h[MKV * DMODEL], g_kvln_l[MKV * DMODEL];
__device__ __half g_qh [MQ  * DMODEL], g_ql [MQ  * DMODEL];
__device__ __half g_kh [MKV * DMODEL];            // K plain (B side)
__device__ __half g_vh [MKV * DMODEL];            // V plain (B side)
__device__ __half g_ctx_h [MQ  * DMODEL], g_ctx_l [MQ  * DMODEL];
__device__ __half g_hln_h [MQ  * DMODEL], g_hln_l [MQ  * DMODEL];
__device__ __half g_m1_h  [MQ  * DFF],    g_m1_l  [MQ  * DFF];

__device__ __half g_wq[DMODEL*DMODEL];
__device__ __half g_wk[DMODEL*DMODEL];
__device__ __half g_wv[DMODEL*DMODEL];
__device__ __half g_wo[DMODEL*DMODEL];
__device__ __half g_w1[DMODEL*DFF];
__device__ __half g_w2[DFF*DMODEL];

// ---------------- low-level helpers ----------------
__device__ __forceinline__ uint32_t smem_u32(const void* p) {
    uint32_t a;
    asm("{ .reg .u64 t; cvta.to.shared.u64 t, %1; cvt.u32.u64 %0, t; }" : "=r"(a) : "l"(p));
    return a;
}
__device__ __forceinline__ void cpa16(uint32_t saddr, const void* g) {
    asm volatile("cp.async.cg.shared.global [%0], [%1], 16;" :: "r"(saddr), "l"(g));
}
__device__ __forceinline__ void cpa_commit() { asm volatile("cp.async.commit_group;"); }
__device__ __forceinline__ void cpa_wait1()  { asm volatile("cp.async.wait_group 1;"); }
__device__ __forceinline__ void cpa_wait0()  { asm volatile("cp.async.wait_group 0;"); }

#define LDMX4(r0, r1, r2, r3, addr) \
    asm volatile("ldmatrix.sync.aligned.m8n8.x4.shared.b16 {%0,%1,%2,%3}, [%4];" \
        : "=r"(r0), "=r"(r1), "=r"(r2), "=r"(r3) : "r"(addr))

#define LDMX4T(r0, r1, r2, r3, addr) \
    asm volatile("ldmatrix.sync.aligned.m8n8.x4.trans.shared.b16 {%0,%1,%2,%3}, [%4];" \
        : "=r"(r0), "=r"(r1), "=r"(r2), "=r"(r3) : "r"(addr))

__device__ __forceinline__ void mma_f16(float* d, const uint32_t* a, const uint32_t* b) {
    asm volatile(
        "mma.sync.aligned.m16n8k16.row.col.f32.f16.f16.f32 "
        "{%0,%1,%2,%3}, {%4,%5,%6,%7}, {%8,%9}, {%0,%1,%2,%3};"
        : "+f"(d[0]), "+f"(d[1]), "+f"(d[2]), "+f"(d[3])
        : "r"(a[0]), "r"(a[1]), "r"(a[2]), "r"(a[3]), "r"(b[0]), "r"(b[1]));
}

// GEMM smem tile: 128 rows x 64 bytes (32 fp16), 16B group swizzle
__device__ __forceinline__ uint32_t tile_off(int row, int grp) {
    return (uint32_t)(row * 64 + ((grp ^ ((row >> 1) & 3)) << 4));
}
// attention smem tile: rows of 128 bytes (64 fp16), 8 groups, xor swizzle
__device__ __forceinline__ uint32_t aoff(int row, int grp) {
    return (uint32_t)(row * 128 + ((grp ^ (row & 7)) << 4));
}

__device__ __forceinline__ uint32_t pack_split(float v0, float v1, float& r0, float& r1) {
    __half2 p = __floats2half2_rn(v0, v1);
    r0 = v0 - __half2float(__low2half(p));
    r1 = v1 - __half2float(__high2half(p));
    return *reinterpret_cast<uint32_t*>(&p);
}

// ---------------- norm kernels ----------------
__device__ __forceinline__ void block_reduce2(float& s1, float& s2) {
    #pragma unroll
    for (int off = 16; off; off >>= 1) {
        s1 += __shfl_xor_sync(0xffffffffu, s1, off);
        s2 += __shfl_xor_sync(0xffffffffu, s2, off);
    }
    __shared__ float a[8], b[8];
    int w = threadIdx.x >> 5, lane = threadIdx.x & 31;
    if (lane == 0) { a[w] = s1; b[w] = s2; }
    __syncthreads();
    s1 = 0.f; s2 = 0.f;
    #pragma unroll
    for (int i = 0; i < 8; i++) { s1 += a[i]; s2 += b[i]; }
}

__device__ __forceinline__ void split_store(__half* hp, __half* lp, long idx,
                                            float v0, float v1, float v2, float v3) {
    float r0, r1, r2, r3;
    uint32_t p01 = pack_split(v0, v1, r0, r1);
    uint32_t p23 = pack_split(v2, v3, r2, r3);
    *(uint32_t*)(hp + idx)     = p01;
    *(uint32_t*)(hp + idx + 2) = p23;
    __half2 l01 = __floats2half2_rn(r0, r1);
    __half2 l23 = __floats2half2_rn(r2, r3);
    *(__half2*)(lp + idx)     = l01;
    *(__half2*)(lp + idx + 2) = l23;
}

__global__ void layernorm_split_k(const float* __restrict__ x, const float* __restrict__ g,
                                  const float* __restrict__ b,
                                  __half* __restrict__ yh, __half* __restrict__ yl,
                                  float eps) {
    long row = blockIdx.x;
    float4 xv = ((const float4*)(x + row * DMODEL))[threadIdx.x];
    float s  = xv.x + xv.y + xv.z + xv.w;
    float sq = xv.x*xv.x + xv.y*xv.y + xv.z*xv.z + xv.w*xv.w;
    block_reduce2(s, sq);
    float mu  = s * (1.0f / DMODEL);
    float var = sq * (1.0f / DMODEL) - mu * mu;
    float rstd = rsqrtf(var + eps);
    float4 gv = ((const float4*)g)[threadIdx.x];
    float4 bv = ((const float4*)b)[threadIdx.x];
    float v0 = (xv.x - mu) * rstd * gv.x + bv.x;
    float v1 = (xv.y - mu) * rstd * gv.y + bv.y;
    float v2 = (xv.z - mu) * rstd * gv.z + bv.z;
    float v3 = (xv.w - mu) * rstd * gv.w + bv.w;
    split_store(yh, yl, row * DMODEL + threadIdx.x * 4, v0, v1, v2, v3);
}

__global__ void rmsnorm_split_k(const float* __restrict__ x, const float* __restrict__ w,
                                __half* __restrict__ yh, __half* __restrict__ yl,
                                float eps) {
    long row = blockIdx.x;
    float4 xv = ((const float4*)(x + row * DMODEL))[threadIdx.x];
    float sq = xv.x*xv.x + xv.y*xv.y + xv.z*xv.z + xv.w*xv.w;
    float dummy = 0.f;
    block_reduce2(sq, dummy);
    float rstd = rsqrtf(sq * (1.0f / DMODEL) + eps);
    float4 wv = ((const float4*)w)[threadIdx.x];
    split_store(yh, yl, row * DMODEL + threadIdx.x * 4,
                xv.x * rstd * wv.x, xv.y * rstd * wv.y,
                xv.z * rstd * wv.z, xv.w * rstd * wv.w);
}

__global__ void rmsnorm_plain_k(const float* __restrict__ x, const float* __restrict__ w,
                                __half* __restrict__ y, float eps) {
    long row = blockIdx.x;
    float4 xv = ((const float4*)(x + row * DMODEL))[threadIdx.x];
    float sq = xv.x*xv.x + xv.y*xv.y + xv.z*xv.z + xv.w*xv.w;
    float dummy = 0.f;
    block_reduce2(sq, dummy);
    float rstd = rsqrtf(sq * (1.0f / DMODEL) + eps);
    float4 wv = ((const float4*)w)[threadIdx.x];
    long idx = row * DMODEL + threadIdx.x * 4;
    __half2 a = __floats2half2_rn(xv.x * rstd * wv.x, xv.y * rstd * wv.y);
    __half2 b = __floats2half2_rn(xv.z * rstd * wv.z, xv.w * rstd * wv.w);
    *(__half2*)(y + idx)     = a;
    *(__half2*)(y + idx + 2) = b;
}

// W[K x N] fp32 -> Wt[N x K] plain fp16
__global__ void wcvt_t_k(const float* __restrict__ W, __half* __restrict__ T, int Kd, int N) {
    __shared__ float ts[32][33];
    int k0 = blockIdx.y * 32, n0 = blockIdx.x * 32;
    int tx = threadIdx.x & 31, ty = threadIdx.x >> 5;
    #pragma unroll
    for (int i = 0; i < 32; i += 8)
        ts[ty + i][tx] = W[(long)(k0 + ty + i) * N + n0 + tx];
    __syncthreads();
    #pragma unroll
    for (int i = 0; i < 32; i += 8)
        T[(long)(n0 + ty + i) * Kd + k0 + tx] = __float2half(ts[tx][ty + i]);
}

// ---------------- fp16x2 HMMA GEMM ----------------
// C[M x N] = A[M x K] @ B^T + bias. A split (Ah,Al), B plain fp16 [N x K].
// EPI: 0 = fp32 out, 1 = fp32 out + residual, 2 = GELU -> split fp16,
//      3 = plain -> split fp16, 4 = plain fp16 single
#define GEMM_SMEM_BYTES (2 * 3 * 8192)   // 48KB

template<int EPI>
__global__ __launch_bounds__(256) void hgemm2_k(
    const __half* __restrict__ Ah, const __half* __restrict__ Al,
    const __half* __restrict__ B,
    const float* __restrict__ bias, const float* __restrict__ R,
    float* __restrict__ Cf, __half* __restrict__ Ch, __half* __restrict__ Cl,
    int M, int N, int Kd)
{
    extern __shared__ char smem[];
    const uint32_t sbase = smem_u32(smem);
    const int tid = threadIdx.x;
    const int lane = tid & 31, wid = tid >> 5;
    const int wm = wid >> 2, wn = wid & 3;
    const int m0 = blockIdx.y * 128, n0 = blockIdx.x * 128;

    float acc[4][4][4] = {};
    const int nch = Kd >> 5;

    auto load_chunk = [&](int c) {
        const uint32_t stg = sbase + (c & 1) * 24576;
        const int k0 = c << 5;
        #pragma unroll
        for (int e = tid; e < 512; e += 256) {
            int row = e >> 2, grp = e & 3;
            uint32_t so = tile_off(row, grp);
            long ga = (long)(m0 + row) * Kd + k0 + grp * 8;
            long gb = (long)(n0 + row) * Kd + k0 + grp * 8;
            cpa16(stg +         so, Ah + ga);
            cpa16(stg +  8192 + so, Al + ga);
            cpa16(stg + 16384 + so, B + gb);
        }
        cpa_commit();
    };

    load_chunk(0);

    const int arow = lane & 15;
    const int akh  = (lane >> 4) & 1;
    const int bn   = ((lane >> 4) & 1) * 8 + (lane & 7);
    const int bkh  = (lane >> 3) & 1;

    for (int c = 0; c < nch; ++c) {
        if (c + 1 < nch) { load_chunk(c + 1); cpa_wait1(); }
        else             { cpa_wait0(); }
        __syncthreads();

        const uint32_t sA = sbase + (c & 1) * 24576;
        const uint32_t sB = sA + 16384;

        #pragma unroll
        for (int ks = 0; ks < 2; ++ks) {
            uint32_t bh[4][2];
            #pragma unroll
            for (int nt2 = 0; nt2 < 2; ++nt2) {
                int row = wn * 32 + nt2 * 16 + bn;
                int grp = ks * 2 + bkh;
                uint32_t so = tile_off(row, grp);
                LDMX4(bh[nt2*2][0], bh[nt2*2][1], bh[nt2*2+1][0], bh[nt2*2+1][1], sB + so);
            }
            #pragma unroll
            for (int mt = 0; mt < 4; ++mt) {
                int row = wm * 64 + mt * 16 + arow;
                int grp = ks * 2 + akh;
                uint32_t so = tile_off(row, grp);
                uint32_t ah[4], al[4];
                LDMX4(ah[0], ah[1], ah[2], ah[3], sA + so);
                LDMX4(al[0], al[1], al[2], al[3], sA + 8192 + so);
                #pragma unroll
                for (int nt = 0; nt < 4; ++nt) {
                    mma_f16(acc[mt][nt], ah, bh[nt]);
                    mma_f16(acc[mt][nt], al, bh[nt]);
                }
            }
        }
        __syncthreads();
    }

    #pragma unroll
    for (int mt = 0; mt < 4; ++mt) {
        #pragma unroll
        for (int nt = 0; nt < 4; ++nt) {
            int r0 = m0 + wm * 64 + mt * 16 + (lane >> 2);
            int c0 = n0 + wn * 32 + nt * 8 + (lane & 3) * 2;
            float b0 = bias[c0], b1 = bias[c0 + 1];
            #pragma unroll
            for (int half = 0; half < 2; ++half) {
                int row = r0 + half * 8;
                long gi = (long)row * N + c0;
                float v0 = acc[mt][nt][half * 2 + 0] + b0;
                float v1 = acc[mt][nt][half * 2 + 1] + b1;
                if (EPI == 1) {
                    float2 rv = *(const float2*)(R + gi);
                    v0 += rv.x; v1 += rv.y;
                }
                if (EPI == 2) {
                    v0 = 0.5f * v0 * (1.0f + erff(v0 * 0.7071067811865476f));
                    v1 = 0.5f * v1 * (1.0f + erff(v1 * 0.7071067811865476f));
                }
                if (EPI == 2 || EPI == 3) {
                    float r0f, r1f;
                    uint32_t ph = pack_split(v0, v1, r0f, r1f);
                    __half2 pl = __floats2half2_rn(r0f, r1f);
                    *(uint32_t*)(Ch + gi) = ph;
                    *(__half2*)(Cl + gi) = pl;
                } else if (EPI == 4) {
                    __half2 ph = __floats2half2_rn(v0, v1);
                    *(__half2*)(Ch + gi) = ph;
                } else {
                    float2 o = {v0, v1};
                    *(float2*)(Cf + gi) = o;
                }
            }
        }
    }
}

// ---------------- HMMA flash attention (fp16x2) ----------------
// grid (KQ/64, NHEAD, BATCH), 128 threads (4 warps x 16 q-rows).
// 64-key tiles, 3-stage cp.async. smem: Q 16KB + 3 x 16KB = 64KB.
#define ATT_SMEM (16384 + 3 * 16384)

__global__ __launch_bounds__(128) void flash_attn_mma(
    const __half* __restrict__ Qh, const __half* __restrict__ Ql,
    const __half* __restrict__ K,  const __half* __restrict__ V,
    __half* __restrict__ Ch, __half* __restrict__ Cl)
{
    extern __shared__ char smem[];
    const uint32_t sb = smem_u32(smem);
    const int tid = threadIdx.x, lane = tid & 31, warp = tid >> 5;
    const int q0 = blockIdx.x * 64, h = blockIdx.y, b = blockIdx.z;
    const int wq0 = warp * 16;
    const float scale = 0.125f;   // 1/sqrt(64)

    const uint32_t sQh = sb, sQl = sb + 8192;

    {
        const long gq = (long)(b * KQ + q0) * DMODEL + h * HD;
        for (int e = tid; e < 512; e += 128) {
            int row = e >> 3, grp = e & 7;
            long g = gq + (long)row * DMODEL + grp * 8;
            uint32_t so = aoff(row, grp);
            cpa16(sQh + so, Qh + g);
            cpa16(sQl + so, Ql + g);
        }
    }
    #define LOAD_KV(it_) do { \
        const uint32_t st_ = sb + 16384 + ((it_) % 3) * 16384; \
        const long gk_ = (long)(b * NKV + (it_) * 64) * DMODEL + h * HD; \
        for (int e = tid; e < 512; e += 128) { \
            int row = e >> 3, grp = e & 7; \
            long g = gk_ + (long)row * DMODEL + grp * 8; \
            uint32_t so = aoff(row, grp); \
            cpa16(st_ +        so, K + g); \
            cpa16(st_ + 8192 + so, V + g); \
        } \
        cpa_commit(); \
    } while (0)

    LOAD_KV(0);
    LOAD_KV(1);

    uint32_t qfh[4][4], qfl[4][4];
    float ctx[8][4] = {};
    float m0 = -INFINITY, m1 = -INFINITY, l0 = 0.f, l1 = 0.f;

    const int NIT = NKV / 64;
    for (int it = 0; it < NIT; ++it) {
        if (it + 1 < NIT) cpa_wait1(); else cpa_wait0();
        __syncthreads();
        if (it == 0) {
            int row = wq0 + (lane & 15);
            #pragma unroll
            for (int ks = 0; ks < 4; ++ks) {
                int grp = ks * 2 + ((lane >> 4) & 1);
                uint32_t so = aoff(row, grp);
                LDMX4(qfh[ks][0], qfh[ks][1], qfh[ks][2], qfh[ks][3], sQh + so);
                LDMX4(qfl[ks][0], qfl[ks][1], qfl[ks][2], qfl[ks][3], sQl + so);
            }
        }
        if (it + 2 < NIT) LOAD_KV(it + 2);

        const uint32_t st  = sb + 16384 + (it % 3) * 16384;
        const uint32_t skh = st, svh = st + 8192;

        // ---- S = Q K^T ----
        float S[8][4] = {};
        #pragma unroll
        for (int ks = 0; ks < 4; ++ks) {
            uint32_t bh[8][2];
            #pragma unroll
            for (int kp = 0; kp < 4; ++kp) {
                int row = kp * 16 + ((lane >> 4) & 1) * 8 + (lane & 7);
                int grp = ks * 2 + ((lane >> 3) & 1);
                uint32_t so = aoff(row, grp);
                LDMX4(bh[2*kp][0], bh[2*kp][1], bh[2*kp+1][0], bh[2*kp+1][1], skh + so);
            }
            #pragma unroll
            for (int nt = 0; nt < 8; ++nt) {
                mma_f16(S[nt], qfh[ks], bh[nt]);
                mma_f16(S[nt], qfl[ks], bh[nt]);
            }
        }

        // ---- online softmax ----
        float mx0 = -INFINITY, mx1 = -INFINITY;
        #pragma unroll
        for (int nt = 0; nt < 8; ++nt) {
            mx0 = fmaxf(mx0, fmaxf(S[nt][0], S[nt][1]));
            mx1 = fmaxf(mx1, fmaxf(S[nt][2], S[nt][3]));
        }
        mx0 = fmaxf(mx0, __shfl_xor_sync(0xffffffffu, mx0, 1));
        mx0 = fmaxf(mx0, __shfl_xor_sync(0xffffffffu, mx0, 2));
        mx1 = fmaxf(mx1, __shfl_xor_sync(0xffffffffu, mx1, 1));
        mx1 = fmaxf(mx1, __shfl_xor_sync(0xffffffffu, mx1, 2));
        float m0n = fmaxf(m0, mx0), m1n = fmaxf(m1, mx1);
        float cr0 = __expf((m0 - m0n) * scale), cr1 = __expf((m1 - m1n) * scale);
        float s0 = 0.f, s1 = 0.f;
        #pragma unroll
        for (int nt = 0; nt < 8; ++nt) {
            S[nt][0] = __expf((S[nt][0] - m0n) * scale);
            S[nt][1] = __expf((S[nt][1] - m0n) * scale);
            S[nt][2] = __expf((S[nt][2] - m1n) * scale);
            S[nt][3] = __expf((S[nt][3] - m1n) * scale);
            s0 += S[nt][0] + S[nt][1];
            s1 += S[nt][2] + S[nt][3];
        }
        s0 += __shfl_xor_sync(0xffffffffu, s0, 1);
        s0 += __shfl_xor_sync(0xffffffffu, s0, 2);
        s1 += __shfl_xor_sync(0xffffffffu, s1, 1);
        s1 += __shfl_xor_sync(0xffffffffu, s1, 2);
        l0 = l0 * cr0 + s0;  l1 = l1 * cr1 + s1;
        m0 = m0n;  m1 = m1n;
        #pragma unroll
        for (int dt = 0; dt < 8; ++dt) {
            ctx[dt][0] *= cr0; ctx[dt][1] *= cr0;
            ctx[dt][2] *= cr1; ctx[dt][3] *= cr1;
        }

        // ---- P fragments (split fp16, register-local) ----
        uint32_t pah[4][4], pal[4][4];
        #pragma unroll
        for (int j = 0; j < 4; ++j) {
            float r0, r1;
            pah[j][0] = pack_split(S[2*j][0],   S[2*j][1],   r0, r1);
            { __half2 t = __floats2half2_rn(r0, r1); pal[j][0] = *(uint32_t*)&t; }
            pah[j][1] = pack_split(S[2*j][2],   S[2*j][3],   r0, r1);
            { __half2 t = __floats2half2_rn(r0, r1); pal[j][1] = *(uint32_t*)&t; }
            pah[j][2] = pack_split(S[2*j+1][0], S[2*j+1][1], r0, r1);
            { __half2 t = __floats2half2_rn(r0, r1); pal[j][2] = *(uint32_t*)&t; }
            pah[j][3] = pack_split(S[2*j+1][2], S[2*j+1][3], r0, r1);
            { __half2 t = __floats2half2_rn(r0, r1); pal[j][3] = *(uint32_t*)&t; }
        }

        // ---- O += P V ----
        #pragma unroll
        for (int ks = 0; ks < 4; ++ks) {
            uint32_t vbh[8][2];
            #pragma unroll
            for (int dp = 0; dp < 4; ++dp) {
                int row = ks * 16 + ((lane >> 3) & 1) * 8 + (lane & 7);
                int grp = dp * 2 + ((lane >> 4) & 1);
                uint32_t so = aoff(row, grp);
                LDMX4T(vbh[2*dp][0], vbh[2*dp][1], vbh[2*dp+1][0], vbh[2*dp+1][1], svh + so);
            }
            #pragma unroll
            for (int dt = 0; dt < 8; ++dt) {
                mma_f16(ctx[dt], pah[ks], vbh[dt]);
                mma_f16(ctx[dt], pal[ks], vbh[dt]);
            }
        }
        __syncthreads();
    }

    // ---- epilogue: split fp16 ctx ----
    float i0 = 1.f / l0, i1 = 1.f / l1;
    int r0 = q0 + wq0 + (lane >> 2);
    int r1 = r0 + 8;
    #pragma unroll
    for (int dt = 0; dt < 8; ++dt) {
        int col = h * HD + dt * 8 + (lane & 3) * 2;
        long g0 = (long)(b * KQ + r0) * DMODEL + col;
        long g1 = (long)(b * KQ + r1) * DMODEL + col;
        float a0, a1;
        uint32_t ph = pack_split(ctx[dt][0] * i0, ctx[dt][1] * i0, a0, a1);
        __half2 pl = __floats2half2_rn(a0, a1);
        *(uint32_t*)(Ch + g0) = ph;
        *(__half2*)(Cl + g0) = pl;
        ph = pack_split(ctx[dt][2] * i1, ctx[dt][3] * i1, a0, a1);
        pl = __floats2half2_rn(a0, a1);
        *(uint32_t*)(Ch + g1) = ph;
        *(__half2*)(Cl + g1) = pl;
    }
    #undef LOAD_KV
}

// ---------------- launch ----------------
extern "C" void kernel_launch(void* const* d_in, const int* in_sizes, int n_in,
                              void* d_out, int out_size) {
    const float* query_tokens   = (const float*)d_in[0];
    const float* point_features = (const float*)d_in[1];
    const float* ln_q_g  = (const float*)d_in[2];
    const float* ln_q_b  = (const float*)d_in[3];
    const float* ln_kv_g = (const float*)d_in[4];
    const float* ln_kv_b = (const float*)d_in[5];
    const float* Wq = (const float*)d_in[6];   const float* bq = (const float*)d_in[7];
    const float* Wk = (const float*)d_in[8];   const float* bk = (const float*)d_in[9];
    const float* Wv = (const float*)d_in[10];  const float* bv = (const float*)d_in[11];
    const float* rms_q_w = (const float*)d_in[12];
    const float* rms_k_w = (const float*)d_in[13];
    const float* Wo = (const float*)d_in[14];  const float* bo = (const float*)d_in[15];
    const float* ln_mlp_g = (const float*)d_in[16];
    const float* ln_mlp_b = (const float*)d_in[17];
    const float* W1 = (const float*)d_in[18];  const float* b1 = (const float*)d_in[19];
    const float* W2 = (const float*)d_in[20];  const float* b2 = (const float*)d_in[21];
    float* out = (float*)d_out;

    float *p_q, *p_k, *p_out;
    cudaGetSymbolAddress((void**)&p_q,   g_q);
    cudaGetSymbolAddress((void**)&p_k,   g_k);
    cudaGetSymbolAddress((void**)&p_out, g_out);

    __half *qln_h,*qln_l,*kvln_h,*kvln_l,*ctx_h,*ctx_l,*hln_h,*hln_l,*m1_h,*m1_l;
    __half *qh,*ql,*kh,*vh;
    __half *wq,*wk,*wv,*wo,*w1,*w2;
    cudaGetSymbolAddress((void**)&qln_h, g_qln_h);  cudaGetSymbolAddress((void**)&qln_l, g_qln_l);
    cudaGetSymbolAddress((void**)&kvln_h, g_kvln_h);cudaGetSymbolAddress((void**)&kvln_l, g_kvln_l);
    cudaGetSymbolAddress((void**)&ctx_h, g_ctx_h);  cudaGetSymbolAddress((void**)&ctx_l, g_ctx_l);
    cudaGetSymbolAddress((void**)&hln_h, g_hln_h);  cudaGetSymbolAddress((void**)&hln_l, g_hln_l);
    cudaGetSymbolAddress((void**)&m1_h, g_m1_h);    cudaGetSymbolAddress((void**)&m1_l, g_m1_l);
    cudaGetSymbolAddress((void**)&qh, g_qh);  cudaGetSymbolAddress((void**)&ql, g_ql);
    cudaGetSymbolAddress((void**)&kh, g_kh);  cudaGetSymbolAddress((void**)&vh, g_vh);
    cudaGetSymbolAddress((void**)&wq, g_wq);  cudaGetSymbolAddress((void**)&wk, g_wk);
    cudaGetSymbolAddress((void**)&wv, g_wv);  cudaGetSymbolAddress((void**)&wo, g_wo);
    cudaGetSymbolAddress((void**)&w1, g_w1);  cudaGetSymbolAddress((void**)&w2, g_w2);

    cudaFuncSetAttribute(hgemm2_k<0>, cudaFuncAttributeMaxDynamicSharedMemorySize, GEMM_SMEM_BYTES);
    cudaFuncSetAttribute(hgemm2_k<1>, cudaFuncAttributeMaxDynamicSharedMemorySize, GEMM_SMEM_BYTES);
    cudaFuncSetAttribute(hgemm2_k<2>, cudaFuncAttributeMaxDynamicSharedMemorySize, GEMM_SMEM_BYTES);
    cudaFuncSetAttribute(hgemm2_k<3>, cudaFuncAttributeMaxDynamicSharedMemorySize, GEMM_SMEM_BYTES);
    cudaFuncSetAttribute(hgemm2_k<4>, cudaFuncAttributeMaxDynamicSharedMemorySize, GEMM_SMEM_BYTES);
    cudaFuncSetAttribute(flash_attn_mma, cudaFuncAttributeMaxDynamicSharedMemorySize, ATT_SMEM);

    // weight transpose + fp16 convert
    wcvt_t_k<<<dim3(DMODEL/32, DMODEL/32), 256>>>(Wq, wq, DMODEL, DMODEL);
    wcvt_t_k<<<dim3(DMODEL/32, DMODEL/32), 256>>>(Wk, wk, DMODEL, DMODEL);
    wcvt_t_k<<<dim3(DMODEL/32, DMODEL/32), 256>>>(Wv, wv, DMODEL, DMODEL);
    wcvt_t_k<<<dim3(DMODEL/32, DMODEL/32), 256>>>(Wo, wo, DMODEL, DMODEL);
    wcvt_t_k<<<dim3(DFF/32,    DMODEL/32), 256>>>(W1, w1, DMODEL, DFF);
    wcvt_t_k<<<dim3(DMODEL/32, DFF/32),    256>>>(W2, w2, DFF, DMODEL);

    // pre-LN (split fp16 out)
    layernorm_split_k<<<MQ,  256>>>(query_tokens,   ln_q_g,  ln_q_b,  qln_h,  qln_l,  1e-5f);
    layernorm_split_k<<<MKV, 256>>>(point_features, ln_kv_g, ln_kv_b, kvln_h, kvln_l, 1e-5f);

    // projections
    hgemm2_k<0><<<dim3(DMODEL/128, MQ/128),  256, GEMM_SMEM_BYTES>>>(
        qln_h, qln_l, wq, bq, nullptr, p_q, nullptr, nullptr, MQ, DMODEL, DMODEL);
    rmsnorm_split_k<<<MQ, 256>>>(p_q, rms_q_w, qh, ql, 1e-6f);
    hgemm2_k<0><<<dim3(DMODEL/128, MKV/128), 256, GEMM_SMEM_BYTES>>>(
        kvln_h, kvln_l, wk, bk, nullptr, p_k, nullptr, nullptr, MKV, DMODEL, DMODEL);
    rmsnorm_plain_k<<<MKV, 256>>>(p_k, rms_k_w, kh, 1e-6f);
    hgemm2_k<4><<<dim3(DMODEL/128, MKV/128), 256, GEMM_SMEM_BYTES>>>(
        kvln_h, kvln_l, wv, bv, nullptr, nullptr, vh, nullptr, MKV, DMODEL, DMODEL);

    // attention
    flash_attn_mma<<<dim3(KQ/64, NHEAD, BATCH), 128, ATT_SMEM>>>(
        qh, ql, kh, vh, ctx_h, ctx_l);

    // output proj + residual
    hgemm2_k<1><<<dim3(DMODEL/128, MQ/128), 256, GEMM_SMEM_BYTES>>>(
        ctx_h, ctx_l, wo, bo, query_tokens, p_out, nullptr, nullptr, MQ, DMODEL, DMODEL);

    // MLP
    layernorm_split_k<<<MQ, 256>>>(p_out, ln_mlp_g, ln_mlp_b, hln_h, hln_l, 1e-5f);
    hgemm2_k<2><<<dim3(DFF/128, MQ/128), 256, GEMM_SMEM_BYTES>>>(
        hln_h, hln_l, w1, b1, nullptr, nullptr, m1_h, m1_l, MQ, DFF, DMODEL);
    hgemm2_k<1><<<dim3(DMODEL/128, MQ/128), 256, GEMM_SMEM_BYTES>>>(
        m1_h, m1_l, w2, b2, p_out, out, nullptr, nullptr, MQ, DMODEL, DFF);
}

// round 7
// speedup vs baseline: 8.8561x; 1.5971x over previous
#include <cuda_runtime.h>
#include <cuda_fp16.h>
#include <math.h>
#include <stdint.h>

// ---------------- problem constants ----------------
#define BATCH 4
#define KQ    512
#define NKV   4096
#define DMODEL 1024
#define NHEAD 16
#define HD    64
#define MQ    (BATCH*KQ)    // 2048
#define MKV   (BATCH*NKV)   // 16384
#define DFF   (4*DMODEL)    // 4096

// ---------------- scratch (device globals, no allocs) ----------------
__device__ float g_q   [MQ  * DMODEL];   // fp32 q proj (pre-rmsnorm)
__device__ float g_k   [MKV * DMODEL];   // fp32 k proj (pre-rmsnorm)
__device__ float g_out [MQ  * DMODEL];

__device__ __half g_qln [MQ  * DMODEL];
__device__ __half g_kvln[MKV * DMODEL];
__device__ __half g_qh  [MQ  * DMODEL];
__device__ __half g_kh  [MKV * DMODEL];
__device__ __half g_vh  [MKV * DMODEL];
__device__ __half g_ctx [MQ  * DMODEL];
__device__ __half g_hln [MQ  * DMODEL];
__device__ __half g_m1  [MQ  * DFF];

__device__ __half g_wq[DMODEL*DMODEL];
__device__ __half g_wk[DMODEL*DMODEL];
__device__ __half g_wv[DMODEL*DMODEL];
__device__ __half g_wo[DMODEL*DMODEL];
__device__ __half g_w1[DMODEL*DFF];
__device__ __half g_w2[DFF*DMODEL];

// ---------------- low-level helpers ----------------
__device__ __forceinline__ uint32_t smem_u32(const void* p) {
    uint32_t a;
    asm("{ .reg .u64 t; cvta.to.shared.u64 t, %1; cvt.u32.u64 %0, t; }" : "=r"(a) : "l"(p));
    return a;
}
__device__ __forceinline__ void cpa16(uint32_t saddr, const void* g) {
    asm volatile("cp.async.cg.shared.global [%0], [%1], 16;" :: "r"(saddr), "l"(g));
}
__device__ __forceinline__ void cpa_commit() { asm volatile("cp.async.commit_group;"); }
__device__ __forceinline__ void cpa_wait1()  { asm volatile("cp.async.wait_group 1;"); }
__device__ __forceinline__ void cpa_wait0()  { asm volatile("cp.async.wait_group 0;"); }

#define LDMX4(r0, r1, r2, r3, addr) \
    asm volatile("ldmatrix.sync.aligned.m8n8.x4.shared.b16 {%0,%1,%2,%3}, [%4];" \
        : "=r"(r0), "=r"(r1), "=r"(r2), "=r"(r3) : "r"(addr))

#define LDMX4T(r0, r1, r2, r3, addr) \
    asm volatile("ldmatrix.sync.aligned.m8n8.x4.trans.shared.b16 {%0,%1,%2,%3}, [%4];" \
        : "=r"(r0), "=r"(r1), "=r"(r2), "=r"(r3) : "r"(addr))

__device__ __forceinline__ void mma_f16(float* d, const uint32_t* a, const uint32_t* b) {
    asm volatile(
        "mma.sync.aligned.m16n8k16.row.col.f32.f16.f16.f32 "
        "{%0,%1,%2,%3}, {%4,%5,%6,%7}, {%8,%9}, {%0,%1,%2,%3};"
        : "+f"(d[0]), "+f"(d[1]), "+f"(d[2]), "+f"(d[3])
        : "r"(a[0]), "r"(a[1]), "r"(a[2]), "r"(a[3]), "r"(b[0]), "r"(b[1]));
}

// GEMM smem tile: 128 rows x 64 bytes (32 fp16), 16B group swizzle
__device__ __forceinline__ uint32_t tile_off(int row, int grp) {
    return (uint32_t)(row * 64 + ((grp ^ ((row >> 1) & 3)) << 4));
}
// attention smem tile: rows of 128 bytes (64 fp16), 8 groups, xor swizzle
__device__ __forceinline__ uint32_t aoff(int row, int grp) {
    return (uint32_t)(row * 128 + ((grp ^ (row & 7)) << 4));
}

// ---------------- norm kernels ----------------
__device__ __forceinline__ void block_reduce2(float& s1, float& s2) {
    #pragma unroll
    for (int off = 16; off; off >>= 1) {
        s1 += __shfl_xor_sync(0xffffffffu, s1, off);
        s2 += __shfl_xor_sync(0xffffffffu, s2, off);
    }
    __shared__ float a[8], b[8];
    int w = threadIdx.x >> 5, lane = threadIdx.x & 31;
    if (lane == 0) { a[w] = s1; b[w] = s2; }
    __syncthreads();
    s1 = 0.f; s2 = 0.f;
    #pragma unroll
    for (int i = 0; i < 8; i++) { s1 += a[i]; s2 += b[i]; }
}

__global__ void layernorm_h_k(const float* __restrict__ x, const float* __restrict__ g,
                              const float* __restrict__ b, __half* __restrict__ y, float eps) {
    long row = blockIdx.x;
    float4 xv = ((const float4*)(x + row * DMODEL))[threadIdx.x];
    float s  = xv.x + xv.y + xv.z + xv.w;
    float sq = xv.x*xv.x + xv.y*xv.y + xv.z*xv.z + xv.w*xv.w;
    block_reduce2(s, sq);
    float mu  = s * (1.0f / DMODEL);
    float var = sq * (1.0f / DMODEL) - mu * mu;
    float rstd = rsqrtf(var + eps);
    float4 gv = ((const float4*)g)[threadIdx.x];
    float4 bv = ((const float4*)b)[threadIdx.x];
    long idx = row * DMODEL + threadIdx.x * 4;
    __half2 a = __floats2half2_rn((xv.x - mu) * rstd * gv.x + bv.x,
                                  (xv.y - mu) * rstd * gv.y + bv.y);
    __half2 c = __floats2half2_rn((xv.z - mu) * rstd * gv.z + bv.z,
                                  (xv.w - mu) * rstd * gv.w + bv.w);
    *(__half2*)(y + idx)     = a;
    *(__half2*)(y + idx + 2) = c;
}

__global__ void rmsnorm_h_k(const float* __restrict__ x, const float* __restrict__ w,
                            __half* __restrict__ y, float eps) {
    long row = blockIdx.x;
    float4 xv = ((const float4*)(x + row * DMODEL))[threadIdx.x];
    float sq = xv.x*xv.x + xv.y*xv.y + xv.z*xv.z + xv.w*xv.w;
    float dummy = 0.f;
    block_reduce2(sq, dummy);
    float rstd = rsqrtf(sq * (1.0f / DMODEL) + eps);
    float4 wv = ((const float4*)w)[threadIdx.x];
    long idx = row * DMODEL + threadIdx.x * 4;
    __half2 a = __floats2half2_rn(xv.x * rstd * wv.x, xv.y * rstd * wv.y);
    __half2 b = __floats2half2_rn(xv.z * rstd * wv.z, xv.w * rstd * wv.w);
    *(__half2*)(y + idx)     = a;
    *(__half2*)(y + idx + 2) = b;
}

// W[K x N] fp32 -> Wt[N x K] plain fp16
__global__ void wcvt_t_k(const float* __restrict__ W, __half* __restrict__ T, int Kd, int N) {
    __shared__ float ts[32][33];
    int k0 = blockIdx.y * 32, n0 = blockIdx.x * 32;
    int tx = threadIdx.x & 31, ty = threadIdx.x >> 5;
    #pragma unroll
    for (int i = 0; i < 32; i += 8)
        ts[ty + i][tx] = W[(long)(k0 + ty + i) * N + n0 + tx];
    __syncthreads();
    #pragma unroll
    for (int i = 0; i < 32; i += 8)
        T[(long)(n0 + ty + i) * Kd + k0 + tx] = __float2half(ts[tx][ty + i]);
}

// ---------------- fp16 HMMA GEMM ----------------
// C[M x N] = A[M x K] @ B^T + bias. A fp16 [M][K], B fp16 [N][K].
// EPI: 0 = fp32 out, 1 = fp32 out + residual, 2 = GELU -> fp16, 3 = plain fp16
#define GEMM_SMEM_BYTES (2 * 2 * 8192)   // 32KB

template<int EPI>
__global__ __launch_bounds__(256) void hgemm_k(
    const __half* __restrict__ A, const __half* __restrict__ B,
    const float* __restrict__ bias, const float* __restrict__ R,
    float* __restrict__ Cf, __half* __restrict__ Ch,
    int M, int N, int Kd)
{
    extern __shared__ char smem[];
    const uint32_t sbase = smem_u32(smem);
    const int tid = threadIdx.x;
    const int lane = tid & 31, wid = tid >> 5;
    const int wm = wid >> 2, wn = wid & 3;
    const int m0 = blockIdx.y * 128, n0 = blockIdx.x * 128;

    float acc[4][4][4] = {};
    const int nch = Kd >> 5;

    auto load_chunk = [&](int c) {
        const uint32_t stg = sbase + (c & 1) * 16384;
        const int k0 = c << 5;
        #pragma unroll
        for (int e = tid; e < 512; e += 256) {
            int row = e >> 2, grp = e & 3;
            uint32_t so = tile_off(row, grp);
            cpa16(stg +        so, A + (long)(m0 + row) * Kd + k0 + grp * 8);
            cpa16(stg + 8192 + so, B + (long)(n0 + row) * Kd + k0 + grp * 8);
        }
        cpa_commit();
    };

    load_chunk(0);

    const int arow = lane & 15;
    const int akh  = (lane >> 4) & 1;
    const int bn   = ((lane >> 4) & 1) * 8 + (lane & 7);
    const int bkh  = (lane >> 3) & 1;

    for (int c = 0; c < nch; ++c) {
        if (c + 1 < nch) { load_chunk(c + 1); cpa_wait1(); }
        else             { cpa_wait0(); }
        __syncthreads();

        const uint32_t sA = sbase + (c & 1) * 16384;
        const uint32_t sB = sA + 8192;

        #pragma unroll
        for (int ks = 0; ks < 2; ++ks) {
            uint32_t bh[4][2];
            #pragma unroll
            for (int nt2 = 0; nt2 < 2; ++nt2) {
                int row = wn * 32 + nt2 * 16 + bn;
                int grp = ks * 2 + bkh;
                uint32_t so = tile_off(row, grp);
                LDMX4(bh[nt2*2][0], bh[nt2*2][1], bh[nt2*2+1][0], bh[nt2*2+1][1], sB + so);
            }
            #pragma unroll
            for (int mt = 0; mt < 4; ++mt) {
                int row = wm * 64 + mt * 16 + arow;
                int grp = ks * 2 + akh;
                uint32_t so = tile_off(row, grp);
                uint32_t ah[4];
                LDMX4(ah[0], ah[1], ah[2], ah[3], sA + so);
                #pragma unroll
                for (int nt = 0; nt < 4; ++nt)
                    mma_f16(acc[mt][nt], ah, bh[nt]);
            }
        }
        __syncthreads();
    }

    #pragma unroll
    for (int mt = 0; mt < 4; ++mt) {
        #pragma unroll
        for (int nt = 0; nt < 4; ++nt) {
            int r0 = m0 + wm * 64 + mt * 16 + (lane >> 2);
            int c0 = n0 + wn * 32 + nt * 8 + (lane & 3) * 2;
            float b0 = bias[c0], b1 = bias[c0 + 1];
            #pragma unroll
            for (int half = 0; half < 2; ++half) {
                int row = r0 + half * 8;
                long gi = (long)row * N + c0;
                float v0 = acc[mt][nt][half * 2 + 0] + b0;
                float v1 = acc[mt][nt][half * 2 + 1] + b1;
                if (EPI == 1) {
                    float2 rv = *(const float2*)(R + gi);
                    v0 += rv.x; v1 += rv.y;
                }
                if (EPI == 2) {
                    v0 = 0.5f * v0 * (1.0f + erff(v0 * 0.7071067811865476f));
                    v1 = 0.5f * v1 * (1.0f + erff(v1 * 0.7071067811865476f));
                }
                if (EPI >= 2) {
                    __half2 ph = __floats2half2_rn(v0, v1);
                    *(__half2*)(Ch + gi) = ph;
                } else {
                    float2 o = {v0, v1};
                    *(float2*)(Cf + gi) = o;
                }
            }
        }
    }
}

// ---------------- HMMA flash attention (plain fp16) ----------------
// grid (KQ/64, NHEAD, BATCH), 128 threads (4 warps x 16 q-rows).
// 64-key tiles, 3-stage cp.async. smem: Q 8KB + 3 x 16KB = 56KB.
#define ATT_SMEM (8192 + 3 * 16384)

__global__ __launch_bounds__(128) void flash_attn_mma(
    const __half* __restrict__ Q, const __half* __restrict__ K,
    const __half* __restrict__ V, __half* __restrict__ C)
{
    extern __shared__ char smem[];
    const uint32_t sb = smem_u32(smem);
    const int tid = threadIdx.x, lane = tid & 31, warp = tid >> 5;
    const int q0 = blockIdx.x * 64, h = blockIdx.y, b = blockIdx.z;
    const int wq0 = warp * 16;
    const float scale = 0.125f;   // 1/sqrt(64)

    const uint32_t sQ = sb;

    {
        const long gq = (long)(b * KQ + q0) * DMODEL + h * HD;
        for (int e = tid; e < 512; e += 128) {
            int row = e >> 3, grp = e & 7;
            cpa16(sQ + aoff(row, grp), Q + gq + (long)row * DMODEL + grp * 8);
        }
    }
    #define LOAD_KV(it_) do { \
        const uint32_t st_ = sb + 8192 + ((it_) % 3) * 16384; \
        const long gk_ = (long)(b * NKV + (it_) * 64) * DMODEL + h * HD; \
        for (int e = tid; e < 512; e += 128) { \
            int row = e >> 3, grp = e & 7; \
            long g = gk_ + (long)row * DMODEL + grp * 8; \
            uint32_t so = aoff(row, grp); \
            cpa16(st_ +        so, K + g); \
            cpa16(st_ + 8192 + so, V + g); \
        } \
        cpa_commit(); \
    } while (0)

    LOAD_KV(0);
    LOAD_KV(1);

    uint32_t qf[4][4];
    float ctx[8][4] = {};
    float m0 = -INFINITY, m1 = -INFINITY, l0 = 0.f, l1 = 0.f;

    const int NIT = NKV / 64;
    for (int it = 0; it < NIT; ++it) {
        if (it + 1 < NIT) cpa_wait1(); else cpa_wait0();
        __syncthreads();
        if (it == 0) {
            int row = wq0 + (lane & 15);
            #pragma unroll
            for (int ks = 0; ks < 4; ++ks) {
                int grp = ks * 2 + ((lane >> 4) & 1);
                uint32_t so = aoff(row, grp);
                LDMX4(qf[ks][0], qf[ks][1], qf[ks][2], qf[ks][3], sQ + so);
            }
        }
        if (it + 2 < NIT) LOAD_KV(it + 2);

        const uint32_t st  = sb + 8192 + (it % 3) * 16384;
        const uint32_t sk = st, sv = st + 8192;

        // ---- S = Q K^T ----
        float S[8][4] = {};
        #pragma unroll
        for (int ks = 0; ks < 4; ++ks) {
            uint32_t bh[8][2];
            #pragma unroll
            for (int kp = 0; kp < 4; ++kp) {
                int row = kp * 16 + ((lane >> 4) & 1) * 8 + (lane & 7);
                int grp = ks * 2 + ((lane >> 3) & 1);
                uint32_t so = aoff(row, grp);
                LDMX4(bh[2*kp][0], bh[2*kp][1], bh[2*kp+1][0], bh[2*kp+1][1], sk + so);
            }
            #pragma unroll
            for (int nt = 0; nt < 8; ++nt)
                mma_f16(S[nt], qf[ks], bh[nt]);
        }

        // ---- online softmax ----
        float mx0 = -INFINITY, mx1 = -INFINITY;
        #pragma unroll
        for (int nt = 0; nt < 8; ++nt) {
            mx0 = fmaxf(mx0, fmaxf(S[nt][0], S[nt][1]));
            mx1 = fmaxf(mx1, fmaxf(S[nt][2], S[nt][3]));
        }
        mx0 = fmaxf(mx0, __shfl_xor_sync(0xffffffffu, mx0, 1));
        mx0 = fmaxf(mx0, __shfl_xor_sync(0xffffffffu, mx0, 2));
        mx1 = fmaxf(mx1, __shfl_xor_sync(0xffffffffu, mx1, 1));
        mx1 = fmaxf(mx1, __shfl_xor_sync(0xffffffffu, mx1, 2));
        float m0n = fmaxf(m0, mx0), m1n = fmaxf(m1, mx1);
        float cr0 = __expf((m0 - m0n) * scale), cr1 = __expf((m1 - m1n) * scale);
        float s0 = 0.f, s1 = 0.f;
        #pragma unroll
        for (int nt = 0; nt < 8; ++nt) {
            S[nt][0] = __expf((S[nt][0] - m0n) * scale);
            S[nt][1] = __expf((S[nt][1] - m0n) * scale);
            S[nt][2] = __expf((S[nt][2] - m1n) * scale);
            S[nt][3] = __expf((S[nt][3] - m1n) * scale);
            s0 += S[nt][0] + S[nt][1];
            s1 += S[nt][2] + S[nt][3];
        }
        s0 += __shfl_xor_sync(0xffffffffu, s0, 1);
        s0 += __shfl_xor_sync(0xffffffffu, s0, 2);
        s1 += __shfl_xor_sync(0xffffffffu, s1, 1);
        s1 += __shfl_xor_sync(0xffffffffu, s1, 2);
        l0 = l0 * cr0 + s0;  l1 = l1 * cr1 + s1;
        m0 = m0n;  m1 = m1n;
        #pragma unroll
        for (int dt = 0; dt < 8; ++dt) {
            ctx[dt][0] *= cr0; ctx[dt][1] *= cr0;
            ctx[dt][2] *= cr1; ctx[dt][3] *= cr1;
        }

        // ---- P fragments (fp16, register-local) ----
        uint32_t pa[4][4];
        #pragma unroll
        for (int j = 0; j < 4; ++j) {
            __half2 t;
            t = __floats2half2_rn(S[2*j][0],   S[2*j][1]);   pa[j][0] = *(uint32_t*)&t;
            t = __floats2half2_rn(S[2*j][2],   S[2*j][3]);   pa[j][1] = *(uint32_t*)&t;
            t = __floats2half2_rn(S[2*j+1][0], S[2*j+1][1]); pa[j][2] = *(uint32_t*)&t;
            t = __floats2half2_rn(S[2*j+1][2], S[2*j+1][3]); pa[j][3] = *(uint32_t*)&t;
        }

        // ---- O += P V ----
        #pragma unroll
        for (int ks = 0; ks < 4; ++ks) {
            uint32_t vb[8][2];
            #pragma unroll
            for (int dp = 0; dp < 4; ++dp) {
                int row = ks * 16 + ((lane >> 3) & 1) * 8 + (lane & 7);
                int grp = dp * 2 + ((lane >> 4) & 1);
                uint32_t so = aoff(row, grp);
                LDMX4T(vb[2*dp][0], vb[2*dp][1], vb[2*dp+1][0], vb[2*dp+1][1], sv + so);
            }
            #pragma unroll
            for (int dt = 0; dt < 8; ++dt)
                mma_f16(ctx[dt], pa[ks], vb[dt]);
        }
        __syncthreads();
    }

    // ---- epilogue ----
    float i0 = 1.f / l0, i1 = 1.f / l1;
    int r0 = q0 + wq0 + (lane >> 2);
    int r1 = r0 + 8;
    #pragma unroll
    for (int dt = 0; dt < 8; ++dt) {
        int col = h * HD + dt * 8 + (lane & 3) * 2;
        long g0 = (long)(b * KQ + r0) * DMODEL + col;
        long g1 = (long)(b * KQ + r1) * DMODEL + col;
        __half2 p0 = __floats2half2_rn(ctx[dt][0] * i0, ctx[dt][1] * i0);
        __half2 p1 = __floats2half2_rn(ctx[dt][2] * i1, ctx[dt][3] * i1);
        *(__half2*)(C + g0) = p0;
        *(__half2*)(C + g1) = p1;
    }
    #undef LOAD_KV
}

// ---------------- launch ----------------
extern "C" void kernel_launch(void* const* d_in, const int* in_sizes, int n_in,
                              void* d_out, int out_size) {
    const float* query_tokens   = (const float*)d_in[0];
    const float* point_features = (const float*)d_in[1];
    const float* ln_q_g  = (const float*)d_in[2];
    const float* ln_q_b  = (const float*)d_in[3];
    const float* ln_kv_g = (const float*)d_in[4];
    const float* ln_kv_b = (const float*)d_in[5];
    const float* Wq = (const float*)d_in[6];   const float* bq = (const float*)d_in[7];
    const float* Wk = (const float*)d_in[8];   const float* bk = (const float*)d_in[9];
    const float* Wv = (const float*)d_in[10];  const float* bv = (const float*)d_in[11];
    const float* rms_q_w = (const float*)d_in[12];
    const float* rms_k_w = (const float*)d_in[13];
    const float* Wo = (const float*)d_in[14];  const float* bo = (const float*)d_in[15];
    const float* ln_mlp_g = (const float*)d_in[16];
    const float* ln_mlp_b = (const float*)d_in[17];
    const float* W1 = (const float*)d_in[18];  const float* b1 = (const float*)d_in[19];
    const float* W2 = (const float*)d_in[20];  const float* b2 = (const float*)d_in[21];
    float* out = (float*)d_out;

    float *p_q, *p_k, *p_out;
    cudaGetSymbolAddress((void**)&p_q,   g_q);
    cudaGetSymbolAddress((void**)&p_k,   g_k);
    cudaGetSymbolAddress((void**)&p_out, g_out);

    __half *qln,*kvln,*ctx,*hln,*m1,*qh,*kh,*vh;
    __half *wq,*wk,*wv,*wo,*w1,*w2;
    cudaGetSymbolAddress((void**)&qln, g_qln);  cudaGetSymbolAddress((void**)&kvln, g_kvln);
    cudaGetSymbolAddress((void**)&ctx, g_ctx);  cudaGetSymbolAddress((void**)&hln, g_hln);
    cudaGetSymbolAddress((void**)&m1, g_m1);
    cudaGetSymbolAddress((void**)&qh, g_qh);    cudaGetSymbolAddress((void**)&kh, g_kh);
    cudaGetSymbolAddress((void**)&vh, g_vh);
    cudaGetSymbolAddress((void**)&wq, g_wq);    cudaGetSymbolAddress((void**)&wk, g_wk);
    cudaGetSymbolAddress((void**)&wv, g_wv);    cudaGetSymbolAddress((void**)&wo, g_wo);
    cudaGetSymbolAddress((void**)&w1, g_w1);    cudaGetSymbolAddress((void**)&w2, g_w2);

    cudaFuncSetAttribute(hgemm_k<0>, cudaFuncAttributeMaxDynamicSharedMemorySize, GEMM_SMEM_BYTES);
    cudaFuncSetAttribute(hgemm_k<1>, cudaFuncAttributeMaxDynamicSharedMemorySize, GEMM_SMEM_BYTES);
    cudaFuncSetAttribute(hgemm_k<2>, cudaFuncAttributeMaxDynamicSharedMemorySize, GEMM_SMEM_BYTES);
    cudaFuncSetAttribute(hgemm_k<3>, cudaFuncAttributeMaxDynamicSharedMemorySize, GEMM_SMEM_BYTES);
    cudaFuncSetAttribute(flash_attn_mma, cudaFuncAttributeMaxDynamicSharedMemorySize, ATT_SMEM);

    // weight transpose + fp16 convert
    wcvt_t_k<<<dim3(DMODEL/32, DMODEL/32), 256>>>(Wq, wq, DMODEL, DMODEL);
    wcvt_t_k<<<dim3(DMODEL/32, DMODEL/32), 256>>>(Wk, wk, DMODEL, DMODEL);
    wcvt_t_k<<<dim3(DMODEL/32, DMODEL/32), 256>>>(Wv, wv, DMODEL, DMODEL);
    wcvt_t_k<<<dim3(DMODEL/32, DMODEL/32), 256>>>(Wo, wo, DMODEL, DMODEL);
    wcvt_t_k<<<dim3(DFF/32,    DMODEL/32), 256>>>(W1, w1, DMODEL, DFF);
    wcvt_t_k<<<dim3(DMODEL/32, DFF/32),    256>>>(W2, w2, DFF, DMODEL);

    // pre-LN
    layernorm_h_k<<<MQ,  256>>>(query_tokens,   ln_q_g,  ln_q_b,  qln,  1e-5f);
    layernorm_h_k<<<MKV, 256>>>(point_features, ln_kv_g, ln_kv_b, kvln, 1e-5f);

    // projections
    hgemm_k<0><<<dim3(DMODEL/128, MQ/128),  256, GEMM_SMEM_BYTES>>>(
        qln, wq, bq, nullptr, p_q, nullptr, MQ, DMODEL, DMODEL);
    rmsnorm_h_k<<<MQ, 256>>>(p_q, rms_q_w, qh, 1e-6f);
    hgemm_k<0><<<dim3(DMODEL/128, MKV/128), 256, GEMM_SMEM_BYTES>>>(
        kvln, wk, bk, nullptr, p_k, nullptr, MKV, DMODEL, DMODEL);
    rmsnorm_h_k<<<MKV, 256>>>(p_k, rms_k_w, kh, 1e-6f);
    hgemm_k<3><<<dim3(DMODEL/128, MKV/128), 256, GEMM_SMEM_BYTES>>>(
        kvln, wv, bv, nullptr, nullptr, vh, MKV, DMODEL, DMODEL);

    // attention
    flash_attn_mma<<<dim3(KQ/64, NHEAD, BATCH), 128, ATT_SMEM>>>(qh, kh, vh, ctx);

    // output proj + residual
    hgemm_k<1><<<dim3(DMODEL/128, MQ/128), 256, GEMM_SMEM_BYTES>>>(
        ctx, wo, bo, query_tokens, p_out, nullptr, MQ, DMODEL, DMODEL);

    // MLP
    layernorm_h_k<<<MQ, 256>>>(p_out, ln_mlp_g, ln_mlp_b, hln, 1e-5f);
    hgemm_k<2><<<dim3(DFF/128, MQ/128), 256, GEMM_SMEM_BYTES>>>(
        hln, w1, b1, nullptr, nullptr, m1, MQ, DFF, DMODEL);
    hgemm_k<1><<<dim3(DMODEL/128, MQ/128), 256, GEMM_SMEM_BYTES>>>(
        m1, w2, b2, p_out, out, nullptr, MQ, DMODEL, DFF);
}

// round 8
// speedup vs baseline: 9.1830x; 1.0369x over previous
#include <cuda_runtime.h>
#include <cuda_fp16.h>
#include <math.h>
#include <stdint.h>

// ---------------- problem constants ----------------
#define BATCH 4
#define KQ    512
#define NKV   4096
#define DMODEL 1024
#define NHEAD 16
#define HD    64
#define MQ    (BATCH*KQ)    // 2048
#define MKV   (BATCH*NKV)   // 16384
#define DFF   (4*DMODEL)    // 4096
#define KVLD  2048          // fused k|v row stride

// ---------------- scratch (device globals, no allocs) ----------------
__device__ float g_out [MQ  * DMODEL];
__device__ float g_bkv [KVLD];

__device__ __half g_qln [MQ  * DMODEL];
__device__ __half g_kvln[MKV * DMODEL];
__device__ __half g_qp  [MQ  * DMODEL];      // q proj (pre/post rmsnorm, in-place)
__device__ __half g_kv  [MKV * KVLD];        // fused [k | v]
__device__ __half g_ctx [MQ  * DMODEL];
__device__ __half g_hln [MQ  * DMODEL];
__device__ __half g_m1  [MQ  * DFF];

__device__ __half g_wq [DMODEL*DMODEL];
__device__ __half g_wkv[KVLD*DMODEL];        // rows 0..1023 = Wk^T, 1024..2047 = Wv^T
__device__ __half g_wo [DMODEL*DMODEL];
__device__ __half g_w1 [DMODEL*DFF];
__device__ __half g_w2 [DFF*DMODEL];

// ---------------- low-level helpers ----------------
__device__ __forceinline__ uint32_t smem_u32(const void* p) {
    uint32_t a;
    asm("{ .reg .u64 t; cvta.to.shared.u64 t, %1; cvt.u32.u64 %0, t; }" : "=r"(a) : "l"(p));
    return a;
}
__device__ __forceinline__ void cpa16(uint32_t saddr, const void* g) {
    asm volatile("cp.async.cg.shared.global [%0], [%1], 16;" :: "r"(saddr), "l"(g));
}
__device__ __forceinline__ void cpa_commit() { asm volatile("cp.async.commit_group;"); }
__device__ __forceinline__ void cpa_wait1()  { asm volatile("cp.async.wait_group 1;"); }
__device__ __forceinline__ void cpa_wait0()  { asm volatile("cp.async.wait_group 0;"); }

#define LDMX4(r0, r1, r2, r3, addr) \
    asm volatile("ldmatrix.sync.aligned.m8n8.x4.shared.b16 {%0,%1,%2,%3}, [%4];" \
        : "=r"(r0), "=r"(r1), "=r"(r2), "=r"(r3) : "r"(addr))

#define LDMX4T(r0, r1, r2, r3, addr) \
    asm volatile("ldmatrix.sync.aligned.m8n8.x4.trans.shared.b16 {%0,%1,%2,%3}, [%4];" \
        : "=r"(r0), "=r"(r1), "=r"(r2), "=r"(r3) : "r"(addr))

__device__ __forceinline__ void mma_f16(float* d, const uint32_t* a, const uint32_t* b) {
    asm volatile(
        "mma.sync.aligned.m16n8k16.row.col.f32.f16.f16.f32 "
        "{%0,%1,%2,%3}, {%4,%5,%6,%7}, {%8,%9}, {%0,%1,%2,%3};"
        : "+f"(d[0]), "+f"(d[1]), "+f"(d[2]), "+f"(d[3])
        : "r"(a[0]), "r"(a[1]), "r"(a[2]), "r"(a[3]), "r"(b[0]), "r"(b[1]));
}

__device__ __forceinline__ uint32_t tile_off(int row, int grp) {
    return (uint32_t)(row * 64 + ((grp ^ ((row >> 1) & 3)) << 4));
}
__device__ __forceinline__ uint32_t aoff(int row, int grp) {
    return (uint32_t)(row * 128 + ((grp ^ (row & 7)) << 4));
}

// ---------------- norm kernels ----------------
__device__ __forceinline__ void block_reduce2(float& s1, float& s2) {
    #pragma unroll
    for (int off = 16; off; off >>= 1) {
        s1 += __shfl_xor_sync(0xffffffffu, s1, off);
        s2 += __shfl_xor_sync(0xffffffffu, s2, off);
    }
    __shared__ float a[8], b[8];
    int w = threadIdx.x >> 5, lane = threadIdx.x & 31;
    if (lane == 0) { a[w] = s1; b[w] = s2; }
    __syncthreads();
    s1 = 0.f; s2 = 0.f;
    #pragma unroll
    for (int i = 0; i < 8; i++) { s1 += a[i]; s2 += b[i]; }
}

__global__ void layernorm_h_k(const float* __restrict__ x, const float* __restrict__ g,
                              const float* __restrict__ b, __half* __restrict__ y, float eps) {
    long row = blockIdx.x;
    float4 xv = ((const float4*)(x + row * DMODEL))[threadIdx.x];
    float s  = xv.x + xv.y + xv.z + xv.w;
    float sq = xv.x*xv.x + xv.y*xv.y + xv.z*xv.z + xv.w*xv.w;
    block_reduce2(s, sq);
    float mu  = s * (1.0f / DMODEL);
    float var = sq * (1.0f / DMODEL) - mu * mu;
    float rstd = rsqrtf(var + eps);
    float4 gv = ((const float4*)g)[threadIdx.x];
    float4 bv = ((const float4*)b)[threadIdx.x];
    long idx = row * DMODEL + threadIdx.x * 4;
    __half2 a = __floats2half2_rn((xv.x - mu) * rstd * gv.x + bv.x,
                                  (xv.y - mu) * rstd * gv.y + bv.y);
    __half2 c = __floats2half2_rn((xv.z - mu) * rstd * gv.z + bv.z,
                                  (xv.w - mu) * rstd * gv.w + bv.w);
    *(__half2*)(y + idx)     = a;
    *(__half2*)(y + idx + 2) = c;
}

// in-place rmsnorm on fp16 rows of length DMODEL, arbitrary row stride
__global__ void rmsnorm_hh_k(__half* __restrict__ x, const float* __restrict__ w, int ld,
                             float eps) {
    long row = blockIdx.x;
    __half* xr = x + row * (long)ld;
    // 256 threads x 4 halfs
    __half2 h01 = *(__half2*)(xr + threadIdx.x * 4);
    __half2 h23 = *(__half2*)(xr + threadIdx.x * 4 + 2);
    float v0 = __half2float(__low2half(h01)), v1 = __half2float(__high2half(h01));
    float v2 = __half2float(__low2half(h23)), v3 = __half2float(__high2half(h23));
    float sq = v0*v0 + v1*v1 + v2*v2 + v3*v3;
    float dummy = 0.f;
    block_reduce2(sq, dummy);
    float rstd = rsqrtf(sq * (1.0f / DMODEL) + eps);
    float4 wv = ((const float4*)w)[threadIdx.x];
    __half2 a = __floats2half2_rn(v0 * rstd * wv.x, v1 * rstd * wv.y);
    __half2 b = __floats2half2_rn(v2 * rstd * wv.z, v3 * rstd * wv.w);
    *(__half2*)(xr + threadIdx.x * 4)     = a;
    *(__half2*)(xr + threadIdx.x * 4 + 2) = b;
}

// all-weights transpose+fp16 convert. 12288 blocks of 256 threads.
__global__ void wcvt_all_k(const float* __restrict__ Wq, const float* __restrict__ Wk,
                           const float* __restrict__ Wv, const float* __restrict__ Wo,
                           const float* __restrict__ W1, const float* __restrict__ W2,
                           __half* __restrict__ wq, __half* __restrict__ wkv,
                           __half* __restrict__ wo, __half* __restrict__ w1,
                           __half* __restrict__ w2) {
    __shared__ float ts[32][33];
    int bid = blockIdx.x;
    const float* src; __half* dst; int Kd, N;
    if      (bid <  1024) { src = Wq; dst = wq;                     Kd = 1024; N = 1024; }
    else if (bid <  2048) { src = Wk; dst = wkv;                    Kd = 1024; N = 1024; bid -= 1024; }
    else if (bid <  3072) { src = Wv; dst = wkv + 1024 * 1024;      Kd = 1024; N = 1024; bid -= 2048; }
    else if (bid <  4096) { src = Wo; dst = wo;                     Kd = 1024; N = 1024; bid -= 3072; }
    else if (bid <  8192) { src = W1; dst = w1;                     Kd = 1024; N = 4096; bid -= 4096; }
    else                  { src = W2; dst = w2;                     Kd = 4096; N = 1024; bid -= 8192; }
    int ntn = N >> 5;
    int n0 = (bid % ntn) << 5, k0 = (bid / ntn) << 5;
    int tx = threadIdx.x & 31, ty = threadIdx.x >> 5;
    #pragma unroll
    for (int i = 0; i < 32; i += 8)
        ts[ty + i][tx] = src[(long)(k0 + ty + i) * N + n0 + tx];
    __syncthreads();
    #pragma unroll
    for (int i = 0; i < 32; i += 8)
        dst[(long)(n0 + ty + i) * Kd + k0 + tx] = __float2half(ts[tx][ty + i]);
}

// ---------------- fp16 HMMA GEMM ----------------
// EPI: 1 = fp32 out + residual, 2 = GELU -> fp16, 3 = plain fp16
#define GEMM_SMEM_BYTES (2 * 2 * 8192)   // 32KB

template<int EPI>
__global__ __launch_bounds__(256) void hgemm_k(
    const __half* __restrict__ A, const __half* __restrict__ B,
    const float* __restrict__ bias, const float* __restrict__ R,
    float* __restrict__ Cf, __half* __restrict__ Ch,
    int M, int N, int Kd)
{
    extern __shared__ char smem[];
    const uint32_t sbase = smem_u32(smem);
    const int tid = threadIdx.x;
    const int lane = tid & 31, wid = tid >> 5;
    const int wm = wid >> 2, wn = wid & 3;
    const int m0 = blockIdx.y * 128, n0 = blockIdx.x * 128;

    float acc[4][4][4] = {};
    const int nch = Kd >> 5;

    auto load_chunk = [&](int c) {
        const uint32_t stg = sbase + (c & 1) * 16384;
        const int k0 = c << 5;
        #pragma unroll
        for (int e = tid; e < 512; e += 256) {
            int row = e >> 2, grp = e & 3;
            uint32_t so = tile_off(row, grp);
            cpa16(stg +        so, A + (long)(m0 + row) * Kd + k0 + grp * 8);
            cpa16(stg + 8192 + so, B + (long)(n0 + row) * Kd + k0 + grp * 8);
        }
        cpa_commit();
    };

    load_chunk(0);

    const int arow = lane & 15;
    const int akh  = (lane >> 4) & 1;
    const int bn   = ((lane >> 4) & 1) * 8 + (lane & 7);
    const int bkh  = (lane >> 3) & 1;

    for (int c = 0; c < nch; ++c) {
        if (c + 1 < nch) { load_chunk(c + 1); cpa_wait1(); }
        else             { cpa_wait0(); }
        __syncthreads();

        const uint32_t sA = sbase + (c & 1) * 16384;
        const uint32_t sB = sA + 8192;

        #pragma unroll
        for (int ks = 0; ks < 2; ++ks) {
            uint32_t bh[4][2];
            #pragma unroll
            for (int nt2 = 0; nt2 < 2; ++nt2) {
                int row = wn * 32 + nt2 * 16 + bn;
                int grp = ks * 2 + bkh;
                uint32_t so = tile_off(row, grp);
                LDMX4(bh[nt2*2][0], bh[nt2*2][1], bh[nt2*2+1][0], bh[nt2*2+1][1], sB + so);
            }
            #pragma unroll
            for (int mt = 0; mt < 4; ++mt) {
                int row = wm * 64 + mt * 16 + arow;
                int grp = ks * 2 + akh;
                uint32_t so = tile_off(row, grp);
                uint32_t ah[4];
                LDMX4(ah[0], ah[1], ah[2], ah[3], sA + so);
                #pragma unroll
                for (int nt = 0; nt < 4; ++nt)
                    mma_f16(acc[mt][nt], ah, bh[nt]);
            }
        }
        __syncthreads();
    }

    #pragma unroll
    for (int mt = 0; mt < 4; ++mt) {
        #pragma unroll
        for (int nt = 0; nt < 4; ++nt) {
            int r0 = m0 + wm * 64 + mt * 16 + (lane >> 2);
            int c0 = n0 + wn * 32 + nt * 8 + (lane & 3) * 2;
            float b0 = bias[c0], b1 = bias[c0 + 1];
            #pragma unroll
            for (int half = 0; half < 2; ++half) {
                int row = r0 + half * 8;
                long gi = (long)row * N + c0;
                float v0 = acc[mt][nt][half * 2 + 0] + b0;
                float v1 = acc[mt][nt][half * 2 + 1] + b1;
                if (EPI == 1) {
                    float2 rv = *(const float2*)(R + gi);
                    v0 += rv.x; v1 += rv.y;
                }
                if (EPI == 2) {
                    v0 = 0.5f * v0 * (1.0f + erff(v0 * 0.7071067811865476f));
                    v1 = 0.5f * v1 * (1.0f + erff(v1 * 0.7071067811865476f));
                }
                if (EPI >= 2) {
                    __half2 ph = __floats2half2_rn(v0, v1);
                    *(__half2*)(Ch + gi) = ph;
                } else {
                    float2 o = {v0, v1};
                    *(float2*)(Cf + gi) = o;
                }
            }
        }
    }
}

// ---------------- HMMA flash attention (plain fp16, strided K/V) ----------------
// grid (KQ/64, NHEAD, BATCH), 128 threads. K/V rows have stride KVLD.
#define ATT_SMEM (8192 + 3 * 16384)

__global__ __launch_bounds__(128) void flash_attn_mma(
    const __half* __restrict__ Q, const __half* __restrict__ K,
    const __half* __restrict__ V, __half* __restrict__ C)
{
    extern __shared__ char smem[];
    const uint32_t sb = smem_u32(smem);
    const int tid = threadIdx.x, lane = tid & 31, warp = tid >> 5;
    const int q0 = blockIdx.x * 64, h = blockIdx.y, b = blockIdx.z;
    const int wq0 = warp * 16;
    const float scale = 0.125f;   // 1/sqrt(64)

    const uint32_t sQ = sb;

    {
        const long gq = (long)(b * KQ + q0) * DMODEL + h * HD;
        for (int e = tid; e < 512; e += 128) {
            int row = e >> 3, grp = e & 7;
            cpa16(sQ + aoff(row, grp), Q + gq + (long)row * DMODEL + grp * 8);
        }
    }
    #define LOAD_KV(it_) do { \
        const uint32_t st_ = sb + 8192 + ((it_) % 3) * 16384; \
        const long gk_ = (long)(b * NKV + (it_) * 64) * KVLD + h * HD; \
        for (int e = tid; e < 512; e += 128) { \
            int row = e >> 3, grp = e & 7; \
            long g = gk_ + (long)row * KVLD + grp * 8; \
            uint32_t so = aoff(row, grp); \
            cpa16(st_ +        so, K + g); \
            cpa16(st_ + 8192 + so, V + g); \
        } \
        cpa_commit(); \
    } while (0)

    LOAD_KV(0);
    LOAD_KV(1);

    uint32_t qf[4][4];
    float ctx[8][4] = {};
    float m0 = -INFINITY, m1 = -INFINITY, l0 = 0.f, l1 = 0.f;

    const int NIT = NKV / 64;
    for (int it = 0; it < NIT; ++it) {
        if (it + 1 < NIT) cpa_wait1(); else cpa_wait0();
        __syncthreads();
        if (it == 0) {
            int row = wq0 + (lane & 15);
            #pragma unroll
            for (int ks = 0; ks < 4; ++ks) {
                int grp = ks * 2 + ((lane >> 4) & 1);
                uint32_t so = aoff(row, grp);
                LDMX4(qf[ks][0], qf[ks][1], qf[ks][2], qf[ks][3], sQ + so);
            }
        }
        if (it + 2 < NIT) LOAD_KV(it + 2);

        const uint32_t st  = sb + 8192 + (it % 3) * 16384;
        const uint32_t sk = st, sv = st + 8192;

        // ---- S = Q K^T ----
        float S[8][4] = {};
        #pragma unroll
        for (int ks = 0; ks < 4; ++ks) {
            uint32_t bh[8][2];
            #pragma unroll
            for (int kp = 0; kp < 4; ++kp) {
                int row = kp * 16 + ((lane >> 4) & 1) * 8 + (lane & 7);
                int grp = ks * 2 + ((lane >> 3) & 1);
                uint32_t so = aoff(row, grp);
                LDMX4(bh[2*kp][0], bh[2*kp][1], bh[2*kp+1][0], bh[2*kp+1][1], sk + so);
            }
            #pragma unroll
            for (int nt = 0; nt < 8; ++nt)
                mma_f16(S[nt], qf[ks], bh[nt]);
        }

        // ---- online softmax ----
        float mx0 = -INFINITY, mx1 = -INFINITY;
        #pragma unroll
        for (int nt = 0; nt < 8; ++nt) {
            mx0 = fmaxf(mx0, fmaxf(S[nt][0], S[nt][1]));
            mx1 = fmaxf(mx1, fmaxf(S[nt][2], S[nt][3]));
        }
        mx0 = fmaxf(mx0, __shfl_xor_sync(0xffffffffu, mx0, 1));
        mx0 = fmaxf(mx0, __shfl_xor_sync(0xffffffffu, mx0, 2));
        mx1 = fmaxf(mx1, __shfl_xor_sync(0xffffffffu, mx1, 1));
        mx1 = fmaxf(mx1, __shfl_xor_sync(0xffffffffu, mx1, 2));
        float m0n = fmaxf(m0, mx0), m1n = fmaxf(m1, mx1);
        float cr0 = __expf((m0 - m0n) * scale), cr1 = __expf((m1 - m1n) * scale);
        float s0 = 0.f, s1 = 0.f;
        #pragma unroll
        for (int nt = 0; nt < 8; ++nt) {
            S[nt][0] = __expf((S[nt][0] - m0n) * scale);
            S[nt][1] = __expf((S[nt][1] - m0n) * scale);
            S[nt][2] = __expf((S[nt][2] - m1n) * scale);
            S[nt][3] = __expf((S[nt][3] - m1n) * scale);
            s0 += S[nt][0] + S[nt][1];
            s1 += S[nt][2] + S[nt][3];
        }
        s0 += __shfl_xor_sync(0xffffffffu, s0, 1);
        s0 += __shfl_xor_sync(0xffffffffu, s0, 2);
        s1 += __shfl_xor_sync(0xffffffffu, s1, 1);
        s1 += __shfl_xor_sync(0xffffffffu, s1, 2);
        l0 = l0 * cr0 + s0;  l1 = l1 * cr1 + s1;
        m0 = m0n;  m1 = m1n;
        #pragma unroll
        for (int dt = 0; dt < 8; ++dt) {
            ctx[dt][0] *= cr0; ctx[dt][1] *= cr0;
            ctx[dt][2] *= cr1; ctx[dt][3] *= cr1;
        }

        // ---- P fragments ----
        uint32_t pa[4][4];
        #pragma unroll
        for (int j = 0; j < 4; ++j) {
            __half2 t;
            t = __floats2half2_rn(S[2*j][0],   S[2*j][1]);   pa[j][0] = *(uint32_t*)&t;
            t = __floats2half2_rn(S[2*j][2],   S[2*j][3]);   pa[j][1] = *(uint32_t*)&t;
            t = __floats2half2_rn(S[2*j+1][0], S[2*j+1][1]); pa[j][2] = *(uint32_t*)&t;
            t = __floats2half2_rn(S[2*j+1][2], S[2*j+1][3]); pa[j][3] = *(uint32_t*)&t;
        }

        // ---- O += P V ----
        #pragma unroll
        for (int ks = 0; ks < 4; ++ks) {
            uint32_t vb[8][2];
            #pragma unroll
            for (int dp = 0; dp < 4; ++dp) {
                int row = ks * 16 + ((lane >> 3) & 1) * 8 + (lane & 7);
                int grp = dp * 2 + ((lane >> 4) & 1);
                uint32_t so = aoff(row, grp);
                LDMX4T(vb[2*dp][0], vb[2*dp][1], vb[2*dp+1][0], vb[2*dp+1][1], sv + so);
            }
            #pragma unroll
            for (int dt = 0; dt < 8; ++dt)
                mma_f16(ctx[dt], pa[ks], vb[dt]);
        }
        __syncthreads();
    }

    // ---- epilogue ----
    float i0 = 1.f / l0, i1 = 1.f / l1;
    int r0 = q0 + wq0 + (lane >> 2);
    int r1 = r0 + 8;
    #pragma unroll
    for (int dt = 0; dt < 8; ++dt) {
        int col = h * HD + dt * 8 + (lane & 3) * 2;
        long g0 = (long)(b * KQ + r0) * DMODEL + col;
        long g1 = (long)(b * KQ + r1) * DMODEL + col;
        __half2 p0 = __floats2half2_rn(ctx[dt][0] * i0, ctx[dt][1] * i0);
        __half2 p1 = __floats2half2_rn(ctx[dt][2] * i1, ctx[dt][3] * i1);
        *(__half2*)(C + g0) = p0;
        *(__half2*)(C + g1) = p1;
    }
    #undef LOAD_KV
}

// ---------------- launch ----------------
extern "C" void kernel_launch(void* const* d_in, const int* in_sizes, int n_in,
                              void* d_out, int out_size) {
    const float* query_tokens   = (const float*)d_in[0];
    const float* point_features = (const float*)d_in[1];
    const float* ln_q_g  = (const float*)d_in[2];
    const float* ln_q_b  = (const float*)d_in[3];
    const float* ln_kv_g = (const float*)d_in[4];
    const float* ln_kv_b = (const float*)d_in[5];
    const float* Wq = (const float*)d_in[6];   const float* bq = (const float*)d_in[7];
    const float* Wk = (const float*)d_in[8];   const float* bk = (const float*)d_in[9];
    const float* Wv = (const float*)d_in[10];  const float* bv = (const float*)d_in[11];
    const float* rms_q_w = (const float*)d_in[12];
    const float* rms_k_w = (const float*)d_in[13];
    const float* Wo = (const float*)d_in[14];  const float* bo = (const float*)d_in[15];
    const float* ln_mlp_g = (const float*)d_in[16];
    const float* ln_mlp_b = (const float*)d_in[17];
    const float* W1 = (const float*)d_in[18];  const float* b1 = (const float*)d_in[19];
    const float* W2 = (const float*)d_in[20];  const float* b2 = (const float*)d_in[21];
    float* out = (float*)d_out;

    float *p_out, *p_bkv;
    cudaGetSymbolAddress((void**)&p_out, g_out);
    cudaGetSymbolAddress((void**)&p_bkv, g_bkv);

    __half *qln,*kvln,*ctx,*hln,*m1,*qp,*kv;
    __half *wq,*wkv,*wo,*w1,*w2;
    cudaGetSymbolAddress((void**)&qln, g_qln);  cudaGetSymbolAddress((void**)&kvln, g_kvln);
    cudaGetSymbolAddress((void**)&ctx, g_ctx);  cudaGetSymbolAddress((void**)&hln, g_hln);
    cudaGetSymbolAddress((void**)&m1, g_m1);
    cudaGetSymbolAddress((void**)&qp, g_qp);    cudaGetSymbolAddress((void**)&kv, g_kv);
    cudaGetSymbolAddress((void**)&wq, g_wq);    cudaGetSymbolAddress((void**)&wkv, g_wkv);
    cudaGetSymbolAddress((void**)&wo, g_wo);
    cudaGetSymbolAddress((void**)&w1, g_w1);    cudaGetSymbolAddress((void**)&w2, g_w2);

    cudaFuncSetAttribute(hgemm_k<1>, cudaFuncAttributeMaxDynamicSharedMemorySize, GEMM_SMEM_BYTES);
    cudaFuncSetAttribute(hgemm_k<2>, cudaFuncAttributeMaxDynamicSharedMemorySize, GEMM_SMEM_BYTES);
    cudaFuncSetAttribute(hgemm_k<3>, cudaFuncAttributeMaxDynamicSharedMemorySize, GEMM_SMEM_BYTES);
    cudaFuncSetAttribute(flash_attn_mma, cudaFuncAttributeMaxDynamicSharedMemorySize, ATT_SMEM);

    // bias concat for fused KV GEMM (device-to-device async copies are graph-legal)
    cudaMemcpyAsync(p_bkv,        bk, DMODEL * sizeof(float), cudaMemcpyDeviceToDevice);
    cudaMemcpyAsync(p_bkv + 1024, bv, DMODEL * sizeof(float), cudaMemcpyDeviceToDevice);

    // all weights: transpose + fp16 convert (single launch)
    wcvt_all_k<<<12288, 256>>>(Wq, Wk, Wv, Wo, W1, W2, wq, wkv, wo, w1, w2);

    // pre-LN
    layernorm_h_k<<<MQ,  256>>>(query_tokens,   ln_q_g,  ln_q_b,  qln,  1e-5f);
    layernorm_h_k<<<MKV, 256>>>(point_features, ln_kv_g, ln_kv_b, kvln, 1e-5f);

    // Q projection (fp16 out) + in-place rmsnorm
    hgemm_k<3><<<dim3(DMODEL/128, MQ/128), 256, GEMM_SMEM_BYTES>>>(
        qln, wq, bq, nullptr, nullptr, qp, MQ, DMODEL, DMODEL);
    rmsnorm_hh_k<<<MQ, 256>>>(qp, rms_q_w, DMODEL, 1e-6f);

    // fused K|V projection (N=2048), then in-place rmsnorm on k half
    hgemm_k<3><<<dim3(KVLD/128, MKV/128), 256, GEMM_SMEM_BYTES>>>(
        kvln, wkv, p_bkv, nullptr, nullptr, kv, MKV, KVLD, DMODEL);
    rmsnorm_hh_k<<<MKV, 256>>>(kv, rms_k_w, KVLD, 1e-6f);

    // attention (K stride KVLD, V = kv + 1024)
    flash_attn_mma<<<dim3(KQ/64, NHEAD, BATCH), 128, ATT_SMEM>>>(qp, kv, kv + 1024, ctx);

    // output proj + residual
    hgemm_k<1><<<dim3(DMODEL/128, MQ/128), 256, GEMM_SMEM_BYTES>>>(
        ctx, wo, bo, query_tokens, p_out, nullptr, MQ, DMODEL, DMODEL);

    // MLP
    layernorm_h_k<<<MQ, 256>>>(p_out, ln_mlp_g, ln_mlp_b, hln, 1e-5f);
    hgemm_k<2><<<dim3(DFF/128, MQ/128), 256, GEMM_SMEM_BYTES>>>(
        hln, w1, b1, nullptr, nullptr, m1, MQ, DFF, DMODEL);
    hgemm_k<1><<<dim3(DMODEL/128, MQ/128), 256, GEMM_SMEM_BYTES>>>(
        m1, w2, b2, p_out, out, nullptr, MQ, DMODEL, DFF);
}

// round 9
// speedup vs baseline: 9.9796x; 1.0867x over previous
#include <cuda_runtime.h>
#include <cuda_fp16.h>
#include <math.h>
#include <stdint.h>

// ---------------- problem constants ----------------
#define BATCH 4
#define KQ    512
#define NKV   4096
#define DMODEL 1024
#define NHEAD 16
#define HD    64
#define MQ    (BATCH*KQ)    // 2048
#define MKV   (BATCH*NKV)   // 16384
#define DFF   (4*DMODEL)    // 4096
#define KVLD  2048          // fused k|v row stride

// ---------------- scratch (device globals, no allocs) ----------------
__device__ float g_out [MQ  * DMODEL];
__device__ float g_bkv [KVLD];

__device__ __half g_qln [MQ  * DMODEL];
__device__ __half g_kvln[MKV * DMODEL];
__device__ __half g_qp  [MQ  * DMODEL];
__device__ __half g_kv  [MKV * KVLD];        // fused [k | v]
__device__ __half g_ctx [MQ  * DMODEL];
__device__ __half g_hln [MQ  * DMODEL];
__device__ __half g_m1  [MQ  * DFF];

__device__ __half g_wq [DMODEL*DMODEL];
__device__ __half g_wkv[KVLD*DMODEL];
__device__ __half g_wo [DMODEL*DMODEL];
__device__ __half g_w1 [DMODEL*DFF];
__device__ __half g_w2 [DFF*DMODEL];

// ---------------- low-level helpers ----------------
__device__ __forceinline__ uint32_t smem_u32(const void* p) {
    uint32_t a;
    asm("{ .reg .u64 t; cvta.to.shared.u64 t, %1; cvt.u32.u64 %0, t; }" : "=r"(a) : "l"(p));
    return a;
}
__device__ __forceinline__ void cpa16(uint32_t saddr, const void* g) {
    asm volatile("cp.async.cg.shared.global [%0], [%1], 16;" :: "r"(saddr), "l"(g));
}
__device__ __forceinline__ void cpa_commit() { asm volatile("cp.async.commit_group;"); }
__device__ __forceinline__ void cpa_wait2()  { asm volatile("cp.async.wait_group 2;"); }
__device__ __forceinline__ void cpa_wait1()  { asm volatile("cp.async.wait_group 1;"); }
__device__ __forceinline__ void cpa_wait0()  { asm volatile("cp.async.wait_group 0;"); }

#define LDMX4(r0, r1, r2, r3, addr) \
    asm volatile("ldmatrix.sync.aligned.m8n8.x4.shared.b16 {%0,%1,%2,%3}, [%4];" \
        : "=r"(r0), "=r"(r1), "=r"(r2), "=r"(r3) : "r"(addr))

#define LDMX4T(r0, r1, r2, r3, addr) \
    asm volatile("ldmatrix.sync.aligned.m8n8.x4.trans.shared.b16 {%0,%1,%2,%3}, [%4];" \
        : "=r"(r0), "=r"(r1), "=r"(r2), "=r"(r3) : "r"(addr))

__device__ __forceinline__ void mma_f16(float* d, const uint32_t* a, const uint32_t* b) {
    asm volatile(
        "mma.sync.aligned.m16n8k16.row.col.f32.f16.f16.f32 "
        "{%0,%1,%2,%3}, {%4,%5,%6,%7}, {%8,%9}, {%0,%1,%2,%3};"
        : "+f"(d[0]), "+f"(d[1]), "+f"(d[2]), "+f"(d[3])
        : "r"(a[0]), "r"(a[1]), "r"(a[2]), "r"(a[3]), "r"(b[0]), "r"(b[1]));
}

__device__ __forceinline__ uint32_t tile_off(int row, int grp) {
    return (uint32_t)(row * 64 + ((grp ^ ((row >> 1) & 3)) << 4));
}
__device__ __forceinline__ uint32_t aoff(int row, int grp) {
    return (uint32_t)(row * 128 + ((grp ^ (row & 7)) << 4));
}

// ---------------- norm kernels ----------------
__device__ __forceinline__ void block_reduce2(float& s1, float& s2) {
    #pragma unroll
    for (int off = 16; off; off >>= 1) {
        s1 += __shfl_xor_sync(0xffffffffu, s1, off);
        s2 += __shfl_xor_sync(0xffffffffu, s2, off);
    }
    __shared__ float a[8], b[8];
    int w = threadIdx.x >> 5, lane = threadIdx.x & 31;
    if (lane == 0) { a[w] = s1; b[w] = s2; }
    __syncthreads();
    s1 = 0.f; s2 = 0.f;
    #pragma unroll
    for (int i = 0; i < 8; i++) { s1 += a[i]; s2 += b[i]; }
}

__global__ void layernorm_h_k(const float* __restrict__ x, const float* __restrict__ g,
                              const float* __restrict__ b, __half* __restrict__ y, float eps) {
    long row = blockIdx.x;
    float4 xv = ((const float4*)(x + row * DMODEL))[threadIdx.x];
    float s  = xv.x + xv.y + xv.z + xv.w;
    float sq = xv.x*xv.x + xv.y*xv.y + xv.z*xv.z + xv.w*xv.w;
    block_reduce2(s, sq);
    float mu  = s * (1.0f / DMODEL);
    float var = sq * (1.0f / DMODEL) - mu * mu;
    float rstd = rsqrtf(var + eps);
    float4 gv = ((const float4*)g)[threadIdx.x];
    float4 bv = ((const float4*)b)[threadIdx.x];
    long idx = row * DMODEL + threadIdx.x * 4;
    __half2 a = __floats2half2_rn((xv.x - mu) * rstd * gv.x + bv.x,
                                  (xv.y - mu) * rstd * gv.y + bv.y);
    __half2 c = __floats2half2_rn((xv.z - mu) * rstd * gv.z + bv.z,
                                  (xv.w - mu) * rstd * gv.w + bv.w);
    *(__half2*)(y + idx)     = a;
    *(__half2*)(y + idx + 2) = c;
}

__global__ void rmsnorm_hh_k(__half* __restrict__ x, const float* __restrict__ w, int ld,
                             float eps) {
    long row = blockIdx.x;
    __half* xr = x + row * (long)ld;
    __half2 h01 = *(__half2*)(xr + threadIdx.x * 4);
    __half2 h23 = *(__half2*)(xr + threadIdx.x * 4 + 2);
    float v0 = __half2float(__low2half(h01)), v1 = __half2float(__high2half(h01));
    float v2 = __half2float(__low2half(h23)), v3 = __half2float(__high2half(h23));
    float sq = v0*v0 + v1*v1 + v2*v2 + v3*v3;
    float dummy = 0.f;
    block_reduce2(sq, dummy);
    float rstd = rsqrtf(sq * (1.0f / DMODEL) + eps);
    float4 wv = ((const float4*)w)[threadIdx.x];
    __half2 a = __floats2half2_rn(v0 * rstd * wv.x, v1 * rstd * wv.y);
    __half2 b = __floats2half2_rn(v2 * rstd * wv.z, v3 * rstd * wv.w);
    *(__half2*)(xr + threadIdx.x * 4)     = a;
    *(__half2*)(xr + threadIdx.x * 4 + 2) = b;
}

// all-weights transpose+fp16 convert. 12288 blocks of 256 threads.
__global__ void wcvt_all_k(const float* __restrict__ Wq, const float* __restrict__ Wk,
                           const float* __restrict__ Wv, const float* __restrict__ Wo,
                           const float* __restrict__ W1, const float* __restrict__ W2,
                           __half* __restrict__ wq, __half* __restrict__ wkv,
                           __half* __restrict__ wo, __half* __restrict__ w1,
                           __half* __restrict__ w2) {
    __shared__ float ts[32][33];
    int bid = blockIdx.x;
    const float* src; __half* dst; int Kd, N;
    if      (bid <  1024) { src = Wq; dst = wq;                Kd = 1024; N = 1024; }
    else if (bid <  2048) { src = Wk; dst = wkv;               Kd = 1024; N = 1024; bid -= 1024; }
    else if (bid <  3072) { src = Wv; dst = wkv + 1024 * 1024; Kd = 1024; N = 1024; bid -= 2048; }
    else if (bid <  4096) { src = Wo; dst = wo;                Kd = 1024; N = 1024; bid -= 3072; }
    else if (bid <  8192) { src = W1; dst = w1;                Kd = 1024; N = 4096; bid -= 4096; }
    else                  { src = W2; dst = w2;                Kd = 4096; N = 1024; bid -= 8192; }
    int ntn = N >> 5;
    int n0 = (bid % ntn) << 5, k0 = (bid / ntn) << 5;
    int tx = threadIdx.x & 31, ty = threadIdx.x >> 5;
    #pragma unroll
    for (int i = 0; i < 32; i += 8)
        ts[ty + i][tx] = src[(long)(k0 + ty + i) * N + n0 + tx];
    __syncthreads();
    #pragma unroll
    for (int i = 0; i < 32; i += 8)
        dst[(long)(n0 + ty + i) * Kd + k0 + tx] = __float2half(ts[tx][ty + i]);
}

// ---------------- fp16 HMMA GEMM (4 warps, 64x64 per warp) ----------------
// C[M x N] = A[M x K] @ B^T + bias. CTA tile 128x128, K-chunk 32, 3-stage cp.async.
// EPI: 1 = fp32 out + residual, 2 = GELU -> fp16, 3 = plain fp16
#define GEMM_SMEM_BYTES (3 * 2 * 8192)   // 48KB

template<int EPI>
__global__ __launch_bounds__(128) void hgemm_k(
    const __half* __restrict__ A, const __half* __restrict__ B,
    const float* __restrict__ bias, const float* __restrict__ R,
    float* __restrict__ Cf, __half* __restrict__ Ch,
    int M, int N, int Kd)
{
    extern __shared__ char smem[];
    const uint32_t sbase = smem_u32(smem);
    const int tid = threadIdx.x;
    const int lane = tid & 31, wid = tid >> 5;
    const int wm = wid >> 1, wn = wid & 1;          // warp grid 2x2, each 64x64
    const int m0 = blockIdx.y * 128, n0 = blockIdx.x * 128;

    float acc[4][8][4] = {};
    const int nch = Kd >> 5;

    auto load_chunk = [&](int c) {
        const uint32_t stg = sbase + (c % 3) * 16384;
        const int k0 = c << 5;
        #pragma unroll
        for (int e = tid; e < 512; e += 128) {
            int row = e >> 2, grp = e & 3;
            uint32_t so = tile_off(row, grp);
            cpa16(stg +        so, A + (long)(m0 + row) * Kd + k0 + grp * 8);
            cpa16(stg + 8192 + so, B + (long)(n0 + row) * Kd + k0 + grp * 8);
        }
        cpa_commit();
    };

    load_chunk(0);
    if (nch > 1) load_chunk(1);

    const int arow = lane & 15;
    const int akh  = (lane >> 4) & 1;
    const int bn   = ((lane >> 4) & 1) * 8 + (lane & 7);
    const int bkh  = (lane >> 3) & 1;

    for (int c = 0; c < nch; ++c) {
        if (c + 2 < nch)      { load_chunk(c + 2); cpa_wait2(); }
        else if (c + 1 < nch) { cpa_wait1(); }
        else                  { cpa_wait0(); }
        __syncthreads();

        const uint32_t sA = sbase + (c % 3) * 16384;
        const uint32_t sB = sA + 8192;

        #pragma unroll
        for (int ks = 0; ks < 2; ++ks) {
            uint32_t bh[8][2];
            #pragma unroll
            for (int nt2 = 0; nt2 < 4; ++nt2) {
                int row = wn * 64 + nt2 * 16 + bn;
                int grp = ks * 2 + bkh;
                uint32_t so = tile_off(row, grp);
                LDMX4(bh[nt2*2][0], bh[nt2*2][1], bh[nt2*2+1][0], bh[nt2*2+1][1], sB + so);
            }
            #pragma unroll
            for (int mt = 0; mt < 4; ++mt) {
                int row = wm * 64 + mt * 16 + arow;
                int grp = ks * 2 + akh;
                uint32_t so = tile_off(row, grp);
                uint32_t ah[4];
                LDMX4(ah[0], ah[1], ah[2], ah[3], sA + so);
                #pragma unroll
                for (int nt = 0; nt < 8; ++nt)
                    mma_f16(acc[mt][nt], ah, bh[nt]);
            }
        }
        __syncthreads();
    }

    #pragma unroll
    for (int mt = 0; mt < 4; ++mt) {
        #pragma unroll
        for (int nt = 0; nt < 8; ++nt) {
            int r0 = m0 + wm * 64 + mt * 16 + (lane >> 2);
            int c0 = n0 + wn * 64 + nt * 8 + (lane & 3) * 2;
            float b0 = bias[c0], b1 = bias[c0 + 1];
            #pragma unroll
            for (int half = 0; half < 2; ++half) {
                int row = r0 + half * 8;
                long gi = (long)row * N + c0;
                float v0 = acc[mt][nt][half * 2 + 0] + b0;
                float v1 = acc[mt][nt][half * 2 + 1] + b1;
                if (EPI == 1) {
                    float2 rv = *(const float2*)(R + gi);
                    v0 += rv.x; v1 += rv.y;
                }
                if (EPI == 2) {
                    v0 = 0.5f * v0 * (1.0f + erff(v0 * 0.7071067811865476f));
                    v1 = 0.5f * v1 * (1.0f + erff(v1 * 0.7071067811865476f));
                }
                if (EPI >= 2) {
                    __half2 ph = __floats2half2_rn(v0, v1);
                    *(__half2*)(Ch + gi) = ph;
                } else {
                    float2 o = {v0, v1};
                    *(float2*)(Cf + gi) = o;
                }
            }
        }
    }
}

// ---------------- HMMA flash attention (plain fp16, strided K/V) ----------------
#define ATT_SMEM (8192 + 3 * 16384)

__global__ __launch_bounds__(128) void flash_attn_mma(
    const __half* __restrict__ Q, const __half* __restrict__ K,
    const __half* __restrict__ V, __half* __restrict__ C)
{
    extern __shared__ char smem[];
    const uint32_t sb = smem_u32(smem);
    const int tid = threadIdx.x, lane = tid & 31, warp = tid >> 5;
    const int q0 = blockIdx.x * 64, h = blockIdx.y, b = blockIdx.z;
    const int wq0 = warp * 16;
    const float scale = 0.125f;

    const uint32_t sQ = sb;

    {
        const long gq = (long)(b * KQ + q0) * DMODEL + h * HD;
        for (int e = tid; e < 512; e += 128) {
            int row = e >> 3, grp = e & 7;
            cpa16(sQ + aoff(row, grp), Q + gq + (long)row * DMODEL + grp * 8);
        }
    }
    #define LOAD_KV(it_) do { \
        const uint32_t st_ = sb + 8192 + ((it_) % 3) * 16384; \
        const long gk_ = (long)(b * NKV + (it_) * 64) * KVLD + h * HD; \
        for (int e = tid; e < 512; e += 128) { \
            int row = e >> 3, grp = e & 7; \
            long g = gk_ + (long)row * KVLD + grp * 8; \
            uint32_t so = aoff(row, grp); \
            cpa16(st_ +        so, K + g); \
            cpa16(st_ + 8192 + so, V + g); \
        } \
        cpa_commit(); \
    } while (0)

    LOAD_KV(0);
    LOAD_KV(1);

    uint32_t qf[4][4];
    float ctx[8][4] = {};
    float m0 = -INFINITY, m1 = -INFINITY, l0 = 0.f, l1 = 0.f;

    const int NIT = NKV / 64;
    for (int it = 0; it < NIT; ++it) {
        if (it + 1 < NIT) cpa_wait1(); else cpa_wait0();
        __syncthreads();
        if (it == 0) {
            int row = wq0 + (lane & 15);
            #pragma unroll
            for (int ks = 0; ks < 4; ++ks) {
                int grp = ks * 2 + ((lane >> 4) & 1);
                uint32_t so = aoff(row, grp);
                LDMX4(qf[ks][0], qf[ks][1], qf[ks][2], qf[ks][3], sQ + so);
            }
        }
        if (it + 2 < NIT) LOAD_KV(it + 2);

        const uint32_t st  = sb + 8192 + (it % 3) * 16384;
        const uint32_t sk = st, sv = st + 8192;

        float S[8][4] = {};
        #pragma unroll
        for (int ks = 0; ks < 4; ++ks) {
            uint32_t bh[8][2];
            #pragma unroll
            for (int kp = 0; kp < 4; ++kp) {
                int row = kp * 16 + ((lane >> 4) & 1) * 8 + (lane & 7);
                int grp = ks * 2 + ((lane >> 3) & 1);
                uint32_t so = aoff(row, grp);
                LDMX4(bh[2*kp][0], bh[2*kp][1], bh[2*kp+1][0], bh[2*kp+1][1], sk + so);
            }
            #pragma unroll
            for (int nt = 0; nt < 8; ++nt)
                mma_f16(S[nt], qf[ks], bh[nt]);
        }

        float mx0 = -INFINITY, mx1 = -INFINITY;
        #pragma unroll
        for (int nt = 0; nt < 8; ++nt) {
            mx0 = fmaxf(mx0, fmaxf(S[nt][0], S[nt][1]));
            mx1 = fmaxf(mx1, fmaxf(S[nt][2], S[nt][3]));
        }
        mx0 = fmaxf(mx0, __shfl_xor_sync(0xffffffffu, mx0, 1));
        mx0 = fmaxf(mx0, __shfl_xor_sync(0xffffffffu, mx0, 2));
        mx1 = fmaxf(mx1, __shfl_xor_sync(0xffffffffu, mx1, 1));
        mx1 = fmaxf(mx1, __shfl_xor_sync(0xffffffffu, mx1, 2));
        float m0n = fmaxf(m0, mx0), m1n = fmaxf(m1, mx1);
        float cr0 = __expf((m0 - m0n) * scale), cr1 = __expf((m1 - m1n) * scale);
        float s0 = 0.f, s1 = 0.f;
        #pragma unroll
        for (int nt = 0; nt < 8; ++nt) {
            S[nt][0] = __expf((S[nt][0] - m0n) * scale);
            S[nt][1] = __expf((S[nt][1] - m0n) * scale);
            S[nt][2] = __expf((S[nt][2] - m1n) * scale);
            S[nt][3] = __expf((S[nt][3] - m1n) * scale);
            s0 += S[nt][0] + S[nt][1];
            s1 += S[nt][2] + S[nt][3];
        }
        s0 += __shfl_xor_sync(0xffffffffu, s0, 1);
        s0 += __shfl_xor_sync(0xffffffffu, s0, 2);
        s1 += __shfl_xor_sync(0xffffffffu, s1, 1);
        s1 += __shfl_xor_sync(0xffffffffu, s1, 2);
        l0 = l0 * cr0 + s0;  l1 = l1 * cr1 + s1;
        m0 = m0n;  m1 = m1n;
        #pragma unroll
        for (int dt = 0; dt < 8; ++dt) {
            ctx[dt][0] *= cr0; ctx[dt][1] *= cr0;
            ctx[dt][2] *= cr1; ctx[dt][3] *= cr1;
        }

        uint32_t pa[4][4];
        #pragma unroll
        for (int j = 0; j < 4; ++j) {
            __half2 t;
            t = __floats2half2_rn(S[2*j][0],   S[2*j][1]);   pa[j][0] = *(uint32_t*)&t;
            t = __floats2half2_rn(S[2*j][2],   S[2*j][3]);   pa[j][1] = *(uint32_t*)&t;
            t = __floats2half2_rn(S[2*j+1][0], S[2*j+1][1]); pa[j][2] = *(uint32_t*)&t;
            t = __floats2half2_rn(S[2*j+1][2], S[2*j+1][3]); pa[j][3] = *(uint32_t*)&t;
        }

        #pragma unroll
        for (int ks = 0; ks < 4; ++ks) {
            uint32_t vb[8][2];
            #pragma unroll
            for (int dp = 0; dp < 4; ++dp) {
                int row = ks * 16 + ((lane >> 3) & 1) * 8 + (lane & 7);
                int grp = dp * 2 + ((lane >> 4) & 1);
                uint32_t so = aoff(row, grp);
                LDMX4T(vb[2*dp][0], vb[2*dp][1], vb[2*dp+1][0], vb[2*dp+1][1], sv + so);
            }
            #pragma unroll
            for (int dt = 0; dt < 8; ++dt)
                mma_f16(ctx[dt], pa[ks], vb[dt]);
        }
        __syncthreads();
    }

    float i0 = 1.f / l0, i1 = 1.f / l1;
    int r0 = q0 + wq0 + (lane >> 2);
    int r1 = r0 + 8;
    #pragma unroll
    for (int dt = 0; dt < 8; ++dt) {
        int col = h * HD + dt * 8 + (lane & 3) * 2;
        long g0 = (long)(b * KQ + r0) * DMODEL + col;
        long g1 = (long)(b * KQ + r1) * DMODEL + col;
        __half2 p0 = __floats2half2_rn(ctx[dt][0] * i0, ctx[dt][1] * i0);
        __half2 p1 = __floats2half2_rn(ctx[dt][2] * i1, ctx[dt][3] * i1);
        *(__half2*)(C + g0) = p0;
        *(__half2*)(C + g1) = p1;
    }
    #undef LOAD_KV
}

// ---------------- launch ----------------
extern "C" void kernel_launch(void* const* d_in, const int* in_sizes, int n_in,
                              void* d_out, int out_size) {
    const float* query_tokens   = (const float*)d_in[0];
    const float* point_features = (const float*)d_in[1];
    const float* ln_q_g  = (const float*)d_in[2];
    const float* ln_q_b  = (const float*)d_in[3];
    const float* ln_kv_g = (const float*)d_in[4];
    const float* ln_kv_b = (const float*)d_in[5];
    const float* Wq = (const float*)d_in[6];   const float* bq = (const float*)d_in[7];
    const float* Wk = (const float*)d_in[8];   const float* bk = (const float*)d_in[9];
    const float* Wv = (const float*)d_in[10];  const float* bv = (const float*)d_in[11];
    const float* rms_q_w = (const float*)d_in[12];
    const float* rms_k_w = (const float*)d_in[13];
    const float* Wo = (const float*)d_in[14];  const float* bo = (const float*)d_in[15];
    const float* ln_mlp_g = (const float*)d_in[16];
    const float* ln_mlp_b = (const float*)d_in[17];
    const float* W1 = (const float*)d_in[18];  const float* b1 = (const float*)d_in[19];
    const float* W2 = (const float*)d_in[20];  const float* b2 = (const float*)d_in[21];
    float* out = (float*)d_out;

    float *p_out, *p_bkv;
    cudaGetSymbolAddress((void**)&p_out, g_out);
    cudaGetSymbolAddress((void**)&p_bkv, g_bkv);

    __half *qln,*kvln,*ctx,*hln,*m1,*qp,*kv;
    __half *wq,*wkv,*wo,*w1,*w2;
    cudaGetSymbolAddress((void**)&qln, g_qln);  cudaGetSymbolAddress((void**)&kvln, g_kvln);
    cudaGetSymbolAddress((void**)&ctx, g_ctx);  cudaGetSymbolAddress((void**)&hln, g_hln);
    cudaGetSymbolAddress((void**)&m1, g_m1);
    cudaGetSymbolAddress((void**)&qp, g_qp);    cudaGetSymbolAddress((void**)&kv, g_kv);
    cudaGetSymbolAddress((void**)&wq, g_wq);    cudaGetSymbolAddress((void**)&wkv, g_wkv);
    cudaGetSymbolAddress((void**)&wo, g_wo);
    cudaGetSymbolAddress((void**)&w1, g_w1);    cudaGetSymbolAddress((void**)&w2, g_w2);

    cudaFuncSetAttribute(hgemm_k<1>, cudaFuncAttributeMaxDynamicSharedMemorySize, GEMM_SMEM_BYTES);
    cudaFuncSetAttribute(hgemm_k<2>, cudaFuncAttributeMaxDynamicSharedMemorySize, GEMM_SMEM_BYTES);
    cudaFuncSetAttribute(hgemm_k<3>, cudaFuncAttributeMaxDynamicSharedMemorySize, GEMM_SMEM_BYTES);
    cudaFuncSetAttribute(flash_attn_mma, cudaFuncAttributeMaxDynamicSharedMemorySize, ATT_SMEM);

    cudaMemcpyAsync(p_bkv,        bk, DMODEL * sizeof(float), cudaMemcpyDeviceToDevice);
    cudaMemcpyAsync(p_bkv + 1024, bv, DMODEL * sizeof(float), cudaMemcpyDeviceToDevice);

    wcvt_all_k<<<12288, 256>>>(Wq, Wk, Wv, Wo, W1, W2, wq, wkv, wo, w1, w2);

    layernorm_h_k<<<MQ,  256>>>(query_tokens,   ln_q_g,  ln_q_b,  qln,  1e-5f);
    layernorm_h_k<<<MKV, 256>>>(point_features, ln_kv_g, ln_kv_b, kvln, 1e-5f);

    hgemm_k<3><<<dim3(DMODEL/128, MQ/128), 128, GEMM_SMEM_BYTES>>>(
        qln, wq, bq, nullptr, nullptr, qp, MQ, DMODEL, DMODEL);
    rmsnorm_hh_k<<<MQ, 256>>>(qp, rms_q_w, DMODEL, 1e-6f);

    hgemm_k<3><<<dim3(KVLD/128, MKV/128), 128, GEMM_SMEM_BYTES>>>(
        kvln, wkv, p_bkv, nullptr, nullptr, kv, MKV, KVLD, DMODEL);
    rmsnorm_hh_k<<<MKV, 256>>>(kv, rms_k_w, KVLD, 1e-6f);

    flash_attn_mma<<<dim3(KQ/64, NHEAD, BATCH), 128, ATT_SMEM>>>(qp, kv, kv + 1024, ctx);

    hgemm_k<1><<<dim3(DMODEL/128, MQ/128), 128, GEMM_SMEM_BYTES>>>(
        ctx, wo, bo, query_tokens, p_out, nullptr, MQ, DMODEL, DMODEL);

    layernorm_h_k<<<MQ, 256>>>(p_out, ln_mlp_g, ln_mlp_b, hln, 1e-5f);
    hgemm_k<2><<<dim3(DFF/128, MQ/128), 128, GEMM_SMEM_BYTES>>>(
        hln, w1, b1, nullptr, nullptr, m1, MQ, DFF, DMODEL);
    hgemm_k<1><<<dim3(DMODEL/128, MQ/128), 128, GEMM_SMEM_BYTES>>>(
        m1, w2, b2, p_out, out, nullptr, MQ, DMODEL, DFF);
}

// round 10
// speedup vs baseline: 10.1550x; 1.0176x over previous
#include <cuda_runtime.h>
#include <cuda_fp16.h>
#include <math.h>
#include <stdint.h>

// ---------------- problem constants ----------------
#define BATCH 4
#define KQ    512
#define NKV   4096
#define DMODEL 1024
#define NHEAD 16
#define HD    64
#define MQ    (BATCH*KQ)    // 2048
#define MKV   (BATCH*NKV)   // 16384
#define DFF   (4*DMODEL)    // 4096
#define KVLD  2048          // fused k|v row stride

// ---------------- scratch (device globals, no allocs) ----------------
__device__ float g_out [MQ  * DMODEL];
__device__ float g_bkv [KVLD];

__device__ __half g_qln [MQ  * DMODEL];
__device__ __half g_kvln[MKV * DMODEL];
__device__ __half g_qp  [MQ  * DMODEL];
__device__ __half g_kv  [MKV * KVLD];        // fused [k | v]
__device__ __half g_ctx [MQ  * DMODEL];
__device__ __half g_hln [MQ  * DMODEL];
__device__ __half g_m1  [MQ  * DFF];

__device__ __half g_wq [DMODEL*DMODEL];
__device__ __half g_wkv[KVLD*DMODEL];
__device__ __half g_wo [DMODEL*DMODEL];
__device__ __half g_w1 [DMODEL*DFF];
__device__ __half g_w2 [DFF*DMODEL];

// ---------------- low-level helpers ----------------
__device__ __forceinline__ uint32_t smem_u32(const void* p) {
    uint32_t a;
    asm("{ .reg .u64 t; cvta.to.shared.u64 t, %1; cvt.u32.u64 %0, t; }" : "=r"(a) : "l"(p));
    return a;
}
__device__ __forceinline__ void cpa16(uint32_t saddr, const void* g) {
    asm volatile("cp.async.cg.shared.global [%0], [%1], 16;" :: "r"(saddr), "l"(g));
}
__device__ __forceinline__ void cpa_commit() { asm volatile("cp.async.commit_group;"); }
__device__ __forceinline__ void cpa_wait1()  { asm volatile("cp.async.wait_group 1;"); }
__device__ __forceinline__ void cpa_wait0()  { asm volatile("cp.async.wait_group 0;"); }

#define LDMX4(r0, r1, r2, r3, addr) \
    asm volatile("ldmatrix.sync.aligned.m8n8.x4.shared.b16 {%0,%1,%2,%3}, [%4];" \
        : "=r"(r0), "=r"(r1), "=r"(r2), "=r"(r3) : "r"(addr))

#define LDMX4T(r0, r1, r2, r3, addr) \
    asm volatile("ldmatrix.sync.aligned.m8n8.x4.trans.shared.b16 {%0,%1,%2,%3}, [%4];" \
        : "=r"(r0), "=r"(r1), "=r"(r2), "=r"(r3) : "r"(addr))

__device__ __forceinline__ void mma_f16(float* d, const uint32_t* a, const uint32_t* b) {
    asm volatile(
        "mma.sync.aligned.m16n8k16.row.col.f32.f16.f16.f32 "
        "{%0,%1,%2,%3}, {%4,%5,%6,%7}, {%8,%9}, {%0,%1,%2,%3};"
        : "+f"(d[0]), "+f"(d[1]), "+f"(d[2]), "+f"(d[3])
        : "r"(a[0]), "r"(a[1]), "r"(a[2]), "r"(a[3]), "r"(b[0]), "r"(b[1]));
}

// 128-byte rows (64 fp16), 8 groups of 16B, xor swizzle — used by GEMM and attention
__device__ __forceinline__ uint32_t aoff(int row, int grp) {
    return (uint32_t)(row * 128 + ((grp ^ (row & 7)) << 4));
}

// ---------------- norm kernels ----------------
__device__ __forceinline__ void block_reduce2(float& s1, float& s2) {
    #pragma unroll
    for (int off = 16; off; off >>= 1) {
        s1 += __shfl_xor_sync(0xffffffffu, s1, off);
        s2 += __shfl_xor_sync(0xffffffffu, s2, off);
    }
    __shared__ float a[8], b[8];
    int w = threadIdx.x >> 5, lane = threadIdx.x & 31;
    if (lane == 0) { a[w] = s1; b[w] = s2; }
    __syncthreads();
    s1 = 0.f; s2 = 0.f;
    #pragma unroll
    for (int i = 0; i < 8; i++) { s1 += a[i]; s2 += b[i]; }
}

// both pre-LNs in one launch: blocks [0,MQ) -> q path, [MQ, MQ+MKV) -> kv path
__global__ void layernorm2_k(const float* __restrict__ xq, const float* __restrict__ xkv,
                             const float* __restrict__ gq, const float* __restrict__ bq,
                             const float* __restrict__ gkv, const float* __restrict__ bkv,
                             __half* __restrict__ yq, __half* __restrict__ ykv) {
    long row = blockIdx.x;
    const float *x, *g, *b; __half* y;
    if (row < MQ) { x = xq + row * DMODEL; g = gq; b = bq; y = yq + row * DMODEL; }
    else { row -= MQ; x = xkv + row * DMODEL; g = gkv; b = bkv; y = ykv + row * DMODEL; }
    float4 xv = ((const float4*)x)[threadIdx.x];
    float s  = xv.x + xv.y + xv.z + xv.w;
    float sq = xv.x*xv.x + xv.y*xv.y + xv.z*xv.z + xv.w*xv.w;
    block_reduce2(s, sq);
    float mu  = s * (1.0f / DMODEL);
    float var = sq * (1.0f / DMODEL) - mu * mu;
    float rstd = rsqrtf(var + 1e-5f);
    float4 gv = ((const float4*)g)[threadIdx.x];
    float4 bv = ((const float4*)b)[threadIdx.x];
    __half2 a = __floats2half2_rn((xv.x - mu) * rstd * gv.x + bv.x,
                                  (xv.y - mu) * rstd * gv.y + bv.y);
    __half2 c = __floats2half2_rn((xv.z - mu) * rstd * gv.z + bv.z,
                                  (xv.w - mu) * rstd * gv.w + bv.w);
    *(__half2*)(y + threadIdx.x * 4)     = a;
    *(__half2*)(y + threadIdx.x * 4 + 2) = c;
}

__global__ void layernorm_h_k(const float* __restrict__ x, const float* __restrict__ g,
                              const float* __restrict__ b, __half* __restrict__ y, float eps) {
    long row = blockIdx.x;
    float4 xv = ((const float4*)(x + row * DMODEL))[threadIdx.x];
    float s  = xv.x + xv.y + xv.z + xv.w;
    float sq = xv.x*xv.x + xv.y*xv.y + xv.z*xv.z + xv.w*xv.w;
    block_reduce2(s, sq);
    float mu  = s * (1.0f / DMODEL);
    float var = sq * (1.0f / DMODEL) - mu * mu;
    float rstd = rsqrtf(var + eps);
    float4 gv = ((const float4*)g)[threadIdx.x];
    float4 bv = ((const float4*)b)[threadIdx.x];
    long idx = row * DMODEL + threadIdx.x * 4;
    __half2 a = __floats2half2_rn((xv.x - mu) * rstd * gv.x + bv.x,
                                  (xv.y - mu) * rstd * gv.y + bv.y);
    __half2 c = __floats2half2_rn((xv.z - mu) * rstd * gv.z + bv.z,
                                  (xv.w - mu) * rstd * gv.w + bv.w);
    *(__half2*)(y + idx)     = a;
    *(__half2*)(y + idx + 2) = c;
}

// both rmsnorms in one launch: blocks [0,MQ) -> qp (ld DMODEL), [MQ,..) -> kv k-half (ld KVLD)
__global__ void rmsnorm2_k(__half* __restrict__ q, __half* __restrict__ kv,
                           const float* __restrict__ wq, const float* __restrict__ wk) {
    long row = blockIdx.x;
    __half* xr; const float* w;
    if (row < MQ) { xr = q + row * DMODEL; w = wq; }
    else { xr = kv + (row - MQ) * (long)KVLD; w = wk; }
    __half2 h01 = *(__half2*)(xr + threadIdx.x * 4);
    __half2 h23 = *(__half2*)(xr + threadIdx.x * 4 + 2);
    float v0 = __half2float(__low2half(h01)), v1 = __half2float(__high2half(h01));
    float v2 = __half2float(__low2half(h23)), v3 = __half2float(__high2half(h23));
    float sq = v0*v0 + v1*v1 + v2*v2 + v3*v3;
    float dummy = 0.f;
    block_reduce2(sq, dummy);
    float rstd = rsqrtf(sq * (1.0f / DMODEL) + 1e-6f);
    float4 wv = ((const float4*)w)[threadIdx.x];
    __half2 a = __floats2half2_rn(v0 * rstd * wv.x, v1 * rstd * wv.y);
    __half2 b = __floats2half2_rn(v2 * rstd * wv.z, v3 * rstd * wv.w);
    *(__half2*)(xr + threadIdx.x * 4)     = a;
    *(__half2*)(xr + threadIdx.x * 4 + 2) = b;
}

// all-weights transpose+fp16 convert. 12288 blocks of 256 threads.
__global__ void wcvt_all_k(const float* __restrict__ Wq, const float* __restrict__ Wk,
                           const float* __restrict__ Wv, const float* __restrict__ Wo,
                           const float* __restrict__ W1, const float* __restrict__ W2,
                           __half* __restrict__ wq, __half* __restrict__ wkv,
                           __half* __restrict__ wo, __half* __restrict__ w1,
                           __half* __restrict__ w2) {
    __shared__ float ts[32][33];
    int bid = blockIdx.x;
    const float* src; __half* dst; int Kd, N;
    if      (bid <  1024) { src = Wq; dst = wq;                Kd = 1024; N = 1024; }
    else if (bid <  2048) { src = Wk; dst = wkv;               Kd = 1024; N = 1024; bid -= 1024; }
    else if (bid <  3072) { src = Wv; dst = wkv + 1024 * 1024; Kd = 1024; N = 1024; bid -= 2048; }
    else if (bid <  4096) { src = Wo; dst = wo;                Kd = 1024; N = 1024; bid -= 3072; }
    else if (bid <  8192) { src = W1; dst = w1;                Kd = 1024; N = 4096; bid -= 4096; }
    else                  { src = W2; dst = w2;                Kd = 4096; N = 1024; bid -= 8192; }
    int ntn = N >> 5;
    int n0 = (bid % ntn) << 5, k0 = (bid / ntn) << 5;
    int tx = threadIdx.x & 31, ty = threadIdx.x >> 5;
    #pragma unroll
    for (int i = 0; i < 32; i += 8)
        ts[ty + i][tx] = src[(long)(k0 + ty + i) * N + n0 + tx];
    __syncthreads();
    #pragma unroll
    for (int i = 0; i < 32; i += 8)
        dst[(long)(n0 + ty + i) * Kd + k0 + tx] = __float2half(ts[tx][ty + i]);
}

// ---------------- fp16 HMMA GEMM (4 warps, 64x64/warp, K-chunk 64, 2-stage) ----------------
// EPI: 1 = fp32 out + residual, 2 = GELU -> fp16, 3 = plain fp16
#define GEMM_SMEM_BYTES (2 * 2 * 16384)   // 64KB

template<int EPI>
__global__ __launch_bounds__(128) void hgemm_k(
    const __half* __restrict__ A, const __half* __restrict__ B,
    const float* __restrict__ bias, const float* __restrict__ R,
    float* __restrict__ Cf, __half* __restrict__ Ch,
    int M, int N, int Kd)
{
    extern __shared__ char smem[];
    const uint32_t sbase = smem_u32(smem);
    const int tid = threadIdx.x;
    const int lane = tid & 31, wid = tid >> 5;
    const int wm = wid >> 1, wn = wid & 1;          // warp grid 2x2, each 64x64
    const int m0 = blockIdx.y * 128, n0 = blockIdx.x * 128;

    float acc[4][8][4] = {};
    const int nch = Kd >> 6;                        // K-chunks of 64

    auto load_chunk = [&](int c) {
        const uint32_t stg = sbase + (c & 1) * 32768;
        const int k0 = c << 6;
        #pragma unroll
        for (int e = tid; e < 1024; e += 128) {
            int row = e >> 3, grp = e & 7;
            uint32_t so = aoff(row, grp);
            cpa16(stg +         so, A + (long)(m0 + row) * Kd + k0 + grp * 8);
            cpa16(stg + 16384 + so, B + (long)(n0 + row) * Kd + k0 + grp * 8);
        }
        cpa_commit();
    };

    load_chunk(0);

    const int arow = lane & 15;
    const int akh  = (lane >> 4) & 1;
    const int bn   = ((lane >> 4) & 1) * 8 + (lane & 7);
    const int bkh  = (lane >> 3) & 1;

    for (int c = 0; c < nch; ++c) {
        if (c + 1 < nch) { load_chunk(c + 1); cpa_wait1(); }
        else             { cpa_wait0(); }
        __syncthreads();

        const uint32_t sA = sbase + (c & 1) * 32768;
        const uint32_t sB = sA + 16384;

        #pragma unroll
        for (int ks = 0; ks < 4; ++ks) {
            uint32_t bh[8][2];
            #pragma unroll
            for (int nt2 = 0; nt2 < 4; ++nt2) {
                int row = wn * 64 + nt2 * 16 + bn;
                int grp = ks * 2 + bkh;
                uint32_t so = aoff(row, grp);
                LDMX4(bh[nt2*2][0], bh[nt2*2][1], bh[nt2*2+1][0], bh[nt2*2+1][1], sB + so);
            }
            #pragma unroll
            for (int mt = 0; mt < 4; ++mt) {
                int row = wm * 64 + mt * 16 + arow;
                int grp = ks * 2 + akh;
                uint32_t so = aoff(row, grp);
                uint32_t ah[4];
                LDMX4(ah[0], ah[1], ah[2], ah[3], sA + so);
                #pragma unroll
                for (int nt = 0; nt < 8; ++nt)
                    mma_f16(acc[mt][nt], ah, bh[nt]);
            }
        }
        __syncthreads();
    }

    #pragma unroll
    for (int mt = 0; mt < 4; ++mt) {
        #pragma unroll
        for (int nt = 0; nt < 8; ++nt) {
            int r0 = m0 + wm * 64 + mt * 16 + (lane >> 2);
            int c0 = n0 + wn * 64 + nt * 8 + (lane & 3) * 2;
            float b0 = bias[c0], b1 = bias[c0 + 1];
            #pragma unroll
            for (int half = 0; half < 2; ++half) {
                int row = r0 + half * 8;
                long gi = (long)row * N + c0;
                float v0 = acc[mt][nt][half * 2 + 0] + b0;
                float v1 = acc[mt][nt][half * 2 + 1] + b1;
                if (EPI == 1) {
                    float2 rv = *(const float2*)(R + gi);
                    v0 += rv.x; v1 += rv.y;
                }
                if (EPI == 2) {
                    v0 = 0.5f * v0 * (1.0f + erff(v0 * 0.7071067811865476f));
                    v1 = 0.5f * v1 * (1.0f + erff(v1 * 0.7071067811865476f));
                }
                if (EPI >= 2) {
                    __half2 ph = __floats2half2_rn(v0, v1);
                    *(__half2*)(Ch + gi) = ph;
                } else {
                    float2 o = {v0, v1};
                    *(float2*)(Cf + gi) = o;
                }
            }
        }
    }
}

// ---------------- HMMA flash attention (plain fp16, strided K/V) ----------------
#define ATT_SMEM (8192 + 3 * 16384)

__global__ __launch_bounds__(128) void flash_attn_mma(
    const __half* __restrict__ Q, const __half* __restrict__ K,
    const __half* __restrict__ V, __half* __restrict__ C)
{
    extern __shared__ char smem[];
    const uint32_t sb = smem_u32(smem);
    const int tid = threadIdx.x, lane = tid & 31, warp = tid >> 5;
    const int q0 = blockIdx.x * 64, h = blockIdx.y, b = blockIdx.z;
    const int wq0 = warp * 16;
    const float scale = 0.125f;

    const uint32_t sQ = sb;

    {
        const long gq = (long)(b * KQ + q0) * DMODEL + h * HD;
        for (int e = tid; e < 512; e += 128) {
            int row = e >> 3, grp = e & 7;
            cpa16(sQ + aoff(row, grp), Q + gq + (long)row * DMODEL + grp * 8);
        }
    }
    #define LOAD_KV(it_) do { \
        const uint32_t st_ = sb + 8192 + ((it_) % 3) * 16384; \
        const long gk_ = (long)(b * NKV + (it_) * 64) * KVLD + h * HD; \
        for (int e = tid; e < 512; e += 128) { \
            int row = e >> 3, grp = e & 7; \
            long g = gk_ + (long)row * KVLD + grp * 8; \
            uint32_t so = aoff(row, grp); \
            cpa16(st_ +        so, K + g); \
            cpa16(st_ + 8192 + so, V + g); \
        } \
        cpa_commit(); \
    } while (0)

    LOAD_KV(0);
    LOAD_KV(1);

    uint32_t qf[4][4];
    float ctx[8][4] = {};
    float m0 = -INFINITY, m1 = -INFINITY, l0 = 0.f, l1 = 0.f;

    const int NIT = NKV / 64;
    for (int it = 0; it < NIT; ++it) {
        if (it + 1 < NIT) cpa_wait1(); else cpa_wait0();
        __syncthreads();
        if (it == 0) {
            int row = wq0 + (lane & 15);
            #pragma unroll
            for (int ks = 0; ks < 4; ++ks) {
                int grp = ks * 2 + ((lane >> 4) & 1);
                uint32_t so = aoff(row, grp);
                LDMX4(qf[ks][0], qf[ks][1], qf[ks][2], qf[ks][3], sQ + so);
            }
        }
        if (it + 2 < NIT) LOAD_KV(it + 2);

        const uint32_t st  = sb + 8192 + (it % 3) * 16384;
        const uint32_t sk = st, sv = st + 8192;

        float S[8][4] = {};
        #pragma unroll
        for (int ks = 0; ks < 4; ++ks) {
            uint32_t bh[8][2];
            #pragma unroll
            for (int kp = 0; kp < 4; ++kp) {
                int row = kp * 16 + ((lane >> 4) & 1) * 8 + (lane & 7);
                int grp = ks * 2 + ((lane >> 3) & 1);
                uint32_t so = aoff(row, grp);
                LDMX4(bh[2*kp][0], bh[2*kp][1], bh[2*kp+1][0], bh[2*kp+1][1], sk + so);
            }
            #pragma unroll
            for (int nt = 0; nt < 8; ++nt)
                mma_f16(S[nt], qf[ks], bh[nt]);
        }

        float mx0 = -INFINITY, mx1 = -INFINITY;
        #pragma unroll
        for (int nt = 0; nt < 8; ++nt) {
            mx0 = fmaxf(mx0, fmaxf(S[nt][0], S[nt][1]));
            mx1 = fmaxf(mx1, fmaxf(S[nt][2], S[nt][3]));
        }
        mx0 = fmaxf(mx0, __shfl_xor_sync(0xffffffffu, mx0, 1));
        mx0 = fmaxf(mx0, __shfl_xor_sync(0xffffffffu, mx0, 2));
        mx1 = fmaxf(mx1, __shfl_xor_sync(0xffffffffu, mx1, 1));
        mx1 = fmaxf(mx1, __shfl_xor_sync(0xffffffffu, mx1, 2));
        float m0n = fmaxf(m0, mx0), m1n = fmaxf(m1, mx1);
        float cr0 = __expf((m0 - m0n) * scale), cr1 = __expf((m1 - m1n) * scale);
        float s0 = 0.f, s1 = 0.f;
        #pragma unroll
        for (int nt = 0; nt < 8; ++nt) {
            S[nt][0] = __expf((S[nt][0] - m0n) * scale);
            S[nt][1] = __expf((S[nt][1] - m0n) * scale);
            S[nt][2] = __expf((S[nt][2] - m1n) * scale);
            S[nt][3] = __expf((S[nt][3] - m1n) * scale);
            s0 += S[nt][0] + S[nt][1];
            s1 += S[nt][2] + S[nt][3];
        }
        s0 += __shfl_xor_sync(0xffffffffu, s0, 1);
        s0 += __shfl_xor_sync(0xffffffffu, s0, 2);
        s1 += __shfl_xor_sync(0xffffffffu, s1, 1);
        s1 += __shfl_xor_sync(0xffffffffu, s1, 2);
        l0 = l0 * cr0 + s0;  l1 = l1 * cr1 + s1;
        m0 = m0n;  m1 = m1n;
        #pragma unroll
        for (int dt = 0; dt < 8; ++dt) {
            ctx[dt][0] *= cr0; ctx[dt][1] *= cr0;
            ctx[dt][2] *= cr1; ctx[dt][3] *= cr1;
        }

        uint32_t pa[4][4];
        #pragma unroll
        for (int j = 0; j < 4; ++j) {
            __half2 t;
            t = __floats2half2_rn(S[2*j][0],   S[2*j][1]);   pa[j][0] = *(uint32_t*)&t;
            t = __floats2half2_rn(S[2*j][2],   S[2*j][3]);   pa[j][1] = *(uint32_t*)&t;
            t = __floats2half2_rn(S[2*j+1][0], S[2*j+1][1]); pa[j][2] = *(uint32_t*)&t;
            t = __floats2half2_rn(S[2*j+1][2], S[2*j+1][3]); pa[j][3] = *(uint32_t*)&t;
        }

        #pragma unroll
        for (int ks = 0; ks < 4; ++ks) {
            uint32_t vb[8][2];
            #pragma unroll
            for (int dp = 0; dp < 4; ++dp) {
                int row = ks * 16 + ((lane >> 3) & 1) * 8 + (lane & 7);
                int grp = dp * 2 + ((lane >> 4) & 1);
                uint32_t so = aoff(row, grp);
                LDMX4T(vb[2*dp][0], vb[2*dp][1], vb[2*dp+1][0], vb[2*dp+1][1], sv + so);
            }
            #pragma unroll
            for (int dt = 0; dt < 8; ++dt)
                mma_f16(ctx[dt], pa[ks], vb[dt]);
        }
        __syncthreads();
    }

    float i0 = 1.f / l0, i1 = 1.f / l1;
    int r0 = q0 + wq0 + (lane >> 2);
    int r1 = r0 + 8;
    #pragma unroll
    for (int dt = 0; dt < 8; ++dt) {
        int col = h * HD + dt * 8 + (lane & 3) * 2;
        long g0 = (long)(b * KQ + r0) * DMODEL + col;
        long g1 = (long)(b * KQ + r1) * DMODEL + col;
        __half2 p0 = __floats2half2_rn(ctx[dt][0] * i0, ctx[dt][1] * i0);
        __half2 p1 = __floats2half2_rn(ctx[dt][2] * i1, ctx[dt][3] * i1);
        *(__half2*)(C + g0) = p0;
        *(__half2*)(C + g1) = p1;
    }
    #undef LOAD_KV
}

// ---------------- launch ----------------
extern "C" void kernel_launch(void* const* d_in, const int* in_sizes, int n_in,
                              void* d_out, int out_size) {
    const float* query_tokens   = (const float*)d_in[0];
    const float* point_features = (const float*)d_in[1];
    const float* ln_q_g  = (const float*)d_in[2];
    const float* ln_q_b  = (const float*)d_in[3];
    const float* ln_kv_g = (const float*)d_in[4];
    const float* ln_kv_b = (const float*)d_in[5];
    const float* Wq = (const float*)d_in[6];   const float* bq = (const float*)d_in[7];
    const float* Wk = (const float*)d_in[8];   const float* bk = (const float*)d_in[9];
    const float* Wv = (const float*)d_in[10];  const float* bv = (const float*)d_in[11];
    const float* rms_q_w = (const float*)d_in[12];
    const float* rms_k_w = (const float*)d_in[13];
    const float* Wo = (const float*)d_in[14];  const float* bo = (const float*)d_in[15];
    const float* ln_mlp_g = (const float*)d_in[16];
    const float* ln_mlp_b = (const float*)d_in[17];
    const float* W1 = (const float*)d_in[18];  const float* b1 = (const float*)d_in[19];
    const float* W2 = (const float*)d_in[20];  const float* b2 = (const float*)d_in[21];
    float* out = (float*)d_out;

    float *p_out, *p_bkv;
    cudaGetSymbolAddress((void**)&p_out, g_out);
    cudaGetSymbolAddress((void**)&p_bkv, g_bkv);

    __half *qln,*kvln,*ctx,*hln,*m1,*qp,*kv;
    __half *wq,*wkv,*wo,*w1,*w2;
    cudaGetSymbolAddress((void**)&qln, g_qln);  cudaGetSymbolAddress((void**)&kvln, g_kvln);
    cudaGetSymbolAddress((void**)&ctx, g_ctx);  cudaGetSymbolAddress((void**)&hln, g_hln);
    cudaGetSymbolAddress((void**)&m1, g_m1);
    cudaGetSymbolAddress((void**)&qp, g_qp);    cudaGetSymbolAddress((void**)&kv, g_kv);
    cudaGetSymbolAddress((void**)&wq, g_wq);    cudaGetSymbolAddress((void**)&wkv, g_wkv);
    cudaGetSymbolAddress((void**)&wo, g_wo);
    cudaGetSymbolAddress((void**)&w1, g_w1);    cudaGetSymbolAddress((void**)&w2, g_w2);

    cudaFuncSetAttribute(hgemm_k<1>, cudaFuncAttributeMaxDynamicSharedMemorySize, GEMM_SMEM_BYTES);
    cudaFuncSetAttribute(hgemm_k<2>, cudaFuncAttributeMaxDynamicSharedMemorySize, GEMM_SMEM_BYTES);
    cudaFuncSetAttribute(hgemm_k<3>, cudaFuncAttributeMaxDynamicSharedMemorySize, GEMM_SMEM_BYTES);
    cudaFuncSetAttribute(flash_attn_mma, cudaFuncAttributeMaxDynamicSharedMemorySize, ATT_SMEM);

    cudaMemcpyAsync(p_bkv,        bk, DMODEL * sizeof(float), cudaMemcpyDeviceToDevice);
    cudaMemcpyAsync(p_bkv + 1024, bv, DMODEL * sizeof(float), cudaMemcpyDeviceToDevice);

    wcvt_all_k<<<12288, 256>>>(Wq, Wk, Wv, Wo, W1, W2, wq, wkv, wo, w1, w2);

    // both pre-LNs fused
    layernorm2_k<<<MQ + MKV, 256>>>(query_tokens, point_features,
                                    ln_q_g, ln_q_b, ln_kv_g, ln_kv_b, qln, kvln);

    // Q projection, then fused K|V projection
    hgemm_k<3><<<dim3(DMODEL/128, MQ/128), 128, GEMM_SMEM_BYTES>>>(
        qln, wq, bq, nullptr, nullptr, qp, MQ, DMODEL, DMODEL);
    hgemm_k<3><<<dim3(KVLD/128, MKV/128), 128, GEMM_SMEM_BYTES>>>(
        kvln, wkv, p_bkv, nullptr, nullptr, kv, MKV, KVLD, DMODEL);

    // both rmsnorms fused (q dep satisfied by stream order)
    rmsnorm2_k<<<MQ + MKV, 256>>>(qp, kv, rms_q_w, rms_k_w);

    flash_attn_mma<<<dim3(KQ/64, NHEAD, BATCH), 128, ATT_SMEM>>>(qp, kv, kv + 1024, ctx);

    hgemm_k<1><<<dim3(DMODEL/128, MQ/128), 128, GEMM_SMEM_BYTES>>>(
        ctx, wo, bo, query_tokens, p_out, nullptr, MQ, DMODEL, DMODEL);

    layernorm_h_k<<<MQ, 256>>>(p_out, ln_mlp_g, ln_mlp_b, hln, 1e-5f);
    hgemm_k<2><<<dim3(DFF/128, MQ/128), 128, GEMM_SMEM_BYTES>>>(
        hln, w1, b1, nullptr, nullptr, m1, MQ, DFF, DMODEL);
    hgemm_k<1><<<dim3(DMODEL/128, MQ/128), 128, GEMM_SMEM_BYTES>>>(
        m1, w2, b2, p_out, out, nullptr, MQ, DMODEL, DFF);
}

// round 11
// speedup vs baseline: 10.3811x; 1.0223x over previous
#include <cuda_runtime.h>
#include <cuda_fp16.h>
#include <math.h>
#include <stdint.h>

// ---------------- problem constants ----------------
#define BATCH 4
#define KQ    512
#define NKV   4096
#define DMODEL 1024
#define NHEAD 16
#define HD    64
#define MQ    (BATCH*KQ)    // 2048
#define MKV   (BATCH*NKV)   // 16384
#define DFF   (4*DMODEL)    // 4096
#define KVLD  2048          // fused k|v row stride

// ---------------- scratch (device globals, no allocs) ----------------
__device__ float g_out [MQ  * DMODEL];
__device__ float g_bkv [KVLD];

__device__ __half g_qln [MQ  * DMODEL];
__device__ __half g_kvln[MKV * DMODEL];
__device__ __half g_qp  [MQ  * DMODEL];
__device__ __half g_kv  [MKV * KVLD];        // fused [k | v]
__device__ __half g_ctx [MQ  * DMODEL];
__device__ __half g_hln [MQ  * DMODEL];
__device__ __half g_m1  [MQ  * DFF];

__device__ __half g_wq [DMODEL*DMODEL];
__device__ __half g_wkv[KVLD*DMODEL];
__device__ __half g_wo [DMODEL*DMODEL];
__device__ __half g_w1 [DMODEL*DFF];
__device__ __half g_w2 [DFF*DMODEL];

// ---------------- low-level helpers ----------------
__device__ __forceinline__ uint32_t smem_u32(const void* p) {
    uint32_t a;
    asm("{ .reg .u64 t; cvta.to.shared.u64 t, %1; cvt.u32.u64 %0, t; }" : "=r"(a) : "l"(p));
    return a;
}
__device__ __forceinline__ void cpa16(uint32_t saddr, const void* g) {
    asm volatile("cp.async.cg.shared.global [%0], [%1], 16;" :: "r"(saddr), "l"(g));
}
__device__ __forceinline__ void cpa_commit() { asm volatile("cp.async.commit_group;"); }
__device__ __forceinline__ void cpa_wait1()  { asm volatile("cp.async.wait_group 1;"); }
__device__ __forceinline__ void cpa_wait0()  { asm volatile("cp.async.wait_group 0;"); }

#define LDMX4(r0, r1, r2, r3, addr) \
    asm volatile("ldmatrix.sync.aligned.m8n8.x4.shared.b16 {%0,%1,%2,%3}, [%4];" \
        : "=r"(r0), "=r"(r1), "=r"(r2), "=r"(r3) : "r"(addr))

#define LDMX4T(r0, r1, r2, r3, addr) \
    asm volatile("ldmatrix.sync.aligned.m8n8.x4.trans.shared.b16 {%0,%1,%2,%3}, [%4];" \
        : "=r"(r0), "=r"(r1), "=r"(r2), "=r"(r3) : "r"(addr))

__device__ __forceinline__ void mma_f16(float* d, const uint32_t* a, const uint32_t* b) {
    asm volatile(
        "mma.sync.aligned.m16n8k16.row.col.f32.f16.f16.f32 "
        "{%0,%1,%2,%3}, {%4,%5,%6,%7}, {%8,%9}, {%0,%1,%2,%3};"
        : "+f"(d[0]), "+f"(d[1]), "+f"(d[2]), "+f"(d[3])
        : "r"(a[0]), "r"(a[1]), "r"(a[2]), "r"(a[3]), "r"(b[0]), "r"(b[1]));
}

// 128-byte rows (64 fp16), 8 groups of 16B, xor swizzle
__device__ __forceinline__ uint32_t aoff(int row, int grp) {
    return (uint32_t)(row * 128 + ((grp ^ (row & 7)) << 4));
}

// ---------------- norm kernels ----------------
__device__ __forceinline__ void block_reduce2(float& s1, float& s2) {
    #pragma unroll
    for (int off = 16; off; off >>= 1) {
        s1 += __shfl_xor_sync(0xffffffffu, s1, off);
        s2 += __shfl_xor_sync(0xffffffffu, s2, off);
    }
    __shared__ float a[8], b[8];
    int w = threadIdx.x >> 5, lane = threadIdx.x & 31;
    if (lane == 0) { a[w] = s1; b[w] = s2; }
    __syncthreads();
    s1 = 0.f; s2 = 0.f;
    #pragma unroll
    for (int i = 0; i < 8; i++) { s1 += a[i]; s2 += b[i]; }
}

__global__ void layernorm2_k(const float* __restrict__ xq, const float* __restrict__ xkv,
                             const float* __restrict__ gq, const float* __restrict__ bq,
                             const float* __restrict__ gkv, const float* __restrict__ bkv,
                             __half* __restrict__ yq, __half* __restrict__ ykv) {
    long row = blockIdx.x;
    const float *x, *g, *b; __half* y;
    if (row < MQ) { x = xq + row * DMODEL; g = gq; b = bq; y = yq + row * DMODEL; }
    else { row -= MQ; x = xkv + row * DMODEL; g = gkv; b = bkv; y = ykv + row * DMODEL; }
    float4 xv = ((const float4*)x)[threadIdx.x];
    float s  = xv.x + xv.y + xv.z + xv.w;
    float sq = xv.x*xv.x + xv.y*xv.y + xv.z*xv.z + xv.w*xv.w;
    block_reduce2(s, sq);
    float mu  = s * (1.0f / DMODEL);
    float var = sq * (1.0f / DMODEL) - mu * mu;
    float rstd = rsqrtf(var + 1e-5f);
    float4 gv = ((const float4*)g)[threadIdx.x];
    float4 bv = ((const float4*)b)[threadIdx.x];
    __half2 a = __floats2half2_rn((xv.x - mu) * rstd * gv.x + bv.x,
                                  (xv.y - mu) * rstd * gv.y + bv.y);
    __half2 c = __floats2half2_rn((xv.z - mu) * rstd * gv.z + bv.z,
                                  (xv.w - mu) * rstd * gv.w + bv.w);
    *(__half2*)(y + threadIdx.x * 4)     = a;
    *(__half2*)(y + threadIdx.x * 4 + 2) = c;
}

__global__ void layernorm_h_k(const float* __restrict__ x, const float* __restrict__ g,
                              const float* __restrict__ b, __half* __restrict__ y, float eps) {
    long row = blockIdx.x;
    float4 xv = ((const float4*)(x + row * DMODEL))[threadIdx.x];
    float s  = xv.x + xv.y + xv.z + xv.w;
    float sq = xv.x*xv.x + xv.y*xv.y + xv.z*xv.z + xv.w*xv.w;
    block_reduce2(s, sq);
    float mu  = s * (1.0f / DMODEL);
    float var = sq * (1.0f / DMODEL) - mu * mu;
    float rstd = rsqrtf(var + eps);
    float4 gv = ((const float4*)g)[threadIdx.x];
    float4 bv = ((const float4*)b)[threadIdx.x];
    long idx = row * DMODEL + threadIdx.x * 4;
    __half2 a = __floats2half2_rn((xv.x - mu) * rstd * gv.x + bv.x,
                                  (xv.y - mu) * rstd * gv.y + bv.y);
    __half2 c = __floats2half2_rn((xv.z - mu) * rstd * gv.z + bv.z,
                                  (xv.w - mu) * rstd * gv.w + bv.w);
    *(__half2*)(y + idx)     = a;
    *(__half2*)(y + idx + 2) = c;
}

__global__ void rmsnorm2_k(__half* __restrict__ q, __half* __restrict__ kv,
                           const float* __restrict__ wq, const float* __restrict__ wk) {
    long row = blockIdx.x;
    __half* xr; const float* w;
    if (row < MQ) { xr = q + row * DMODEL; w = wq; }
    else { xr = kv + (row - MQ) * (long)KVLD; w = wk; }
    __half2 h01 = *(__half2*)(xr + threadIdx.x * 4);
    __half2 h23 = *(__half2*)(xr + threadIdx.x * 4 + 2);
    float v0 = __half2float(__low2half(h01)), v1 = __half2float(__high2half(h01));
    float v2 = __half2float(__low2half(h23)), v3 = __half2float(__high2half(h23));
    float sq = v0*v0 + v1*v1 + v2*v2 + v3*v3;
    float dummy = 0.f;
    block_reduce2(sq, dummy);
    float rstd = rsqrtf(sq * (1.0f / DMODEL) + 1e-6f);
    float4 wv = ((const float4*)w)[threadIdx.x];
    __half2 a = __floats2half2_rn(v0 * rstd * wv.x, v1 * rstd * wv.y);
    __half2 b = __floats2half2_rn(v2 * rstd * wv.z, v3 * rstd * wv.w);
    *(__half2*)(xr + threadIdx.x * 4)     = a;
    *(__half2*)(xr + threadIdx.x * 4 + 2) = b;
}

__global__ void wcvt_all_k(const float* __restrict__ Wq, const float* __restrict__ Wk,
                           const float* __restrict__ Wv, const float* __restrict__ Wo,
                           const float* __restrict__ W1, const float* __restrict__ W2,
                           __half* __restrict__ wq, __half* __restrict__ wkv,
                           __half* __restrict__ wo, __half* __restrict__ w1,
                           __half* __restrict__ w2) {
    __shared__ float ts[32][33];
    int bid = blockIdx.x;
    const float* src; __half* dst; int Kd, N;
    if      (bid <  1024) { src = Wq; dst = wq;                Kd = 1024; N = 1024; }
    else if (bid <  2048) { src = Wk; dst = wkv;               Kd = 1024; N = 1024; bid -= 1024; }
    else if (bid <  3072) { src = Wv; dst = wkv + 1024 * 1024; Kd = 1024; N = 1024; bid -= 2048; }
    else if (bid <  4096) { src = Wo; dst = wo;                Kd = 1024; N = 1024; bid -= 3072; }
    else if (bid <  8192) { src = W1; dst = w1;                Kd = 1024; N = 4096; bid -= 4096; }
    else                  { src = W2; dst = w2;                Kd = 4096; N = 1024; bid -= 8192; }
    int ntn = N >> 5;
    int n0 = (bid % ntn) << 5, k0 = (bid / ntn) << 5;
    int tx = threadIdx.x & 31, ty = threadIdx.x >> 5;
    #pragma unroll
    for (int i = 0; i < 32; i += 8)
        ts[ty + i][tx] = src[(long)(k0 + ty + i) * N + n0 + tx];
    __syncthreads();
    #pragma unroll
    for (int i = 0; i < 32; i += 8)
        dst[(long)(n0 + ty + i) * Kd + k0 + tx] = __float2half(ts[tx][ty + i]);
}

// ---------------- fp16 HMMA GEMM (4 warps, 64x64/warp, K-chunk 64, 3-stage, 1 sync/chunk) ----
// EPI: 1 = fp32 out + residual, 2 = GELU -> fp16, 3 = plain fp16
#define GEMM_SMEM_BYTES (3 * 2 * 16384)   // 96KB

template<int EPI>
__global__ __launch_bounds__(128) void hgemm_k(
    const __half* __restrict__ A, const __half* __restrict__ B,
    const float* __restrict__ bias, const float* __restrict__ R,
    float* __restrict__ Cf, __half* __restrict__ Ch,
    int M, int N, int Kd)
{
    extern __shared__ char smem[];
    const uint32_t sbase = smem_u32(smem);
    const int tid = threadIdx.x;
    const int lane = tid & 31, wid = tid >> 5;
    const int wm = wid >> 1, wn = wid & 1;          // warp grid 2x2, each 64x64
    const int m0 = blockIdx.y * 128, n0 = blockIdx.x * 128;

    float acc[4][8][4] = {};
    const int nch = Kd >> 6;                        // K-chunks of 64

    auto load_chunk = [&](int c) {
        const uint32_t stg = sbase + (c % 3) * 32768;
        const int k0 = c << 6;
        #pragma unroll
        for (int e = tid; e < 1024; e += 128) {
            int row = e >> 3, grp = e & 7;
            uint32_t so = aoff(row, grp);
            cpa16(stg +         so, A + (long)(m0 + row) * Kd + k0 + grp * 8);
            cpa16(stg + 16384 + so, B + (long)(n0 + row) * Kd + k0 + grp * 8);
        }
        cpa_commit();
    };

    load_chunk(0);
    if (nch > 1) load_chunk(1);

    const int arow = lane & 15;
    const int akh  = (lane >> 4) & 1;
    const int bn   = ((lane >> 4) & 1) * 8 + (lane & 7);
    const int bkh  = (lane >> 3) & 1;

    for (int c = 0; c < nch; ++c) {
        if (c + 1 < nch) cpa_wait1(); else cpa_wait0();
        __syncthreads();                         // single barrier per chunk
        if (c + 2 < nch) load_chunk(c + 2);      // overwrites buf consumed in iter c-1 (safe: after barrier)

        const uint32_t sA = sbase + (c % 3) * 32768;
        const uint32_t sB = sA + 16384;

        #pragma unroll
        for (int ks = 0; ks < 4; ++ks) {
            uint32_t bh[8][2];
            #pragma unroll
            for (int nt2 = 0; nt2 < 4; ++nt2) {
                int row = wn * 64 + nt2 * 16 + bn;
                int grp = ks * 2 + bkh;
                uint32_t so = aoff(row, grp);
                LDMX4(bh[nt2*2][0], bh[nt2*2][1], bh[nt2*2+1][0], bh[nt2*2+1][1], sB + so);
            }
            #pragma unroll
            for (int mt = 0; mt < 4; ++mt) {
                int row = wm * 64 + mt * 16 + arow;
                int grp = ks * 2 + akh;
                uint32_t so = aoff(row, grp);
                uint32_t ah[4];
                LDMX4(ah[0], ah[1], ah[2], ah[3], sA + so);
                #pragma unroll
                for (int nt = 0; nt < 8; ++nt)
                    mma_f16(acc[mt][nt], ah, bh[nt]);
            }
        }
    }

    #pragma unroll
    for (int mt = 0; mt < 4; ++mt) {
        #pragma unroll
        for (int nt = 0; nt < 8; ++nt) {
            int r0 = m0 + wm * 64 + mt * 16 + (lane >> 2);
            int c0 = n0 + wn * 64 + nt * 8 + (lane & 3) * 2;
            float b0 = bias[c0], b1 = bias[c0 + 1];
            #pragma unroll
            for (int half = 0; half < 2; ++half) {
                int row = r0 + half * 8;
                long gi = (long)row * N + c0;
                float v0 = acc[mt][nt][half * 2 + 0] + b0;
                float v1 = acc[mt][nt][half * 2 + 1] + b1;
                if (EPI == 1) {
                    float2 rv = *(const float2*)(R + gi);
                    v0 += rv.x; v1 += rv.y;
                }
                if (EPI == 2) {
                    v0 = 0.5f * v0 * (1.0f + erff(v0 * 0.7071067811865476f));
                    v1 = 0.5f * v1 * (1.0f + erff(v1 * 0.7071067811865476f));
                }
                if (EPI >= 2) {
                    __half2 ph = __floats2half2_rn(v0, v1);
                    *(__half2*)(Ch + gi) = ph;
                } else {
                    float2 o = {v0, v1};
                    *(float2*)(Cf + gi) = o;
                }
            }
        }
    }
}

// ---------------- HMMA flash attention (plain fp16, strided K/V, 1 sync/iter) ----------------
#define ATT_SMEM (8192 + 3 * 16384)

__global__ __launch_bounds__(128) void flash_attn_mma(
    const __half* __restrict__ Q, const __half* __restrict__ K,
    const __half* __restrict__ V, __half* __restrict__ C)
{
    extern __shared__ char smem[];
    const uint32_t sb = smem_u32(smem);
    const int tid = threadIdx.x, lane = tid & 31, warp = tid >> 5;
    const int q0 = blockIdx.x * 64, h = blockIdx.y, b = blockIdx.z;
    const int wq0 = warp * 16;
    const float scale = 0.125f;

    const uint32_t sQ = sb;

    {
        const long gq = (long)(b * KQ + q0) * DMODEL + h * HD;
        for (int e = tid; e < 512; e += 128) {
            int row = e >> 3, grp = e & 7;
            cpa16(sQ + aoff(row, grp), Q + gq + (long)row * DMODEL + grp * 8);
        }
    }
    #define LOAD_KV(it_) do { \
        const uint32_t st_ = sb + 8192 + ((it_) % 3) * 16384; \
        const long gk_ = (long)(b * NKV + (it_) * 64) * KVLD + h * HD; \
        for (int e = tid; e < 512; e += 128) { \
            int row = e >> 3, grp = e & 7; \
            long g = gk_ + (long)row * KVLD + grp * 8; \
            uint32_t so = aoff(row, grp); \
            cpa16(st_ +        so, K + g); \
            cpa16(st_ + 8192 + so, V + g); \
        } \
        cpa_commit(); \
    } while (0)

    LOAD_KV(0);
    LOAD_KV(1);

    uint32_t qf[4][4];
    float ctx[8][4] = {};
    float m0 = -INFINITY, m1 = -INFINITY, l0 = 0.f, l1 = 0.f;

    const int NIT = NKV / 64;
    for (int it = 0; it < NIT; ++it) {
        if (it + 1 < NIT) cpa_wait1(); else cpa_wait0();
        __syncthreads();                         // single barrier per iteration
        if (it == 0) {
            int row = wq0 + (lane & 15);
            #pragma unroll
            for (int ks = 0; ks < 4; ++ks) {
                int grp = ks * 2 + ((lane >> 4) & 1);
                uint32_t so = aoff(row, grp);
                LDMX4(qf[ks][0], qf[ks][1], qf[ks][2], qf[ks][3], sQ + so);
            }
        }
        if (it + 2 < NIT) LOAD_KV(it + 2);

        const uint32_t st  = sb + 8192 + (it % 3) * 16384;
        const uint32_t sk = st, sv = st + 8192;

        float S[8][4] = {};
        #pragma unroll
        for (int ks = 0; ks < 4; ++ks) {
            uint32_t bh[8][2];
            #pragma unroll
            for (int kp = 0; kp < 4; ++kp) {
                int row = kp * 16 + ((lane >> 4) & 1) * 8 + (lane & 7);
                int grp = ks * 2 + ((lane >> 3) & 1);
                uint32_t so = aoff(row, grp);
                LDMX4(bh[2*kp][0], bh[2*kp][1], bh[2*kp+1][0], bh[2*kp+1][1], sk + so);
            }
            #pragma unroll
            for (int nt = 0; nt < 8; ++nt)
                mma_f16(S[nt], qf[ks], bh[nt]);
        }

        float mx0 = -INFINITY, mx1 = -INFINITY;
        #pragma unroll
        for (int nt = 0; nt < 8; ++nt) {
            mx0 = fmaxf(mx0, fmaxf(S[nt][0], S[nt][1]));
            mx1 = fmaxf(mx1, fmaxf(S[nt][2], S[nt][3]));
        }
        mx0 = fmaxf(mx0, __shfl_xor_sync(0xffffffffu, mx0, 1));
        mx0 = fmaxf(mx0, __shfl_xor_sync(0xffffffffu, mx0, 2));
        mx1 = fmaxf(mx1, __shfl_xor_sync(0xffffffffu, mx1, 1));
        mx1 = fmaxf(mx1, __shfl_xor_sync(0xffffffffu, mx1, 2));
        float m0n = fmaxf(m0, mx0), m1n = fmaxf(m1, mx1);
        float cr0 = __expf((m0 - m0n) * scale), cr1 = __expf((m1 - m1n) * scale);
        float s0 = 0.f, s1 = 0.f;
        #pragma unroll
        for (int nt = 0; nt < 8; ++nt) {
            S[nt][0] = __expf((S[nt][0] - m0n) * scale);
            S[nt][1] = __expf((S[nt][1] - m0n) * scale);
            S[nt][2] = __expf((S[nt][2] - m1n) * scale);
            S[nt][3] = __expf((S[nt][3] - m1n) * scale);
            s0 += S[nt][0] + S[nt][1];
            s1 += S[nt][2] + S[nt][3];
        }
        s0 += __shfl_xor_sync(0xffffffffu, s0, 1);
        s0 += __shfl_xor_sync(0xffffffffu, s0, 2);
        s1 += __shfl_xor_sync(0xffffffffu, s1, 1);
        s1 += __shfl_xor_sync(0xffffffffu, s1, 2);
        l0 = l0 * cr0 + s0;  l1 = l1 * cr1 + s1;
        m0 = m0n;  m1 = m1n;
        #pragma unroll
        for (int dt = 0; dt < 8; ++dt) {
            ctx[dt][0] *= cr0; ctx[dt][1] *= cr0;
            ctx[dt][2] *= cr1; ctx[dt][3] *= cr1;
        }

        uint32_t pa[4][4];
        #pragma unroll
        for (int j = 0; j < 4; ++j) {
            __half2 t;
            t = __floats2half2_rn(S[2*j][0],   S[2*j][1]);   pa[j][0] = *(uint32_t*)&t;
            t = __floats2half2_rn(S[2*j][2],   S[2*j][3]);   pa[j][1] = *(uint32_t*)&t;
            t = __floats2half2_rn(S[2*j+1][0], S[2*j+1][1]); pa[j][2] = *(uint32_t*)&t;
            t = __floats2half2_rn(S[2*j+1][2], S[2*j+1][3]); pa[j][3] = *(uint32_t*)&t;
        }

        #pragma unroll
        for (int ks = 0; ks < 4; ++ks) {
            uint32_t vb[8][2];
            #pragma unroll
            for (int dp = 0; dp < 4; ++dp) {
                int row = ks * 16 + ((lane >> 3) & 1) * 8 + (lane & 7);
                int grp = dp * 2 + ((lane >> 4) & 1);
                uint32_t so = aoff(row, grp);
                LDMX4T(vb[2*dp][0], vb[2*dp][1], vb[2*dp+1][0], vb[2*dp+1][1], sv + so);
            }
            #pragma unroll
            for (int dt = 0; dt < 8; ++dt)
                mma_f16(ctx[dt], pa[ks], vb[dt]);
        }
    }

    float i0 = 1.f / l0, i1 = 1.f / l1;
    int r0 = q0 + wq0 + (lane >> 2);
    int r1 = r0 + 8;
    #pragma unroll
    for (int dt = 0; dt < 8; ++dt) {
        int col = h * HD + dt * 8 + (lane & 3) * 2;
        long g0 = (long)(b * KQ + r0) * DMODEL + col;
        long g1 = (long)(b * KQ + r1) * DMODEL + col;
        __half2 p0 = __floats2half2_rn(ctx[dt][0] * i0, ctx[dt][1] * i0);
        __half2 p1 = __floats2half2_rn(ctx[dt][2] * i1, ctx[dt][3] * i1);
        *(__half2*)(C + g0) = p0;
        *(__half2*)(C + g1) = p1;
    }
    #undef LOAD_KV
}

// ---------------- launch ----------------
extern "C" void kernel_launch(void* const* d_in, const int* in_sizes, int n_in,
                              void* d_out, int out_size) {
    const float* query_tokens   = (const float*)d_in[0];
    const float* point_features = (const float*)d_in[1];
    const float* ln_q_g  = (const float*)d_in[2];
    const float* ln_q_b  = (const float*)d_in[3];
    const float* ln_kv_g = (const float*)d_in[4];
    const float* ln_kv_b = (const float*)d_in[5];
    const float* Wq = (const float*)d_in[6];   const float* bq = (const float*)d_in[7];
    const float* Wk = (const float*)d_in[8];   const float* bk = (const float*)d_in[9];
    const float* Wv = (const float*)d_in[10];  const float* bv = (const float*)d_in[11];
    const float* rms_q_w = (const float*)d_in[12];
    const float* rms_k_w = (const float*)d_in[13];
    const float* Wo = (const float*)d_in[14];  const float* bo = (const float*)d_in[15];
    const float* ln_mlp_g = (const float*)d_in[16];
    const float* ln_mlp_b = (const float*)d_in[17];
    const float* W1 = (const float*)d_in[18];  const float* b1 = (const float*)d_in[19];
    const float* W2 = (const float*)d_in[20];  const float* b2 = (const float*)d_in[21];
    float* out = (float*)d_out;

    float *p_out, *p_bkv;
    cudaGetSymbolAddress((void**)&p_out, g_out);
    cudaGetSymbolAddress((void**)&p_bkv, g_bkv);

    __half *qln,*kvln,*ctx,*hln,*m1,*qp,*kv;
    __half *wq,*wkv,*wo,*w1,*w2;
    cudaGetSymbolAddress((void**)&qln, g_qln);  cudaGetSymbolAddress((void**)&kvln, g_kvln);
    cudaGetSymbolAddress((void**)&ctx, g_ctx);  cudaGetSymbolAddress((void**)&hln, g_hln);
    cudaGetSymbolAddress((void**)&m1, g_m1);
    cudaGetSymbolAddress((void**)&qp, g_qp);    cudaGetSymbolAddress((void**)&kv, g_kv);
    cudaGetSymbolAddress((void**)&wq, g_wq);    cudaGetSymbolAddress((void**)&wkv, g_wkv);
    cudaGetSymbolAddress((void**)&wo, g_wo);
    cudaGetSymbolAddress((void**)&w1, g_w1);    cudaGetSymbolAddress((void**)&w2, g_w2);

    cudaFuncSetAttribute(hgemm_k<1>, cudaFuncAttributeMaxDynamicSharedMemorySize, GEMM_SMEM_BYTES);
    cudaFuncSetAttribute(hgemm_k<2>, cudaFuncAttributeMaxDynamicSharedMemorySize, GEMM_SMEM_BYTES);
    cudaFuncSetAttribute(hgemm_k<3>, cudaFuncAttributeMaxDynamicSharedMemorySize, GEMM_SMEM_BYTES);
    cudaFuncSetAttribute(flash_attn_mma, cudaFuncAttributeMaxDynamicSharedMemorySize, ATT_SMEM);

    cudaMemcpyAsync(p_bkv,        bk, DMODEL * sizeof(float), cudaMemcpyDeviceToDevice);
    cudaMemcpyAsync(p_bkv + 1024, bv, DMODEL * sizeof(float), cudaMemcpyDeviceToDevice);

    wcvt_all_k<<<12288, 256>>>(Wq, Wk, Wv, Wo, W1, W2, wq, wkv, wo, w1, w2);

    layernorm2_k<<<MQ + MKV, 256>>>(query_tokens, point_features,
                                    ln_q_g, ln_q_b, ln_kv_g, ln_kv_b, qln, kvln);

    hgemm_k<3><<<dim3(DMODEL/128, MQ/128), 128, GEMM_SMEM_BYTES>>>(
        qln, wq, bq, nullptr, nullptr, qp, MQ, DMODEL, DMODEL);
    hgemm_k<3><<<dim3(KVLD/128, MKV/128), 128, GEMM_SMEM_BYTES>>>(
        kvln, wkv, p_bkv, nullptr, nullptr, kv, MKV, KVLD, DMODEL);

    rmsnorm2_k<<<MQ + MKV, 256>>>(qp, kv, rms_q_w, rms_k_w);

    flash_attn_mma<<<dim3(KQ/64, NHEAD, BATCH), 128, ATT_SMEM>>>(qp, kv, kv + 1024, ctx);

    hgemm_k<1><<<dim3(DMODEL/128, MQ/128), 128, GEMM_SMEM_BYTES>>>(
        ctx, wo, bo, query_tokens, p_out, nullptr, MQ, DMODEL, DMODEL);

    layernorm_h_k<<<MQ, 256>>>(p_out, ln_mlp_g, ln_mlp_b, hln, 1e-5f);
    hgemm_k<2><<<dim3(DFF/128, MQ/128), 128, GEMM_SMEM_BYTES>>>(
        hln, w1, b1, nullptr, nullptr, m1, MQ, DFF, DMODEL);
    hgemm_k<1><<<dim3(DMODEL/128, MQ/128), 128, GEMM_SMEM_BYTES>>>(
        m1, w2, b2, p_out, out, nullptr, MQ, DMODEL, DFF);
}